// round 1
// baseline (speedup 1.0000x reference)
#include <cuda_runtime.h>
#include <cuda_bf16.h>

// ---------------------------------------------------------------------------
// Problem constants: B=8, N=1024, DIM=512, H=8, HD=64, INNER=512, KS=5
// Layouts: all activations row-major [b*n, cols].
// QKV buffer: [8*1024, 2048]; q cols 0+h*64, k cols 512+h*64, v 1024+h*64, s 1536+h*64
// ---------------------------------------------------------------------------

__device__ float g_qkv1[8ull * 1024 * 2048];
__device__ float g_qkv2[8ull * 1024 * 2048];
__device__ float g_msg [8ull * 1024 * 512];
__device__ float g_P   [64ull * 1024 * 1024];   // scores for one pass (all b,h)
__device__ float g_u1  [8ull * 1024 * 512];
__device__ float g_u2  [8ull * 1024 * 512];
__device__ float g_t1  [8ull * 1024 * 512];
__device__ float g_t2  [8ull * 1024 * 512];

// ---------------------------------------------------------------------------
// Generic SGEMM NN: C[M,N] = A[M,K] @ B[K,N] (+ bias row).  128x128x8, 256 thr.
// M,N multiples of 128; K multiple of 8. Row-major with leading dims.
// ---------------------------------------------------------------------------
__global__ __launch_bounds__(256) void sgemm_nn(
    const float* __restrict__ A, const float* __restrict__ B,
    const float* __restrict__ bias, float* __restrict__ C,
    int M, int N, int K, int lda, int ldb, int ldc)
{
    __shared__ float As[8][128];
    __shared__ float Bs[8][128];
    const int tid = threadIdx.x;
    const int bx = blockIdx.x, by = blockIdx.y;
    const float* Ab = A + (size_t)by * 128 * lda;
    const float* Bb = B + (size_t)bx * 128;
    const int ar_ = tid >> 1, ac_ = (tid & 1) * 4;
    const int br_ = tid >> 5, bc_ = (tid & 31) * 4;
    const int ty = tid >> 4, tx = tid & 15;

    float acc[8][8];
#pragma unroll
    for (int i = 0; i < 8; i++)
#pragma unroll
        for (int j = 0; j < 8; j++) acc[i][j] = 0.f;

    for (int k0 = 0; k0 < K; k0 += 8) {
        float4 av = *(const float4*)(Ab + (size_t)ar_ * lda + k0 + ac_);
        float4 bv = *(const float4*)(Bb + (size_t)(k0 + br_) * ldb + bc_);
        As[ac_ + 0][ar_] = av.x;
        As[ac_ + 1][ar_] = av.y;
        As[ac_ + 2][ar_] = av.z;
        As[ac_ + 3][ar_] = av.w;
        *(float4*)&Bs[br_][bc_] = bv;
        __syncthreads();
#pragma unroll
        for (int k = 0; k < 8; k++) {
            float a_[8], b_[8];
            *(float4*)&a_[0] = *(const float4*)&As[k][ty * 8];
            *(float4*)&a_[4] = *(const float4*)&As[k][ty * 8 + 4];
            *(float4*)&b_[0] = *(const float4*)&Bs[k][tx * 8];
            *(float4*)&b_[4] = *(const float4*)&Bs[k][tx * 8 + 4];
#pragma unroll
            for (int i = 0; i < 8; i++)
#pragma unroll
                for (int j = 0; j < 8; j++)
                    acc[i][j] += a_[i] * b_[j];
        }
        __syncthreads();
    }

#pragma unroll
    for (int i = 0; i < 8; i++) {
        int row = by * 128 + ty * 8 + i;
#pragma unroll
        for (int j = 0; j < 8; j += 4) {
            int col = bx * 128 + tx * 8 + j;
            float4 v;
            v.x = acc[i][j + 0]; v.y = acc[i][j + 1];
            v.z = acc[i][j + 2]; v.w = acc[i][j + 3];
            if (bias) {
                v.x += bias[col + 0]; v.y += bias[col + 1];
                v.z += bias[col + 2]; v.w += bias[col + 3];
            }
            *(float4*)(C + (size_t)row * ldc + col) = v;
        }
    }
}

// ---------------------------------------------------------------------------
// Gate: MS = s1+s2; depthwise conv-5 along feature axis with per-token kernel;
// MSg = sigmoid(conv(MS)+b) * MS.  One block per (b,n) row, 128 threads.
// ---------------------------------------------------------------------------
__global__ __launch_bounds__(128) void gate_conv(
    const float* __restrict__ qkv1, const float* __restrict__ qkv2,
    const float* __restrict__ w, const float* __restrict__ cb,
    float* __restrict__ msg)
{
    __shared__ float ms[516];
    const int bn = blockIdx.x;
    const int n = bn & 1023;
    const int tid = threadIdx.x;
    const float* r1 = qkv1 + (size_t)bn * 2048 + 1536;
    const float* r2 = qkv2 + (size_t)bn * 2048 + 1536;
    for (int f = tid; f < 512; f += 128) ms[f + 2] = r1[f] + r2[f];
    if (tid < 2) { ms[tid] = 0.f; ms[514 + tid] = 0.f; }
    __syncthreads();
    const float w0 = w[n * 5 + 0], w1 = w[n * 5 + 1], w2 = w[n * 5 + 2],
                w3 = w[n * 5 + 3], w4 = w[n * 5 + 4], bb = cb[n];
    for (int f = tid; f < 512; f += 128) {
        float a = w0 * ms[f] + w1 * ms[f + 1] + w2 * ms[f + 2]
                + w3 * ms[f + 3] + w4 * ms[f + 4] + bb;
        float s = 1.f / (1.f + __expf(-a));
        msg[(size_t)bn * 512 + f] = s * ms[f + 2];
    }
}

// ---------------------------------------------------------------------------
// Scores (NT): P[bz, i, j] = scale * dot(A[b,i,cA+h*64 : +64], B[b,j,cB+h*64 : +64])
// 128x128 tile, K=64 (8 steps of 8). grid (8, 8, 64).
// ---------------------------------------------------------------------------
__global__ __launch_bounds__(256) void score_nt(
    const float* __restrict__ Abase, int cA, int lda,
    const float* __restrict__ Bbase, int cB, int ldb,
    float* __restrict__ P, float scale)
{
    const int bz = blockIdx.z;
    const int b = bz >> 3, h = bz & 7;
    const float* A  = Abase + (size_t)b * 1024 * lda + cA + h * 64;
    const float* Bp = Bbase + (size_t)b * 1024 * ldb + cB + h * 64;
    float* Pb = P + (size_t)bz * 1024 * 1024;

    __shared__ float As[8][128];
    __shared__ float Bs[8][128];
    const int tid = threadIdx.x;
    const int bx = blockIdx.x, by = blockIdx.y;
    const int r_ = tid >> 1, c_ = (tid & 1) * 4;
    const int ty = tid >> 4, tx = tid & 15;

    float acc[8][8];
#pragma unroll
    for (int i = 0; i < 8; i++)
#pragma unroll
        for (int j = 0; j < 8; j++) acc[i][j] = 0.f;

    for (int k0 = 0; k0 < 64; k0 += 8) {
        float4 av = *(const float4*)(A  + (size_t)(by * 128 + r_) * lda + k0 + c_);
        float4 bv = *(const float4*)(Bp + (size_t)(bx * 128 + r_) * ldb + k0 + c_);
        As[c_ + 0][r_] = av.x; As[c_ + 1][r_] = av.y;
        As[c_ + 2][r_] = av.z; As[c_ + 3][r_] = av.w;
        Bs[c_ + 0][r_] = bv.x; Bs[c_ + 1][r_] = bv.y;
        Bs[c_ + 2][r_] = bv.z; Bs[c_ + 3][r_] = bv.w;
        __syncthreads();
#pragma unroll
        for (int k = 0; k < 8; k++) {
            float a_[8], b_[8];
            *(float4*)&a_[0] = *(const float4*)&As[k][ty * 8];
            *(float4*)&a_[4] = *(const float4*)&As[k][ty * 8 + 4];
            *(float4*)&b_[0] = *(const float4*)&Bs[k][tx * 8];
            *(float4*)&b_[4] = *(const float4*)&Bs[k][tx * 8 + 4];
#pragma unroll
            for (int i = 0; i < 8; i++)
#pragma unroll
                for (int j = 0; j < 8; j++)
                    acc[i][j] += a_[i] * b_[j];
        }
        __syncthreads();
    }

#pragma unroll
    for (int i = 0; i < 8; i++) {
        size_t row = (size_t)(by * 128 + ty * 8 + i);
#pragma unroll
        for (int j = 0; j < 8; j += 4) {
            int col = bx * 128 + tx * 8 + j;
            float4 v;
            v.x = acc[i][j + 0] * scale; v.y = acc[i][j + 1] * scale;
            v.z = acc[i][j + 2] * scale; v.w = acc[i][j + 3] * scale;
            *(float4*)(Pb + row * 1024 + col) = v;
        }
    }
}

// ---------------------------------------------------------------------------
// Row softmax in place over P rows of length 1024. grid (1024, 64), 256 thr.
// ---------------------------------------------------------------------------
__global__ __launch_bounds__(256) void softmax_rows(float* __restrict__ P)
{
    float* row = P + ((size_t)blockIdx.y * 1024 + blockIdx.x) * 1024;
    const int tid = threadIdx.x;
    const int warp = tid >> 5, lane = tid & 31;
    __shared__ float red[10];

    float4 x = *(float4*)(row + tid * 4);
    float m = fmaxf(fmaxf(x.x, x.y), fmaxf(x.z, x.w));
#pragma unroll
    for (int o = 16; o; o >>= 1) m = fmaxf(m, __shfl_xor_sync(~0u, m, o));
    if (lane == 0) red[warp] = m;
    __syncthreads();
    if (tid == 0) {
        float t = red[0];
#pragma unroll
        for (int i = 1; i < 8; i++) t = fmaxf(t, red[i]);
        red[8] = t;
    }
    __syncthreads();
    m = red[8];
    __syncthreads();

    x.x = __expf(x.x - m); x.y = __expf(x.y - m);
    x.z = __expf(x.z - m); x.w = __expf(x.w - m);
    float s = x.x + x.y + x.z + x.w;
#pragma unroll
    for (int o = 16; o; o >>= 1) s += __shfl_xor_sync(~0u, s, o);
    if (lane == 0) red[warp] = s;
    __syncthreads();
    if (tid == 0) {
        float t = 0.f;
#pragma unroll
        for (int i = 0; i < 8; i++) t += red[i];
        red[9] = t;
    }
    __syncthreads();
    float inv = 1.f / red[9];
    x.x *= inv; x.y *= inv; x.z *= inv; x.w *= inv;
    *(float4*)(row + tid * 4) = x;
}

// ---------------------------------------------------------------------------
// PV: O[b, i, h*64+j] = sum_j' P[bz,i,j'] * V[b,j',cV+h*64+j]  (+ V[b,i,..] if addv)
// Tile 128x64x16, 256 threads, micro 8x4. grid (8, 1, 64).
// ---------------------------------------------------------------------------
__global__ __launch_bounds__(256) void pv(
    const float* __restrict__ P,
    const float* __restrict__ Vbase, int cV, int ldv,
    float* __restrict__ Obase, int ldo,
    int addv)
{
    const int bz = blockIdx.z, b = bz >> 3, h = bz & 7;
    const float* Pb = P + (size_t)bz * 1024 * 1024 + (size_t)blockIdx.x * 128 * 1024;
    const float* V  = Vbase + (size_t)b * 1024 * ldv + cV + h * 64;
    float* O = Obase + (size_t)b * 1024 * ldo + h * 64 + (size_t)blockIdx.x * 128 * ldo;

    __shared__ float Ps[16][128];
    __shared__ float Vs[16][64];
    const int tid = threadIdx.x;
    const int pr = tid >> 1, pc = (tid & 1) * 8;
    const int vr = tid >> 4, vc = (tid & 15) * 4;
    const int ty = tid >> 4, tx = tid & 15;

    float acc[8][4];
#pragma unroll
    for (int i = 0; i < 8; i++)
#pragma unroll
        for (int j = 0; j < 4; j++) acc[i][j] = 0.f;

    for (int k0 = 0; k0 < 1024; k0 += 16) {
        float4 p0 = *(const float4*)(Pb + (size_t)pr * 1024 + k0 + pc);
        float4 p1 = *(const float4*)(Pb + (size_t)pr * 1024 + k0 + pc + 4);
        float4 vv = *(const float4*)(V + (size_t)(k0 + vr) * ldv + vc);
        Ps[pc + 0][pr] = p0.x; Ps[pc + 1][pr] = p0.y;
        Ps[pc + 2][pr] = p0.z; Ps[pc + 3][pr] = p0.w;
        Ps[pc + 4][pr] = p1.x; Ps[pc + 5][pr] = p1.y;
        Ps[pc + 6][pr] = p1.z; Ps[pc + 7][pr] = p1.w;
        *(float4*)&Vs[vr][vc] = vv;
        __syncthreads();
#pragma unroll
        for (int k = 0; k < 16; k++) {
            float a_[8], b_[4];
            *(float4*)&a_[0] = *(const float4*)&Ps[k][ty * 8];
            *(float4*)&a_[4] = *(const float4*)&Ps[k][ty * 8 + 4];
            *(float4*)&b_[0] = *(const float4*)&Vs[k][tx * 4];
#pragma unroll
            for (int i = 0; i < 8; i++)
#pragma unroll
                for (int j = 0; j < 4; j++)
                    acc[i][j] += a_[i] * b_[j];
        }
        __syncthreads();
    }

#pragma unroll
    for (int i = 0; i < 8; i++) {
        int row = ty * 8 + i;
        float4 v;
        v.x = acc[i][0]; v.y = acc[i][1]; v.z = acc[i][2]; v.w = acc[i][3];
        if (addv) {
            int grow = blockIdx.x * 128 + row;
            float4 va = *(const float4*)(V + (size_t)grow * ldv + tx * 4);
            v.x += va.x; v.y += va.y; v.z += va.z; v.w += va.w;
        }
        *(float4*)(O + (size_t)row * ldo + tx * 4) = v;
    }
}

// ---------------------------------------------------------------------------
// Launch
// ---------------------------------------------------------------------------
extern "C" void kernel_launch(void* const* d_in, const int* in_sizes, int n_in,
                              void* d_out, int out_size)
{
    const float* x1    = (const float*)d_in[0];
    const float* x2    = (const float*)d_in[1];
    const float* Wqkv1 = (const float*)d_in[2];
    const float* Wqkv2 = (const float*)d_in[3];
    const float* Wout1 = (const float*)d_in[4];
    const float* bout1 = (const float*)d_in[5];
    const float* Wout2 = (const float*)d_in[6];
    const float* bout2 = (const float*)d_in[7];
    const float* convw = (const float*)d_in[8];
    const float* convb = (const float*)d_in[9];
    float* out = (float*)d_out;

    float *qkv1, *qkv2, *msg, *P, *u1, *u2, *t1, *t2;
    cudaGetSymbolAddress((void**)&qkv1, g_qkv1);
    cudaGetSymbolAddress((void**)&qkv2, g_qkv2);
    cudaGetSymbolAddress((void**)&msg,  g_msg);
    cudaGetSymbolAddress((void**)&P,    g_P);
    cudaGetSymbolAddress((void**)&u1,   g_u1);
    cudaGetSymbolAddress((void**)&u2,   g_u2);
    cudaGetSymbolAddress((void**)&t1,   g_t1);
    cudaGetSymbolAddress((void**)&t2,   g_t2);

    const dim3 blk(256);
    const float scale = 0.125f;  // 64^-0.5

    // QKVS projections
    sgemm_nn<<<dim3(16, 64), blk>>>(x1, Wqkv1, nullptr, qkv1, 8192, 2048, 512, 512, 2048, 2048);
    sgemm_nn<<<dim3(16, 64), blk>>>(x2, Wqkv2, nullptr, qkv2, 8192, 2048, 512, 512, 2048, 2048);

    // Gate path -> MSg
    gate_conv<<<8192, 128>>>(qkv1, qkv2, convw, convb, msg);

    // Pass 3: a3 = softmax(MSh MSh^T * scale); u = a3 @ v + v (both streams)
    score_nt<<<dim3(8, 8, 64), blk>>>(msg, 0, 512, msg, 0, 512, P, scale);
    softmax_rows<<<dim3(1024, 64), blk>>>(P);
    pv<<<dim3(8, 1, 64), blk>>>(P, qkv1, 1024, 2048, u1, 512, 1);
    pv<<<dim3(8, 1, 64), blk>>>(P, qkv2, 1024, 2048, u2, 512, 1);

    // Pass 1: t1 = softmax(q1 k1^T * scale) @ u1
    score_nt<<<dim3(8, 8, 64), blk>>>(qkv1, 0, 2048, qkv1, 512, 2048, P, scale);
    softmax_rows<<<dim3(1024, 64), blk>>>(P);
    pv<<<dim3(8, 1, 64), blk>>>(P, u1, 0, 512, t1, 512, 0);

    // Pass 2: t2 = softmax(q2 k2^T * scale) @ u2
    score_nt<<<dim3(8, 8, 64), blk>>>(qkv2, 0, 2048, qkv2, 512, 2048, P, scale);
    softmax_rows<<<dim3(1024, 64), blk>>>(P);
    pv<<<dim3(8, 1, 64), blk>>>(P, u2, 0, 512, t2, 512, 0);

    // Output projections (out1 then out2, concatenated in d_out)
    sgemm_nn<<<dim3(4, 64), blk>>>(t1, Wout1, bout1, out,           8192, 512, 512, 512, 512, 512);
    sgemm_nn<<<dim3(4, 64), blk>>>(t2, Wout2, bout2, out + 4194304, 8192, 512, 512, 512, 512, 512);
}

// round 3
// speedup vs baseline: 1.7660x; 1.7660x over previous
#include <cuda_runtime.h>
#include <cuda_bf16.h>
#include <cstdint>

// ---------------------------------------------------------------------------
// B=8, N=1024, DIM=512, H=8, HD=64, INNER=512, KS=5
// Split-bf16 tensor-core pipeline: every GEMM operand lives as (hi, lo) bf16
// planes; C = Ah*Bh + Ah*Bl + Al*Bh accumulated in fp32 via mma.sync m16n8k16.
// A operands: [M][K] row-major planes. B operands: [N][K] row-major planes.
// ---------------------------------------------------------------------------

#define F_F32    1
#define F_PLANES 2
#define F_PLT    4
#define F_RES    8
#define F_BIAS   16
#define F_SCALE  32

// ---------------- scratch (device globals; no allocs allowed) --------------
__device__ __nv_bfloat16 g_xp1 [2ull*8192*512];
__device__ __nv_bfloat16 g_xp2 [2ull*8192*512];
__device__ __nv_bfloat16 g_Wq1 [2ull*2048*512];
__device__ __nv_bfloat16 g_Wq2 [2ull*2048*512];
__device__ __nv_bfloat16 g_Wo1 [2ull*512*512];
__device__ __nv_bfloat16 g_Wo2 [2ull*512*512];
__device__ float         g_qkv1[8192ull*2048];
__device__ float         g_qkv2[8192ull*2048];
__device__ __nv_bfloat16 g_qkvp1[2ull*8192*2048];
__device__ __nv_bfloat16 g_qkvp2[2ull*8192*2048];
__device__ __nv_bfloat16 g_vT1 [2ull*64*64*1024];
__device__ __nv_bfloat16 g_vT2 [2ull*64*64*1024];
__device__ __nv_bfloat16 g_msgp[2ull*8192*512];
__device__ float         g_P   [64ull*1024*1024];
__device__ __nv_bfloat16 g_Pp  [2ull*64*1024*1024];
__device__ __nv_bfloat16 g_uT1 [2ull*64*64*1024];
__device__ __nv_bfloat16 g_uT2 [2ull*64*64*1024];
__device__ __nv_bfloat16 g_tp1 [2ull*8192*512];
__device__ __nv_bfloat16 g_tp2 [2ull*8192*512];

// ---------------- helpers --------------------------------------------------
__device__ __forceinline__ void split1(float v, __nv_bfloat16& h, __nv_bfloat16& l) {
    h = __float2bfloat16(v);
    l = __float2bfloat16(v - __bfloat162float(h));
}
__device__ __forceinline__ uint32_t smaddr(const void* p) {
    return (uint32_t)__cvta_generic_to_shared(p);
}
__device__ __forceinline__ void ldsm4(uint32_t& r0, uint32_t& r1, uint32_t& r2, uint32_t& r3, uint32_t a) {
    asm volatile("ldmatrix.sync.aligned.m8n8.x4.shared.b16 {%0,%1,%2,%3},[%4];\n"
                 : "=r"(r0), "=r"(r1), "=r"(r2), "=r"(r3) : "r"(a));
}
__device__ __forceinline__ void ldsm2(uint32_t& r0, uint32_t& r1, uint32_t a) {
    asm volatile("ldmatrix.sync.aligned.m8n8.x2.shared.b16 {%0,%1},[%2];\n"
                 : "=r"(r0), "=r"(r1) : "r"(a));
}
#define MMA16816(c, a, b)                                                            \
    asm volatile("mma.sync.aligned.m16n8k16.row.col.f32.bf16.bf16.f32 "              \
                 "{%0,%1,%2,%3},{%4,%5,%6,%7},{%8,%9},{%0,%1,%2,%3};\n"              \
                 : "+f"((c)[0]), "+f"((c)[1]), "+f"((c)[2]), "+f"((c)[3])            \
                 : "r"((a)[0]), "r"((a)[1]), "r"((a)[2]), "r"((a)[3]),               \
                   "r"((b)[0]), "r"((b)[1]))

// ---------------------------------------------------------------------------
// Generic split-bf16 GEMM. Block tile 128 x BN, K-step 16, double-buffered.
// Batched over blockIdx.z with z = zb*8 + zh; offsets = zb*outer + zh*inner.
// ---------------------------------------------------------------------------
template <int BN, int FLAGS>
__global__ __launch_bounds__(256) void gemm_bs(
    const __nv_bfloat16* __restrict__ Ah, const __nv_bfloat16* __restrict__ Al,
    long long lda, long long bAo, long long bAi,
    const __nv_bfloat16* __restrict__ Bh, const __nv_bfloat16* __restrict__ Bl,
    long long ldb, long long bBo, long long bBi,
    float* __restrict__ C32, long long ldc, long long bCo, long long bCi,
    __nv_bfloat16* __restrict__ Ch, __nv_bfloat16* __restrict__ Cl,
    long long ldcp, long long bPo, long long bPi,
    const float* __restrict__ Res, long long ldr, long long bRo, long long bRi,
    const float* __restrict__ bias, float scale, int K)
{
    constexpr int WCOLS = BN / 32;
    constexpr int WROWS = 8 / WCOLS;
    constexpr int WM = 128 / WROWS;
    constexpr int MF = WM / 16;
    constexpr int BLB = (BN == 128) ? 2 : 1;

    __shared__ __align__(16) __nv_bfloat16 sA[2][2][128][24];
    __shared__ __align__(16) __nv_bfloat16 sB[2][2][BN][24];

    const int tid = threadIdx.x;
    const int z = blockIdx.z, zb = z >> 3, zh = z & 7;
    Ah += zb * bAo + zh * bAi;  Al += zb * bAo + zh * bAi;
    Bh += zb * bBo + zh * bBi;  Bl += zb * bBo + zh * bBi;

    // A loader mapping: 512 16B-chunks (2 planes x 128 rows x 2 halves)
    const __nv_bfloat16* srcA[2]; int aP[2], aR[2], aH[2];
#pragma unroll
    for (int j = 0; j < 2; j++) {
        int idx = tid + j * 256;
        aP[j] = idx >> 8; int rem = idx & 255; aR[j] = rem >> 1; aH[j] = rem & 1;
        const __nv_bfloat16* base = aP[j] ? Al : Ah;
        srcA[j] = base + (size_t)(blockIdx.y * 128 + aR[j]) * lda + aH[j] * 8;
    }
    const __nv_bfloat16* srcB[BLB]; int bP[BLB], bR[BLB], bH[BLB];
#pragma unroll
    for (int j = 0; j < BLB; j++) {
        int idx = tid + j * 256;
        bP[j] = idx / (BN * 2); int rem = idx % (BN * 2); bR[j] = rem >> 1; bH[j] = rem & 1;
        const __nv_bfloat16* base = bP[j] ? Bl : Bh;
        srcB[j] = base + (size_t)(blockIdx.x * BN + bR[j]) * ldb + bH[j] * 8;
    }

    // stage 0
#pragma unroll
    for (int j = 0; j < 2; j++)
        *(uint4*)&sA[0][aP[j]][aR[j]][aH[j] * 8] = *(const uint4*)srcA[j];
#pragma unroll
    for (int j = 0; j < BLB; j++)
        *(uint4*)&sB[0][bP[j]][bR[j]][bH[j] * 8] = *(const uint4*)srcB[j];
    __syncthreads();

    const int lane = tid & 31, w = tid >> 5;
    const int wm = (w / WCOLS) * WM, wn = (w % WCOLS) * 32;

    float acc[MF][4][4];
#pragma unroll
    for (int i = 0; i < MF; i++)
#pragma unroll
        for (int j = 0; j < 4; j++)
#pragma unroll
            for (int k = 0; k < 4; k++) acc[i][j][k] = 0.f;

    const int nk = K >> 4;
    for (int kt = 0; kt < nk; ++kt) {
        const int cur = kt & 1;
        const bool pf = (kt + 1) < nk;
        uint4 ra[2], rb[BLB];
        if (pf) {
            long long k0 = (long long)(kt + 1) * 16;
#pragma unroll
            for (int j = 0; j < 2; j++)   ra[j] = *(const uint4*)(srcA[j] + k0);
#pragma unroll
            for (int j = 0; j < BLB; j++) rb[j] = *(const uint4*)(srcB[j] + k0);
        }

        uint32_t bhf[4][2], blf[4][2], af[MF][4];
#pragma unroll
        for (int nf = 0; nf < 4; nf++) {
            uint32_t ad = smaddr(&sB[cur][0][wn + nf * 8 + (lane & 7)][((lane >> 3) & 1) * 8]);
            ldsm2(bhf[nf][0], bhf[nf][1], ad);
            ad = smaddr(&sB[cur][1][wn + nf * 8 + (lane & 7)][((lane >> 3) & 1) * 8]);
            ldsm2(blf[nf][0], blf[nf][1], ad);
        }
#pragma unroll
        for (int mf = 0; mf < MF; mf++) {
            uint32_t ad = smaddr(&sA[cur][0][wm + mf * 16 + (lane & 15)][(lane >> 4) * 8]);
            ldsm4(af[mf][0], af[mf][1], af[mf][2], af[mf][3], ad);
        }
#pragma unroll
        for (int mf = 0; mf < MF; mf++)
#pragma unroll
            for (int nf = 0; nf < 4; nf++) MMA16816(acc[mf][nf], af[mf], bhf[nf]);
#pragma unroll
        for (int mf = 0; mf < MF; mf++)
#pragma unroll
            for (int nf = 0; nf < 4; nf++) MMA16816(acc[mf][nf], af[mf], blf[nf]);
#pragma unroll
        for (int mf = 0; mf < MF; mf++) {
            uint32_t ad = smaddr(&sA[cur][1][wm + mf * 16 + (lane & 15)][(lane >> 4) * 8]);
            ldsm4(af[mf][0], af[mf][1], af[mf][2], af[mf][3], ad);
        }
#pragma unroll
        for (int mf = 0; mf < MF; mf++)
#pragma unroll
            for (int nf = 0; nf < 4; nf++) MMA16816(acc[mf][nf], af[mf], bhf[nf]);

        if (pf) {
            const int nb = cur ^ 1;
#pragma unroll
            for (int j = 0; j < 2; j++)
                *(uint4*)&sA[nb][aP[j]][aR[j]][aH[j] * 8] = ra[j];
#pragma unroll
            for (int j = 0; j < BLB; j++)
                *(uint4*)&sB[nb][bP[j]][bR[j]][bH[j] * 8] = rb[j];
        }
        __syncthreads();
    }

    // epilogue
#pragma unroll
    for (int mf = 0; mf < MF; mf++) {
        const int r0 = blockIdx.y * 128 + wm + mf * 16 + (lane >> 2);
#pragma unroll
        for (int nf = 0; nf < 4; nf++) {
            const int c0 = blockIdx.x * BN + wn + nf * 8 + (lane & 3) * 2;
            float v00 = acc[mf][nf][0], v01 = acc[mf][nf][1];
            float v10 = acc[mf][nf][2], v11 = acc[mf][nf][3];
            if constexpr (FLAGS & F_SCALE) { v00 *= scale; v01 *= scale; v10 *= scale; v11 *= scale; }
            if constexpr (FLAGS & F_RES) {
                const float* R = Res + zb * bRo + zh * bRi;
                v00 += R[(size_t)r0 * ldr + c0];       v01 += R[(size_t)r0 * ldr + c0 + 1];
                v10 += R[(size_t)(r0 + 8) * ldr + c0]; v11 += R[(size_t)(r0 + 8) * ldr + c0 + 1];
            }
            if constexpr (FLAGS & F_BIAS) {
                float b0 = bias[c0], b1 = bias[c0 + 1];
                v00 += b0; v01 += b1; v10 += b0; v11 += b1;
            }
            if constexpr (FLAGS & F_F32) {
                float* C = C32 + zb * bCo + zh * bCi;
                *(float2*)&C[(size_t)r0 * ldc + c0]       = make_float2(v00, v01);
                *(float2*)&C[(size_t)(r0 + 8) * ldc + c0] = make_float2(v10, v11);
            }
            if constexpr (FLAGS & (F_PLANES | F_PLT)) {
                __nv_bfloat16 h00, l00, h01, l01, h10, l10, h11, l11;
                split1(v00, h00, l00); split1(v01, h01, l01);
                split1(v10, h10, l10); split1(v11, h11, l11);
                __nv_bfloat16* CH = Ch + zb * bPo + zh * bPi;
                __nv_bfloat16* CL = Cl + zb * bPo + zh * bPi;
                if constexpr (FLAGS & F_PLANES) {
                    __nv_bfloat162 t;
                    t.x = h00; t.y = h01; *(__nv_bfloat162*)&CH[(size_t)r0 * ldcp + c0] = t;
                    t.x = l00; t.y = l01; *(__nv_bfloat162*)&CL[(size_t)r0 * ldcp + c0] = t;
                    t.x = h10; t.y = h11; *(__nv_bfloat162*)&CH[(size_t)(r0 + 8) * ldcp + c0] = t;
                    t.x = l10; t.y = l11; *(__nv_bfloat162*)&CL[(size_t)(r0 + 8) * ldcp + c0] = t;
                } else {
                    CH[(size_t)c0 * ldcp + r0]           = h00;
                    CH[(size_t)(c0 + 1) * ldcp + r0]     = h01;
                    CH[(size_t)c0 * ldcp + r0 + 8]       = h10;
                    CH[(size_t)(c0 + 1) * ldcp + r0 + 8] = h11;
                    CL[(size_t)c0 * ldcp + r0]           = l00;
                    CL[(size_t)(c0 + 1) * ldcp + r0]     = l01;
                    CL[(size_t)c0 * ldcp + r0 + 8]       = l10;
                    CL[(size_t)(c0 + 1) * ldcp + r0 + 8] = l11;
                }
            }
        }
    }
}

// ---------------------------------------------------------------------------
// Converters
// ---------------------------------------------------------------------------
__global__ void convN(const float* __restrict__ X, __nv_bfloat16* __restrict__ H,
                      __nv_bfloat16* __restrict__ L, int n4)
{
    int i = blockIdx.x * blockDim.x + threadIdx.x;
    if (i >= n4) return;
    float4 v = ((const float4*)X)[i];
    __nv_bfloat16 h0, l0, h1, l1, h2, l2, h3, l3;
    split1(v.x, h0, l0); split1(v.y, h1, l1); split1(v.z, h2, l2); split1(v.w, h3, l3);
    __nv_bfloat162 t;
    t.x = h0; t.y = h1; *(__nv_bfloat162*)&H[(size_t)i * 4]     = t;
    t.x = h2; t.y = h3; *(__nv_bfloat162*)&H[(size_t)i * 4 + 2] = t;
    t.x = l0; t.y = l1; *(__nv_bfloat162*)&L[(size_t)i * 4]     = t;
    t.x = l2; t.y = l3; *(__nv_bfloat162*)&L[(size_t)i * 4 + 2] = t;
}

__global__ void convT(const float* __restrict__ W, __nv_bfloat16* __restrict__ H,
                      __nv_bfloat16* __restrict__ L, int K, int N)
{
    int i = blockIdx.x * blockDim.x + threadIdx.x;
    if (i >= K * N) return;
    int n = i / K, k = i % K;
    float v = W[(size_t)k * N + n];
    split1(v, H[i], L[i]);
}

// qkv fp32 v-region -> transposed planes vT[(z*64+n)][token]
__global__ void vtrans(const float* __restrict__ qkv, __nv_bfloat16* __restrict__ H,
                       __nv_bfloat16* __restrict__ L)
{
    __shared__ float t[64][65];
    const int z = blockIdx.y, tokb = blockIdx.x, b = z >> 3, h = z & 7;
    const int tid = threadIdx.x;
    for (int i = tid; i < 4096; i += 256) {
        int tl = i >> 6, n = i & 63;
        t[tl][n] = qkv[(size_t)(b * 1024 + tokb * 64 + tl) * 2048 + 1024 + h * 64 + n];
    }
    __syncthreads();
    for (int i = tid; i < 4096; i += 256) {
        int n = i >> 6, tl = i & 63;
        float v = t[tl][n];
        size_t o = ((size_t)z * 64 + n) * 1024 + tokb * 64 + tl;
        split1(v, H[o], L[o]);
    }
}

// ---------------------------------------------------------------------------
// Gate: MS = s1+s2; depthwise conv-5 over features; MSg = sigmoid(.)*MS -> planes
// ---------------------------------------------------------------------------
__global__ __launch_bounds__(128) void gate_conv(
    const float* __restrict__ qkv1, const float* __restrict__ qkv2,
    const float* __restrict__ w, const float* __restrict__ cb,
    __nv_bfloat16* __restrict__ H, __nv_bfloat16* __restrict__ L)
{
    __shared__ float ms[516];
    const int bn = blockIdx.x, n = bn & 1023, tid = threadIdx.x;
    const float* r1 = qkv1 + (size_t)bn * 2048 + 1536;
    const float* r2 = qkv2 + (size_t)bn * 2048 + 1536;
    for (int f = tid; f < 512; f += 128) ms[f + 2] = r1[f] + r2[f];
    if (tid < 2) { ms[tid] = 0.f; ms[514 + tid] = 0.f; }
    __syncthreads();
    const float w0 = w[n * 5], w1 = w[n * 5 + 1], w2 = w[n * 5 + 2],
                w3 = w[n * 5 + 3], w4 = w[n * 5 + 4], bb = cb[n];
    for (int f = tid; f < 512; f += 128) {
        float a = w0 * ms[f] + w1 * ms[f + 1] + w2 * ms[f + 2]
                + w3 * ms[f + 3] + w4 * ms[f + 4] + bb;
        float s = 1.f / (1.f + __expf(-a));
        float v = s * ms[f + 2];
        split1(v, H[(size_t)bn * 512 + f], L[(size_t)bn * 512 + f]);
    }
}

// ---------------------------------------------------------------------------
// Row softmax: read fp32 P row (1024), write softmax as hi/lo planes.
// ---------------------------------------------------------------------------
__global__ __launch_bounds__(256) void softmax_p(
    const float* __restrict__ P, __nv_bfloat16* __restrict__ H, __nv_bfloat16* __restrict__ L)
{
    const size_t off = ((size_t)blockIdx.y * 1024 + blockIdx.x) * 1024;
    const float* row = P + off;
    const int tid = threadIdx.x, warp = tid >> 5, lane = tid & 31;
    __shared__ float red[10];

    float4 x = *(const float4*)(row + tid * 4);
    float m = fmaxf(fmaxf(x.x, x.y), fmaxf(x.z, x.w));
#pragma unroll
    for (int o = 16; o; o >>= 1) m = fmaxf(m, __shfl_xor_sync(~0u, m, o));
    if (lane == 0) red[warp] = m;
    __syncthreads();
    if (tid == 0) {
        float t = red[0];
#pragma unroll
        for (int i = 1; i < 8; i++) t = fmaxf(t, red[i]);
        red[8] = t;
    }
    __syncthreads();
    m = red[8];
    __syncthreads();

    x.x = __expf(x.x - m); x.y = __expf(x.y - m);
    x.z = __expf(x.z - m); x.w = __expf(x.w - m);
    float s = x.x + x.y + x.z + x.w;
#pragma unroll
    for (int o = 16; o; o >>= 1) s += __shfl_xor_sync(~0u, s, o);
    if (lane == 0) red[warp] = s;
    __syncthreads();
    if (tid == 0) {
        float t = 0.f;
#pragma unroll
        for (int i = 0; i < 8; i++) t += red[i];
        red[9] = t;
    }
    __syncthreads();
    const float inv = 1.f / red[9];
    x.x *= inv; x.y *= inv; x.z *= inv; x.w *= inv;

    __nv_bfloat16 h0, l0, h1, l1, h2, l2, h3, l3;
    split1(x.x, h0, l0); split1(x.y, h1, l1); split1(x.z, h2, l2); split1(x.w, h3, l3);
    __nv_bfloat162 t;
    size_t o = off + tid * 4;
    t.x = h0; t.y = h1; *(__nv_bfloat162*)&H[o]     = t;
    t.x = h2; t.y = h3; *(__nv_bfloat162*)&H[o + 2] = t;
    t.x = l0; t.y = l1; *(__nv_bfloat162*)&L[o]     = t;
    t.x = l2; t.y = l3; *(__nv_bfloat162*)&L[o + 2] = t;
}

// ---------------------------------------------------------------------------
// Launch
// ---------------------------------------------------------------------------
extern "C" void kernel_launch(void* const* d_in, const int* in_sizes, int n_in,
                              void* d_out, int out_size)
{
    const float* x1    = (const float*)d_in[0];
    const float* x2    = (const float*)d_in[1];
    const float* Wqkv1 = (const float*)d_in[2];
    const float* Wqkv2 = (const float*)d_in[3];
    const float* Wout1 = (const float*)d_in[4];
    const float* bout1 = (const float*)d_in[5];
    const float* Wout2 = (const float*)d_in[6];
    const float* bout2 = (const float*)d_in[7];
    const float* convw = (const float*)d_in[8];
    const float* convb = (const float*)d_in[9];
    float* out = (float*)d_out;

    __nv_bfloat16 *xp1, *xp2, *Wq1, *Wq2, *Wo1, *Wo2, *qkvp1, *qkvp2,
                  *vT1, *vT2, *msgp, *Pp, *uT1, *uT2, *tp1, *tp2;
    float *qkv1, *qkv2, *P;
    cudaGetSymbolAddress((void**)&xp1, g_xp1);   cudaGetSymbolAddress((void**)&xp2, g_xp2);
    cudaGetSymbolAddress((void**)&Wq1, g_Wq1);   cudaGetSymbolAddress((void**)&Wq2, g_Wq2);
    cudaGetSymbolAddress((void**)&Wo1, g_Wo1);   cudaGetSymbolAddress((void**)&Wo2, g_Wo2);
    cudaGetSymbolAddress((void**)&qkv1, g_qkv1); cudaGetSymbolAddress((void**)&qkv2, g_qkv2);
    cudaGetSymbolAddress((void**)&qkvp1, g_qkvp1); cudaGetSymbolAddress((void**)&qkvp2, g_qkvp2);
    cudaGetSymbolAddress((void**)&vT1, g_vT1);   cudaGetSymbolAddress((void**)&vT2, g_vT2);
    cudaGetSymbolAddress((void**)&msgp, g_msgp); cudaGetSymbolAddress((void**)&Pp, g_Pp);
    cudaGetSymbolAddress((void**)&uT1, g_uT1);   cudaGetSymbolAddress((void**)&uT2, g_uT2);
    cudaGetSymbolAddress((void**)&tp1, g_tp1);   cudaGetSymbolAddress((void**)&tp2, g_tp2);
    cudaGetSymbolAddress((void**)&P, g_P);

    const long long PX  = 4194304;    // 8192*512 plane elems
    const long long PQ  = 16777216;   // 8192*2048
    const long long PW  = 1048576;    // 2048*512
    const long long PWo = 262144;     // 512*512
    const long long PV  = 4194304;    // 64*64*1024
    const long long PP  = 67108864;   // 64*1024*1024
    const float scale = 0.125f;

    // operand conversion
    convN<<<4096, 256>>>(x1, xp1, xp1 + PX, 1048576);
    convN<<<4096, 256>>>(x2, xp2, xp2 + PX, 1048576);
    convT<<<4096, 256>>>(Wqkv1, Wq1, Wq1 + PW, 512, 2048);
    convT<<<4096, 256>>>(Wqkv2, Wq2, Wq2 + PW, 512, 2048);
    convT<<<1024, 256>>>(Wout1, Wo1, Wo1 + PWo, 512, 512);
    convT<<<1024, 256>>>(Wout2, Wo2, Wo2 + PWo, 512, 512);

    // QKVS projections: fp32 + planes
    gemm_bs<128, F_F32 | F_PLANES><<<dim3(16, 64, 1), 256>>>(
        xp1, xp1 + PX, 512, 0, 0,  Wq1, Wq1 + PW, 512, 0, 0,
        qkv1, 2048, 0, 0,  qkvp1, qkvp1 + PQ, 2048, 0, 0,
        nullptr, 0, 0, 0, nullptr, 1.f, 512);
    gemm_bs<128, F_F32 | F_PLANES><<<dim3(16, 64, 1), 256>>>(
        xp2, xp2 + PX, 512, 0, 0,  Wq2, Wq2 + PW, 512, 0, 0,
        qkv2, 2048, 0, 0,  qkvp2, qkvp2 + PQ, 2048, 0, 0,
        nullptr, 0, 0, 0, nullptr, 1.f, 512);

    gate_conv<<<8192, 128>>>(qkv1, qkv2, convw, convb, msgp, msgp + PX);
    vtrans<<<dim3(16, 64), 256>>>(qkv1, vT1, vT1 + PV);
    vtrans<<<dim3(16, 64), 256>>>(qkv2, vT2, vT2 + PV);

    // Pass 3: a3 = softmax(scale * MSh MSh^T); u = a3 @ v + v   (K = 64 per head!)
    gemm_bs<128, F_F32 | F_SCALE><<<dim3(8, 8, 64), 256>>>(
        msgp, msgp + PX, 512, 524288, 64,  msgp, msgp + PX, 512, 524288, 64,
        P, 1024, 8388608, 1048576,  nullptr, nullptr, 0, 0, 0,
        nullptr, 0, 0, 0, nullptr, scale, 64);
    softmax_p<<<dim3(1024, 64), 256>>>(P, Pp, Pp + PP);
    gemm_bs<64, F_PLT | F_RES><<<dim3(1, 8, 64), 256>>>(
        Pp, Pp + PP, 1024, 8388608, 1048576,  vT1, vT1 + PV, 1024, 524288, 65536,
        nullptr, 0, 0, 0,  uT1, uT1 + PV, 1024, 524288, 65536,
        qkv1 + 1024, 2048, 2097152, 64, nullptr, 1.f, 1024);
    gemm_bs<64, F_PLT | F_RES><<<dim3(1, 8, 64), 256>>>(
        Pp, Pp + PP, 1024, 8388608, 1048576,  vT2, vT2 + PV, 1024, 524288, 65536,
        nullptr, 0, 0, 0,  uT2, uT2 + PV, 1024, 524288, 65536,
        qkv2 + 1024, 2048, 2097152, 64, nullptr, 1.f, 1024);

    // Pass 1: t1 = softmax(scale * q1 k1^T) @ u1
    gemm_bs<128, F_F32 | F_SCALE><<<dim3(8, 8, 64), 256>>>(
        qkvp1, qkvp1 + PQ, 2048, 2097152, 64,  qkvp1 + 512, qkvp1 + PQ + 512, 2048, 2097152, 64,
        P, 1024, 8388608, 1048576,  nullptr, nullptr, 0, 0, 0,
        nullptr, 0, 0, 0, nullptr, scale, 64);
    softmax_p<<<dim3(1024, 64), 256>>>(P, Pp, Pp + PP);
    gemm_bs<64, F_PLANES><<<dim3(1, 8, 64), 256>>>(
        Pp, Pp + PP, 1024, 8388608, 1048576,  uT1, uT1 + PV, 1024, 524288, 65536,
        nullptr, 0, 0, 0,  tp1, tp1 + PX, 512, 524288, 64,
        nullptr, 0, 0, 0, nullptr, 1.f, 1024);

    // Pass 2: t2 = softmax(scale * q2 k2^T) @ u2
    gemm_bs<128, F_F32 | F_SCALE><<<dim3(8, 8, 64), 256>>>(
        qkvp2, qkvp2 + PQ, 2048, 2097152, 64,  qkvp2 + 512, qkvp2 + PQ + 512, 2048, 2097152, 64,
        P, 1024, 8388608, 1048576,  nullptr, nullptr, 0, 0, 0,
        nullptr, 0, 0, 0, nullptr, scale, 64);
    softmax_p<<<dim3(1024, 64), 256>>>(P, Pp, Pp + PP);
    gemm_bs<64, F_PLANES><<<dim3(1, 8, 64), 256>>>(
        Pp, Pp + PP, 1024, 8388608, 1048576,  uT2, uT2 + PV, 1024, 524288, 65536,
        nullptr, 0, 0, 0,  tp2, tp2 + PX, 512, 524288, 64,
        nullptr, 0, 0, 0, nullptr, 1.f, 1024);

    // Output projections
    gemm_bs<128, F_F32 | F_BIAS><<<dim3(4, 64, 1), 256>>>(
        tp1, tp1 + PX, 512, 0, 0,  Wo1, Wo1 + PWo, 512, 0, 0,
        out, 512, 0, 0,  nullptr, nullptr, 0, 0, 0,
        nullptr, 0, 0, 0, bout1, 1.f, 512);
    gemm_bs<128, F_F32 | F_BIAS><<<dim3(4, 64, 1), 256>>>(
        tp2, tp2 + PX, 512, 0, 0,  Wo2, Wo2 + PWo, 512, 0, 0,
        out + 4194304, 512, 0, 0,  nullptr, nullptr, 0, 0, 0,
        nullptr, 0, 0, 0, bout2, 1.f, 512);
}

// round 5
// speedup vs baseline: 2.6585x; 1.5054x over previous
#include <cuda_runtime.h>
#include <cuda_bf16.h>
#include <cstdint>

// ---------------------------------------------------------------------------
// B=8, N=1024, DIM=512, H=8, HD=64, INNER=512, KS=5
// Split-bf16 tensor-core pipeline + fused flash-style attention passes.
// ---------------------------------------------------------------------------

#define F_F32    1
#define F_PLANES 2
#define F_BIAS   16

// ---------------- scratch ---------------------------------------------------
__device__ __nv_bfloat16 g_xp1 [2ull*8192*512];
__device__ __nv_bfloat16 g_xp2 [2ull*8192*512];
__device__ __nv_bfloat16 g_Wq1 [2ull*2048*512];
__device__ __nv_bfloat16 g_Wq2 [2ull*2048*512];
__device__ __nv_bfloat16 g_Wo1 [2ull*512*512];
__device__ __nv_bfloat16 g_Wo2 [2ull*512*512];
__device__ float         g_qkv1[8192ull*2048];
__device__ float         g_qkv2[8192ull*2048];
__device__ __nv_bfloat16 g_qkvp1[2ull*8192*2048];
__device__ __nv_bfloat16 g_qkvp2[2ull*8192*2048];
__device__ __nv_bfloat16 g_vT1 [2ull*64*64*1024];
__device__ __nv_bfloat16 g_vT2 [2ull*64*64*1024];
__device__ __nv_bfloat16 g_msgp[2ull*8192*512];
__device__ __nv_bfloat16 g_uT1 [2ull*64*64*1024];
__device__ __nv_bfloat16 g_uT2 [2ull*64*64*1024];
__device__ __nv_bfloat16 g_tp1 [2ull*8192*512];
__device__ __nv_bfloat16 g_tp2 [2ull*8192*512];

// ---------------- helpers ----------------------------------------------------
__device__ __forceinline__ void split1(float v, __nv_bfloat16& h, __nv_bfloat16& l) {
    h = __float2bfloat16(v);
    l = __float2bfloat16(v - __bfloat162float(h));
}
__device__ __forceinline__ void split2pack(float f0, float f1, uint32_t& hp, uint32_t& lp) {
    __nv_bfloat16 h0, l0, h1, l1;
    split1(f0, h0, l0); split1(f1, h1, l1);
    __nv_bfloat162 th; th.x = h0; th.y = h1; hp = *(uint32_t*)&th;
    __nv_bfloat162 tl; tl.x = l0; tl.y = l1; lp = *(uint32_t*)&tl;
}
__device__ __forceinline__ uint32_t smaddr(const void* p) {
    return (uint32_t)__cvta_generic_to_shared(p);
}
__device__ __forceinline__ void ldsm4(uint32_t& r0, uint32_t& r1, uint32_t& r2, uint32_t& r3, uint32_t a) {
    asm volatile("ldmatrix.sync.aligned.m8n8.x4.shared.b16 {%0,%1,%2,%3},[%4];\n"
                 : "=r"(r0), "=r"(r1), "=r"(r2), "=r"(r3) : "r"(a));
}
__device__ __forceinline__ void ldsm2(uint32_t& r0, uint32_t& r1, uint32_t a) {
    asm volatile("ldmatrix.sync.aligned.m8n8.x2.shared.b16 {%0,%1},[%2];\n"
                 : "=r"(r0), "=r"(r1) : "r"(a));
}
#define MMA16816(c, a, b)                                                            \
    asm volatile("mma.sync.aligned.m16n8k16.row.col.f32.bf16.bf16.f32 "              \
                 "{%0,%1,%2,%3},{%4,%5,%6,%7},{%8,%9},{%0,%1,%2,%3};\n"              \
                 : "+f"((c)[0]), "+f"((c)[1]), "+f"((c)[2]), "+f"((c)[3])            \
                 : "r"((a)[0]), "r"((a)[1]), "r"((a)[2]), "r"((a)[3]),               \
                   "r"((b)[0]), "r"((b)[1]))
#define CPA16(dst, src)                                                              \
    asm volatile("cp.async.ca.shared.global [%0], [%1], 16;\n" :: "r"(dst), "l"(src))
#define CPWAIT() asm volatile("cp.async.wait_all;\n" ::: "memory")

// ---------------------------------------------------------------------------
// Split-bf16 GEMM (projections). Block 128x128xK16, double-buffered.
// ---------------------------------------------------------------------------
template <int FLAGS>
__global__ __launch_bounds__(256) void gemm_bs(
    const __nv_bfloat16* __restrict__ Ah, const __nv_bfloat16* __restrict__ Al, long long lda,
    const __nv_bfloat16* __restrict__ Bh, const __nv_bfloat16* __restrict__ Bl, long long ldb,
    float* __restrict__ C32, long long ldc,
    __nv_bfloat16* __restrict__ Ch, __nv_bfloat16* __restrict__ Cl, long long ldcp,
    const float* __restrict__ bias, int K)
{
    __shared__ __align__(16) __nv_bfloat16 sA[2][2][128][24];
    __shared__ __align__(16) __nv_bfloat16 sB[2][2][128][24];

    const int tid = threadIdx.x;
    const __nv_bfloat16* srcA[2]; int aP[2], aR[2], aH[2];
#pragma unroll
    for (int j = 0; j < 2; j++) {
        int idx = tid + j * 256;
        aP[j] = idx >> 8; int rem = idx & 255; aR[j] = rem >> 1; aH[j] = rem & 1;
        const __nv_bfloat16* base = aP[j] ? Al : Ah;
        srcA[j] = base + (size_t)(blockIdx.y * 128 + aR[j]) * lda + aH[j] * 8;
    }
    const __nv_bfloat16* srcB[2]; int bP[2], bR[2], bH[2];
#pragma unroll
    for (int j = 0; j < 2; j++) {
        int idx = tid + j * 256;
        bP[j] = idx >> 8; int rem = idx & 255; bR[j] = rem >> 1; bH[j] = rem & 1;
        const __nv_bfloat16* base = bP[j] ? Bl : Bh;
        srcB[j] = base + (size_t)(blockIdx.x * 128 + bR[j]) * ldb + bH[j] * 8;
    }
#pragma unroll
    for (int j = 0; j < 2; j++) {
        *(uint4*)&sA[0][aP[j]][aR[j]][aH[j] * 8] = *(const uint4*)srcA[j];
        *(uint4*)&sB[0][bP[j]][bR[j]][bH[j] * 8] = *(const uint4*)srcB[j];
    }
    __syncthreads();

    const int lane = tid & 31, w = tid >> 5;
    const int wm = (w >> 2) * 64, wn = (w & 3) * 32;

    float acc[4][4][4];
#pragma unroll
    for (int i = 0; i < 4; i++)
#pragma unroll
        for (int j = 0; j < 4; j++)
#pragma unroll
            for (int k = 0; k < 4; k++) acc[i][j][k] = 0.f;

    const int nk = K >> 4;
    for (int kt = 0; kt < nk; ++kt) {
        const int cur = kt & 1;
        const bool pf = (kt + 1) < nk;
        uint4 ra[2], rb[2];
        if (pf) {
            long long k0 = (long long)(kt + 1) * 16;
#pragma unroll
            for (int j = 0; j < 2; j++) { ra[j] = *(const uint4*)(srcA[j] + k0); rb[j] = *(const uint4*)(srcB[j] + k0); }
        }
        uint32_t bhf[4][2], blf[4][2], af[4][4];
#pragma unroll
        for (int nf = 0; nf < 4; nf++) {
            ldsm2(bhf[nf][0], bhf[nf][1], smaddr(&sB[cur][0][wn + nf * 8 + (lane & 7)][((lane >> 3) & 1) * 8]));
            ldsm2(blf[nf][0], blf[nf][1], smaddr(&sB[cur][1][wn + nf * 8 + (lane & 7)][((lane >> 3) & 1) * 8]));
        }
#pragma unroll
        for (int mf = 0; mf < 4; mf++)
            ldsm4(af[mf][0], af[mf][1], af[mf][2], af[mf][3],
                  smaddr(&sA[cur][0][wm + mf * 16 + (lane & 15)][(lane >> 4) * 8]));
#pragma unroll
        for (int mf = 0; mf < 4; mf++)
#pragma unroll
            for (int nf = 0; nf < 4; nf++) { MMA16816(acc[mf][nf], af[mf], bhf[nf]); MMA16816(acc[mf][nf], af[mf], blf[nf]); }
#pragma unroll
        for (int mf = 0; mf < 4; mf++)
            ldsm4(af[mf][0], af[mf][1], af[mf][2], af[mf][3],
                  smaddr(&sA[cur][1][wm + mf * 16 + (lane & 15)][(lane >> 4) * 8]));
#pragma unroll
        for (int mf = 0; mf < 4; mf++)
#pragma unroll
            for (int nf = 0; nf < 4; nf++) MMA16816(acc[mf][nf], af[mf], bhf[nf]);
        if (pf) {
            const int nb = cur ^ 1;
#pragma unroll
            for (int j = 0; j < 2; j++) {
                *(uint4*)&sA[nb][aP[j]][aR[j]][aH[j] * 8] = ra[j];
                *(uint4*)&sB[nb][bP[j]][bR[j]][bH[j] * 8] = rb[j];
            }
        }
        __syncthreads();
    }

#pragma unroll
    for (int mf = 0; mf < 4; mf++) {
        const int r0 = blockIdx.y * 128 + wm + mf * 16 + (lane >> 2);
#pragma unroll
        for (int nf = 0; nf < 4; nf++) {
            const int c0 = blockIdx.x * 128 + wn + nf * 8 + (lane & 3) * 2;
            float v00 = acc[mf][nf][0], v01 = acc[mf][nf][1];
            float v10 = acc[mf][nf][2], v11 = acc[mf][nf][3];
            if constexpr (FLAGS & F_BIAS) {
                float b0 = bias[c0], b1 = bias[c0 + 1];
                v00 += b0; v01 += b1; v10 += b0; v11 += b1;
            }
            if constexpr (FLAGS & F_F32) {
                *(float2*)&C32[(size_t)r0 * ldc + c0]       = make_float2(v00, v01);
                *(float2*)&C32[(size_t)(r0 + 8) * ldc + c0] = make_float2(v10, v11);
            }
            if constexpr (FLAGS & F_PLANES) {
                uint32_t hp, lp;
                split2pack(v00, v01, hp, lp);
                *(uint32_t*)&Ch[(size_t)r0 * ldcp + c0] = hp;
                *(uint32_t*)&Cl[(size_t)r0 * ldcp + c0] = lp;
                split2pack(v10, v11, hp, lp);
                *(uint32_t*)&Ch[(size_t)(r0 + 8) * ldcp + c0] = hp;
                *(uint32_t*)&Cl[(size_t)(r0 + 8) * ldcp + c0] = lp;
            }
        }
    }
}

// ---------------------------------------------------------------------------
// Fused flash attention. NV=2 (pass3): dual V streams + residual + transposed
// plane output (uT layout). NV=1 (pass1/2): single V, row-major plane output.
// Grid (8, 1, 64); 256 threads; dynamic smem.
// ---------------------------------------------------------------------------
template <int NV>
__global__ __launch_bounds__(256) void fattn(
    const __nv_bfloat16* __restrict__ Qh, const __nv_bfloat16* __restrict__ Ql,
    long long ldq, long long qob, long long qoh,
    const __nv_bfloat16* __restrict__ Kh, const __nv_bfloat16* __restrict__ Kl,
    long long ldk, long long kob, long long koh,
    const __nv_bfloat16* __restrict__ V1h, const __nv_bfloat16* __restrict__ V1l,
    const __nv_bfloat16* __restrict__ V2h, const __nv_bfloat16* __restrict__ V2l,
    const float* __restrict__ R1, const float* __restrict__ R2,
    __nv_bfloat16* __restrict__ O1h, __nv_bfloat16* __restrict__ O1l,
    __nv_bfloat16* __restrict__ O2h, __nv_bfloat16* __restrict__ O2l)
{
    constexpr int SKP = 128 * 72;   // K/Q plane tile elems
    constexpr int SVP = 64 * 136;   // V plane tile elems
    extern __shared__ __align__(16) __nv_bfloat16 sm[];
    __nv_bfloat16* sKh = sm;
    __nv_bfloat16* sKl = sm + SKP;
    __nv_bfloat16* sV1h = sm + 2 * SKP;
    __nv_bfloat16* sV1l = sV1h + SVP;
    __nv_bfloat16* sV2h = sV1l + SVP;
    __nv_bfloat16* sV2l = sV2h + SVP;

    const int tid = threadIdx.x, lane = tid & 31, w = tid >> 5;
    const int wm = w * 16;
    const int z = blockIdx.z, zb = z >> 3, zh = z & 7;
    const int tok0 = blockIdx.x * 128;

    const __nv_bfloat16* Qbh = Qh + zb * qob + zh * qoh + (long long)tok0 * ldq;
    const __nv_bfloat16* Qbl = Ql + zb * qob + zh * qoh + (long long)tok0 * ldq;
    const __nv_bfloat16* Kbh = Kh + zb * kob + zh * koh;
    const __nv_bfloat16* Kbl = Kl + zb * kob + zh * koh;
    const __nv_bfloat16* V1bh = V1h + (size_t)z * 65536;
    const __nv_bfloat16* V1bl = V1l + (size_t)z * 65536;
    const __nv_bfloat16* V2bh = (NV == 2) ? V2h + (size_t)z * 65536 : nullptr;
    const __nv_bfloat16* V2bl = (NV == 2) ? V2l + (size_t)z * 65536 : nullptr;

    // ---- stage Q (scaled by 2^-3, exact on both planes) into sK, ldmatrix ----
    {
        __nv_bfloat162 sc = __float2bfloat162_rn(0.125f);
        for (int i = tid; i < 1024; i += 256) {
            int r = i >> 3, c = (i & 7) * 8;
            const __nv_bfloat162* s0 = (const __nv_bfloat162*)(Qbh + (size_t)r * ldq + c);
            __nv_bfloat162* d0 = (__nv_bfloat162*)&sKh[r * 72 + c];
            d0[0] = __hmul2(s0[0], sc); d0[1] = __hmul2(s0[1], sc);
            d0[2] = __hmul2(s0[2], sc); d0[3] = __hmul2(s0[3], sc);
            const __nv_bfloat162* s1 = (const __nv_bfloat162*)(Qbl + (size_t)r * ldq + c);
            __nv_bfloat162* d1 = (__nv_bfloat162*)&sKl[r * 72 + c];
            d1[0] = __hmul2(s1[0], sc); d1[1] = __hmul2(s1[1], sc);
            d1[2] = __hmul2(s1[2], sc); d1[3] = __hmul2(s1[3], sc);
        }
    }
    __syncthreads();
    uint32_t qh[4][4], ql[4][4];
#pragma unroll
    for (int kc = 0; kc < 4; kc++) {
        ldsm4(qh[kc][0], qh[kc][1], qh[kc][2], qh[kc][3],
              smaddr(&sKh[(wm + (lane & 15)) * 72 + kc * 16 + (lane >> 4) * 8]));
        ldsm4(ql[kc][0], ql[kc][1], ql[kc][2], ql[kc][3],
              smaddr(&sKl[(wm + (lane & 15)) * 72 + kc * 16 + (lane >> 4) * 8]));
    }
    __syncthreads();

    float m0 = -1e30f, m1 = -1e30f, l0 = 0.f, l1 = 0.f;
    float O1a[8][4], O2a[8][4];
#pragma unroll
    for (int i = 0; i < 8; i++)
#pragma unroll
        for (int j = 0; j < 4; j++) { O1a[i][j] = 0.f; if (NV == 2) O2a[i][j] = 0.f; }

    for (int kt = 0; kt < 8; kt++) {
        // ---- async stage K + V tiles ----
        for (int i = tid; i < 1024; i += 256) {
            int r = i >> 3, c = (i & 7) * 8;
            CPA16(smaddr(&sKh[r * 72 + c]), Kbh + (size_t)(kt * 128 + r) * ldk + c);
            CPA16(smaddr(&sKl[r * 72 + c]), Kbl + (size_t)(kt * 128 + r) * ldk + c);
        }
        for (int i = tid; i < 1024; i += 256) {
            int d = i >> 4, c = (i & 15) * 8;
            size_t so = (size_t)d * 1024 + kt * 128 + c;
            CPA16(smaddr(&sV1h[d * 136 + c]), V1bh + so);
            CPA16(smaddr(&sV1l[d * 136 + c]), V1bl + so);
            if (NV == 2) {
                CPA16(smaddr(&sV2h[d * 136 + c]), V2bh + so);
                CPA16(smaddr(&sV2l[d * 136 + c]), V2bl + so);
            }
        }
        CPWAIT();
        __syncthreads();

        // ---- S = Q K^T (3-term split) ----
        float sacc[16][4];
#pragma unroll
        for (int nf = 0; nf < 16; nf++)
#pragma unroll
            for (int j = 0; j < 4; j++) sacc[nf][j] = 0.f;
#pragma unroll
        for (int nf = 0; nf < 16; nf++) {
#pragma unroll
            for (int kc = 0; kc < 4; kc++) {
                uint32_t bh[2], bl[2];
                int off = (nf * 8 + (lane & 7)) * 72 + kc * 16 + ((lane >> 3) & 1) * 8;
                ldsm2(bh[0], bh[1], smaddr(&sKh[off]));
                ldsm2(bl[0], bl[1], smaddr(&sKl[off]));
                MMA16816(sacc[nf], qh[kc], bh);
                MMA16816(sacc[nf], qh[kc], bl);
                MMA16816(sacc[nf], ql[kc], bh);
            }
        }

        // ---- online softmax ----
        float tm0 = -1e30f, tm1 = -1e30f;
#pragma unroll
        for (int nf = 0; nf < 16; nf++) {
            tm0 = fmaxf(tm0, fmaxf(sacc[nf][0], sacc[nf][1]));
            tm1 = fmaxf(tm1, fmaxf(sacc[nf][2], sacc[nf][3]));
        }
        tm0 = fmaxf(tm0, __shfl_xor_sync(~0u, tm0, 1));
        tm0 = fmaxf(tm0, __shfl_xor_sync(~0u, tm0, 2));
        tm1 = fmaxf(tm1, __shfl_xor_sync(~0u, tm1, 1));
        tm1 = fmaxf(tm1, __shfl_xor_sync(~0u, tm1, 2));
        float mn0 = fmaxf(m0, tm0), mn1 = fmaxf(m1, tm1);
        float a0 = __expf(m0 - mn0), a1 = __expf(m1 - mn1);
        m0 = mn0; m1 = mn1;
        float rs0 = 0.f, rs1 = 0.f;
#pragma unroll
        for (int nf = 0; nf < 16; nf++) {
            float p0 = __expf(sacc[nf][0] - mn0); sacc[nf][0] = p0; rs0 += p0;
            float p1 = __expf(sacc[nf][1] - mn0); sacc[nf][1] = p1; rs0 += p1;
            float p2 = __expf(sacc[nf][2] - mn1); sacc[nf][2] = p2; rs1 += p2;
            float p3 = __expf(sacc[nf][3] - mn1); sacc[nf][3] = p3; rs1 += p3;
        }
        rs0 += __shfl_xor_sync(~0u, rs0, 1); rs0 += __shfl_xor_sync(~0u, rs0, 2);
        rs1 += __shfl_xor_sync(~0u, rs1, 1); rs1 += __shfl_xor_sync(~0u, rs1, 2);
        l0 = l0 * a0 + rs0; l1 = l1 * a1 + rs1;
#pragma unroll
        for (int vnf = 0; vnf < 8; vnf++) {
            O1a[vnf][0] *= a0; O1a[vnf][1] *= a0; O1a[vnf][2] *= a1; O1a[vnf][3] *= a1;
            if (NV == 2) { O2a[vnf][0] *= a0; O2a[vnf][1] *= a0; O2a[vnf][2] *= a1; O2a[vnf][3] *= a1; }
        }

        // ---- O += P V (3-term split) ----
#pragma unroll
        for (int kcp = 0; kcp < 8; kcp++) {
            uint32_t ph[4], pl[4];
            split2pack(sacc[2 * kcp][0],     sacc[2 * kcp][1],     ph[0], pl[0]);
            split2pack(sacc[2 * kcp][2],     sacc[2 * kcp][3],     ph[1], pl[1]);
            split2pack(sacc[2 * kcp + 1][0], sacc[2 * kcp + 1][1], ph[2], pl[2]);
            split2pack(sacc[2 * kcp + 1][2], sacc[2 * kcp + 1][3], ph[3], pl[3]);
#pragma unroll
            for (int vnf = 0; vnf < 8; vnf++) {
                int off = (vnf * 8 + (lane & 7)) * 136 + kcp * 16 + ((lane >> 3) & 1) * 8;
                uint32_t vh[2], vl[2];
                ldsm2(vh[0], vh[1], smaddr(&sV1h[off]));
                ldsm2(vl[0], vl[1], smaddr(&sV1l[off]));
                MMA16816(O1a[vnf], ph, vh);
                MMA16816(O1a[vnf], ph, vl);
                MMA16816(O1a[vnf], pl, vh);
                if (NV == 2) {
                    uint32_t wh[2], wl[2];
                    ldsm2(wh[0], wh[1], smaddr(&sV2h[off]));
                    ldsm2(wl[0], wl[1], smaddr(&sV2l[off]));
                    MMA16816(O2a[vnf], ph, wh);
                    MMA16816(O2a[vnf], ph, wl);
                    MMA16816(O2a[vnf], pl, wh);
                }
            }
        }
        __syncthreads();
    }

    // ---- finalize ----
    const float i0 = 1.f / l0, i1 = 1.f / l1;
#pragma unroll
    for (int vnf = 0; vnf < 8; vnf++) {
        O1a[vnf][0] *= i0; O1a[vnf][1] *= i0; O1a[vnf][2] *= i1; O1a[vnf][3] *= i1;
        if (NV == 2) { O2a[vnf][0] *= i0; O2a[vnf][1] *= i0; O2a[vnf][2] *= i1; O2a[vnf][3] *= i1; }
    }

    const int r = wm + (lane >> 2);
    if (NV == 2) {
        // residual add (u = a3 @ v + v)
        const float* R1p = R1 + (size_t)zb * 2097152 + (size_t)zh * 64;
        const float* R2p = R2 + (size_t)zb * 2097152 + (size_t)zh * 64;
        const size_t row = (size_t)(tok0 + r);
#pragma unroll
        for (int vnf = 0; vnf < 8; vnf++) {
            int c0 = vnf * 8 + (lane & 3) * 2;
            float2 ra = *(const float2*)&R1p[row * 2048 + c0];
            float2 rb = *(const float2*)&R1p[(row + 8) * 2048 + c0];
            O1a[vnf][0] += ra.x; O1a[vnf][1] += ra.y; O1a[vnf][2] += rb.x; O1a[vnf][3] += rb.y;
            float2 rc = *(const float2*)&R2p[row * 2048 + c0];
            float2 rd = *(const float2*)&R2p[(row + 8) * 2048 + c0];
            O2a[vnf][0] += rc.x; O2a[vnf][1] += rc.y; O2a[vnf][2] += rd.x; O2a[vnf][3] += rd.y;
        }
        // transposed plane output via smem bounce
#pragma unroll
        for (int s = 0; s < 2; s++) {
            float (*Oa)[4] = s ? O2a : O1a;
#pragma unroll
            for (int vnf = 0; vnf < 8; vnf++) {
                int c0 = vnf * 8 + (lane & 3) * 2;
                uint32_t hp, lp;
                split2pack(Oa[vnf][0], Oa[vnf][1], hp, lp);
                *(uint32_t*)&sKh[r * 72 + c0] = hp;
                *(uint32_t*)&sKl[r * 72 + c0] = lp;
                split2pack(Oa[vnf][2], Oa[vnf][3], hp, lp);
                *(uint32_t*)&sKh[(r + 8) * 72 + c0] = hp;
                *(uint32_t*)&sKl[(r + 8) * 72 + c0] = lp;
            }
            __syncthreads();
            __nv_bfloat16* OH = (s ? O2h : O1h) + (size_t)z * 65536 + tok0;
            __nv_bfloat16* OL = (s ? O2l : O1l) + (size_t)z * 65536 + tok0;
            for (int i = tid; i < 2048; i += 256) {
                int plane = i >> 10, rem = i & 1023, d = rem >> 4, ch = (rem & 15) * 8;
                const unsigned short* src = (const unsigned short*)(plane ? sKl : sKh);
                unsigned short v[8];
#pragma unroll
                for (int j = 0; j < 8; j++) v[j] = src[(ch + j) * 72 + d];
                uint4 pk;
                pk.x = (uint32_t)v[0] | ((uint32_t)v[1] << 16);
                pk.y = (uint32_t)v[2] | ((uint32_t)v[3] << 16);
                pk.z = (uint32_t)v[4] | ((uint32_t)v[5] << 16);
                pk.w = (uint32_t)v[6] | ((uint32_t)v[7] << 16);
                *(uint4*)((plane ? OL : OH) + (size_t)d * 1024 + ch) = pk;
            }
            __syncthreads();
        }
    } else {
        // row-major plane output
        __nv_bfloat16* OH = O1h + (size_t)zb * 524288 + zh * 64;
        __nv_bfloat16* OL = O1l + (size_t)zb * 524288 + zh * 64;
        const size_t row = (size_t)(tok0 + r);
#pragma unroll
        for (int vnf = 0; vnf < 8; vnf++) {
            int c0 = vnf * 8 + (lane & 3) * 2;
            uint32_t hp, lp;
            split2pack(O1a[vnf][0], O1a[vnf][1], hp, lp);
            *(uint32_t*)&OH[row * 512 + c0] = hp;
            *(uint32_t*)&OL[row * 512 + c0] = lp;
            split2pack(O1a[vnf][2], O1a[vnf][3], hp, lp);
            *(uint32_t*)&OH[(row + 8) * 512 + c0] = hp;
            *(uint32_t*)&OL[(row + 8) * 512 + c0] = lp;
        }
    }
}

// ---------------------------------------------------------------------------
// Converters / gate / vtrans
// ---------------------------------------------------------------------------
__global__ void convN(const float* __restrict__ X, __nv_bfloat16* __restrict__ H,
                      __nv_bfloat16* __restrict__ L, int n4)
{
    int i = blockIdx.x * blockDim.x + threadIdx.x;
    if (i >= n4) return;
    float4 v = ((const float4*)X)[i];
    uint32_t hp, lp;
    split2pack(v.x, v.y, hp, lp);
    *(uint32_t*)&H[(size_t)i * 4] = hp; *(uint32_t*)&L[(size_t)i * 4] = lp;
    split2pack(v.z, v.w, hp, lp);
    *(uint32_t*)&H[(size_t)i * 4 + 2] = hp; *(uint32_t*)&L[(size_t)i * 4 + 2] = lp;
}

__global__ void convT(const float* __restrict__ W, __nv_bfloat16* __restrict__ H,
                      __nv_bfloat16* __restrict__ L, int K, int N)
{
    int i = blockIdx.x * blockDim.x + threadIdx.x;
    if (i >= K * N) return;
    int n = i / K, k = i % K;
    float v = W[(size_t)k * N + n];
    split1(v, H[i], L[i]);
}

__global__ void vtrans(const float* __restrict__ qkv, __nv_bfloat16* __restrict__ H,
                       __nv_bfloat16* __restrict__ L)
{
    __shared__ float t[64][65];
    const int z = blockIdx.y, tokb = blockIdx.x, b = z >> 3, h = z & 7;
    const int tid = threadIdx.x;
    for (int i = tid; i < 4096; i += 256) {
        int tl = i >> 6, n = i & 63;
        t[tl][n] = qkv[(size_t)(b * 1024 + tokb * 64 + tl) * 2048 + 1024 + h * 64 + n];
    }
    __syncthreads();
    for (int i = tid; i < 4096; i += 256) {
        int n = i >> 6, tl = i & 63;
        float v = t[tl][n];
        size_t o = ((size_t)z * 64 + n) * 1024 + tokb * 64 + tl;
        split1(v, H[o], L[o]);
    }
}

__global__ __launch_bounds__(128) void gate_conv(
    const float* __restrict__ qkv1, const float* __restrict__ qkv2,
    const float* __restrict__ w, const float* __restrict__ cb,
    __nv_bfloat16* __restrict__ H, __nv_bfloat16* __restrict__ L)
{
    __shared__ float ms[516];
    const int bn = blockIdx.x, n = bn & 1023, tid = threadIdx.x;
    const float* r1 = qkv1 + (size_t)bn * 2048 + 1536;
    const float* r2 = qkv2 + (size_t)bn * 2048 + 1536;
    for (int f = tid; f < 512; f += 128) ms[f + 2] = r1[f] + r2[f];
    if (tid < 2) { ms[tid] = 0.f; ms[514 + tid] = 0.f; }
    __syncthreads();
    const float w0 = w[n * 5], w1 = w[n * 5 + 1], w2 = w[n * 5 + 2],
                w3 = w[n * 5 + 3], w4 = w[n * 5 + 4], bb = cb[n];
    for (int f = tid; f < 512; f += 128) {
        float a = w0 * ms[f] + w1 * ms[f + 1] + w2 * ms[f + 2]
                + w3 * ms[f + 3] + w4 * ms[f + 4] + bb;
        float s = 1.f / (1.f + __expf(-a));
        float v = s * ms[f + 2];
        split1(v, H[(size_t)bn * 512 + f], L[(size_t)bn * 512 + f]);
    }
}

// ---------------------------------------------------------------------------
// Launch
// ---------------------------------------------------------------------------
extern "C" void kernel_launch(void* const* d_in, const int* in_sizes, int n_in,
                              void* d_out, int out_size)
{
    const float* x1    = (const float*)d_in[0];
    const float* x2    = (const float*)d_in[1];
    const float* Wqkv1 = (const float*)d_in[2];
    const float* Wqkv2 = (const float*)d_in[3];
    const float* Wout1 = (const float*)d_in[4];
    const float* bout1 = (const float*)d_in[5];
    const float* Wout2 = (const float*)d_in[6];
    const float* bout2 = (const float*)d_in[7];
    const float* convw = (const float*)d_in[8];
    const float* convb = (const float*)d_in[9];
    float* out = (float*)d_out;

    __nv_bfloat16 *xp1, *xp2, *Wq1, *Wq2, *Wo1, *Wo2, *qkvp1, *qkvp2,
                  *vT1, *vT2, *msgp, *uT1, *uT2, *tp1, *tp2;
    float *qkv1, *qkv2;
    cudaGetSymbolAddress((void**)&xp1, g_xp1);   cudaGetSymbolAddress((void**)&xp2, g_xp2);
    cudaGetSymbolAddress((void**)&Wq1, g_Wq1);   cudaGetSymbolAddress((void**)&Wq2, g_Wq2);
    cudaGetSymbolAddress((void**)&Wo1, g_Wo1);   cudaGetSymbolAddress((void**)&Wo2, g_Wo2);
    cudaGetSymbolAddress((void**)&qkv1, g_qkv1); cudaGetSymbolAddress((void**)&qkv2, g_qkv2);
    cudaGetSymbolAddress((void**)&qkvp1, g_qkvp1); cudaGetSymbolAddress((void**)&qkvp2, g_qkvp2);
    cudaGetSymbolAddress((void**)&vT1, g_vT1);   cudaGetSymbolAddress((void**)&vT2, g_vT2);
    cudaGetSymbolAddress((void**)&msgp, g_msgp);
    cudaGetSymbolAddress((void**)&uT1, g_uT1);   cudaGetSymbolAddress((void**)&uT2, g_uT2);
    cudaGetSymbolAddress((void**)&tp1, g_tp1);   cudaGetSymbolAddress((void**)&tp2, g_tp2);

    const long long PX  = 4194304;    // 8192*512
    const long long PQ  = 16777216;   // 8192*2048
    const long long PW  = 1048576;    // 2048*512
    const long long PWo = 262144;     // 512*512
    const long long PV  = 4194304;    // 64*64*1024

    const int SMEM2 = (2 * 128 * 72 + 4 * 64 * 136) * 2;  // 106496
    const int SMEM1 = (2 * 128 * 72 + 2 * 64 * 136) * 2;  // 71680
    cudaFuncSetAttribute(fattn<2>, cudaFuncAttributeMaxDynamicSharedMemorySize, SMEM2);
    cudaFuncSetAttribute(fattn<1>, cudaFuncAttributeMaxDynamicSharedMemorySize, SMEM1);

    // operand conversion
    convN<<<4096, 256>>>(x1, xp1, xp1 + PX, 1048576);
    convN<<<4096, 256>>>(x2, xp2, xp2 + PX, 1048576);
    convT<<<4096, 256>>>(Wqkv1, Wq1, Wq1 + PW, 512, 2048);
    convT<<<4096, 256>>>(Wqkv2, Wq2, Wq2 + PW, 512, 2048);
    convT<<<1024, 256>>>(Wout1, Wo1, Wo1 + PWo, 512, 512);
    convT<<<1024, 256>>>(Wout2, Wo2, Wo2 + PWo, 512, 512);

    // QKVS projections
    gemm_bs<F_F32 | F_PLANES><<<dim3(16, 64), 256>>>(
        xp1, xp1 + PX, 512, Wq1, Wq1 + PW, 512,
        qkv1, 2048, qkvp1, qkvp1 + PQ, 2048, nullptr, 512);
    gemm_bs<F_F32 | F_PLANES><<<dim3(16, 64), 256>>>(
        xp2, xp2 + PX, 512, Wq2, Wq2 + PW, 512,
        qkv2, 2048, qkvp2, qkvp2 + PQ, 2048, nullptr, 512);

    gate_conv<<<8192, 128>>>(qkv1, qkv2, convw, convb, msgp, msgp + PX);
    vtrans<<<dim3(16, 64), 256>>>(qkv1, vT1, vT1 + PV);
    vtrans<<<dim3(16, 64), 256>>>(qkv2, vT2, vT2 + PV);

    // Pass 3 fused: a3 = softmax(MSh MSh^T * scale); u_i = a3 @ v_i + v_i
    fattn<2><<<dim3(8, 1, 64), 256, SMEM2>>>(
        msgp, msgp + PX, 512, 524288, 64,
        msgp, msgp + PX, 512, 524288, 64,
        vT1, vT1 + PV, vT2, vT2 + PV,
        qkv1 + 1024, qkv2 + 1024,
        uT1, uT1 + PV, uT2, uT2 + PV);

    // Pass 1 fused: t1 = softmax(q1 k1^T * scale) @ u1
    fattn<1><<<dim3(8, 1, 64), 256, SMEM1>>>(
        qkvp1, qkvp1 + PQ, 2048, 2097152, 64,
        qkvp1 + 512, qkvp1 + PQ + 512, 2048, 2097152, 64,
        uT1, uT1 + PV, nullptr, nullptr,
        nullptr, nullptr,
        tp1, tp1 + PX, nullptr, nullptr);

    // Pass 2 fused: t2 = softmax(q2 k2^T * scale) @ u2
    fattn<1><<<dim3(8, 1, 64), 256, SMEM1>>>(
        qkvp2, qkvp2 + PQ, 2048, 2097152, 64,
        qkvp2 + 512, qkvp2 + PQ + 512, 2048, 2097152, 64,
        uT2, uT2 + PV, nullptr, nullptr,
        nullptr, nullptr,
        tp2, tp2 + PX, nullptr, nullptr);

    // Output projections
    gemm_bs<F_F32 | F_BIAS><<<dim3(4, 64), 256>>>(
        tp1, tp1 + PX, 512, Wo1, Wo1 + PWo, 512,
        out, 512, nullptr, nullptr, 0, bout1, 512);
    gemm_bs<F_F32 | F_BIAS><<<dim3(4, 64), 256>>>(
        tp2, tp2 + PX, 512, Wo2, Wo2 + PWo, 512,
        out + 4194304, 512, nullptr, nullptr, 0, bout2, 512);
}

// round 7
// speedup vs baseline: 2.7951x; 1.0514x over previous
#include <cuda_runtime.h>
#include <cuda_bf16.h>
#include <cstdint>

// ---------------------------------------------------------------------------
// B=8, N=1024, DIM=512, H=8, HD=64, INNER=512, KS=5
// Split-bf16 tensor-core pipeline + fused flash-style attention passes.
// ---------------------------------------------------------------------------

#define F_F32    1
#define F_PLANES 2
#define F_BIAS   16
#define F_QKVSPL 32

// ---------------- scratch ---------------------------------------------------
__device__ __nv_bfloat16 g_xp1 [2ull*8192*512];
__device__ __nv_bfloat16 g_xp2 [2ull*8192*512];
__device__ __nv_bfloat16 g_Wq1 [2ull*2048*512];
__device__ __nv_bfloat16 g_Wq2 [2ull*2048*512];
__device__ __nv_bfloat16 g_Wo1 [2ull*512*512];
__device__ __nv_bfloat16 g_Wo2 [2ull*512*512];
__device__ float         g_qkv1[8192ull*2048];
__device__ float         g_qkv2[8192ull*2048];
__device__ __nv_bfloat16 g_qkvp1[2ull*8192*2048];
__device__ __nv_bfloat16 g_qkvp2[2ull*8192*2048];
__device__ __nv_bfloat16 g_vT1 [2ull*64*64*1024];
__device__ __nv_bfloat16 g_vT2 [2ull*64*64*1024];
__device__ __nv_bfloat16 g_msgp[2ull*8192*512];
__device__ __nv_bfloat16 g_uT1 [2ull*64*64*1024];
__device__ __nv_bfloat16 g_uT2 [2ull*64*64*1024];
__device__ __nv_bfloat16 g_tp1 [2ull*8192*512];
__device__ __nv_bfloat16 g_tp2 [2ull*8192*512];

// ---------------- helpers ----------------------------------------------------
__device__ __forceinline__ void split1(float v, __nv_bfloat16& h, __nv_bfloat16& l) {
    h = __float2bfloat16(v);
    l = __float2bfloat16(v - __bfloat162float(h));
}
__device__ __forceinline__ void split2pack(float f0, float f1, uint32_t& hp, uint32_t& lp) {
    __nv_bfloat16 h0, l0, h1, l1;
    split1(f0, h0, l0); split1(f1, h1, l1);
    __nv_bfloat162 th; th.x = h0; th.y = h1; hp = *(uint32_t*)&th;
    __nv_bfloat162 tl; tl.x = l0; tl.y = l1; lp = *(uint32_t*)&tl;
}
__device__ __forceinline__ uint32_t smaddr(const void* p) {
    return (uint32_t)__cvta_generic_to_shared(p);
}
__device__ __forceinline__ void ldsm4(uint32_t& r0, uint32_t& r1, uint32_t& r2, uint32_t& r3, uint32_t a) {
    asm volatile("ldmatrix.sync.aligned.m8n8.x4.shared.b16 {%0,%1,%2,%3},[%4];\n"
                 : "=r"(r0), "=r"(r1), "=r"(r2), "=r"(r3) : "r"(a));
}
__device__ __forceinline__ void ldsm2(uint32_t& r0, uint32_t& r1, uint32_t a) {
    asm volatile("ldmatrix.sync.aligned.m8n8.x2.shared.b16 {%0,%1},[%2];\n"
                 : "=r"(r0), "=r"(r1) : "r"(a));
}
#define MMA16816(c, a, b)                                                            \
    asm volatile("mma.sync.aligned.m16n8k16.row.col.f32.bf16.bf16.f32 "              \
                 "{%0,%1,%2,%3},{%4,%5,%6,%7},{%8,%9},{%0,%1,%2,%3};\n"              \
                 : "+f"((c)[0]), "+f"((c)[1]), "+f"((c)[2]), "+f"((c)[3])            \
                 : "r"((a)[0]), "r"((a)[1]), "r"((a)[2]), "r"((a)[3]),               \
                   "r"((b)[0]), "r"((b)[1]))
#define CPA16(dst, src)                                                              \
    asm volatile("cp.async.ca.shared.global [%0], [%1], 16;\n" :: "r"(dst), "l"(src))
#define CPCOMMIT() asm volatile("cp.async.commit_group;\n" ::: "memory")
#define CPWAIT1()  asm volatile("cp.async.wait_group 1;\n" ::: "memory")
#define CPWAIT0()  asm volatile("cp.async.wait_group 0;\n" ::: "memory")

// ---------------------------------------------------------------------------
// Split-bf16 GEMM (projections). Block 128x128xK16, double-buffered.
// ---------------------------------------------------------------------------
template <int FLAGS>
__global__ __launch_bounds__(256) void gemm_bs(
    const __nv_bfloat16* __restrict__ Ah, const __nv_bfloat16* __restrict__ Al, long long lda,
    const __nv_bfloat16* __restrict__ Bh, const __nv_bfloat16* __restrict__ Bl, long long ldb,
    float* __restrict__ C32, long long ldc,
    __nv_bfloat16* __restrict__ Ch, __nv_bfloat16* __restrict__ Cl, long long ldcp,
    const float* __restrict__ bias, int K)
{
    __shared__ __align__(16) __nv_bfloat16 sA[2][2][128][24];
    __shared__ __align__(16) __nv_bfloat16 sB[2][2][128][24];

    const int tid = threadIdx.x;
    const __nv_bfloat16* srcA[2]; int aP[2], aR[2], aH[2];
#pragma unroll
    for (int j = 0; j < 2; j++) {
        int idx = tid + j * 256;
        aP[j] = idx >> 8; int rem = idx & 255; aR[j] = rem >> 1; aH[j] = rem & 1;
        const __nv_bfloat16* base = aP[j] ? Al : Ah;
        srcA[j] = base + (size_t)(blockIdx.y * 128 + aR[j]) * lda + aH[j] * 8;
    }
    const __nv_bfloat16* srcB[2]; int bP[2], bR[2], bH[2];
#pragma unroll
    for (int j = 0; j < 2; j++) {
        int idx = tid + j * 256;
        bP[j] = idx >> 8; int rem = idx & 255; bR[j] = rem >> 1; bH[j] = rem & 1;
        const __nv_bfloat16* base = bP[j] ? Bl : Bh;
        srcB[j] = base + (size_t)(blockIdx.x * 128 + bR[j]) * ldb + bH[j] * 8;
    }
#pragma unroll
    for (int j = 0; j < 2; j++) {
        *(uint4*)&sA[0][aP[j]][aR[j]][aH[j] * 8] = *(const uint4*)srcA[j];
        *(uint4*)&sB[0][bP[j]][bR[j]][bH[j] * 8] = *(const uint4*)srcB[j];
    }
    __syncthreads();

    const int lane = tid & 31, w = tid >> 5;
    const int wm = (w >> 2) * 64, wn = (w & 3) * 32;

    float acc[4][4][4];
#pragma unroll
    for (int i = 0; i < 4; i++)
#pragma unroll
        for (int j = 0; j < 4; j++)
#pragma unroll
            for (int k = 0; k < 4; k++) acc[i][j][k] = 0.f;

    const int nk = K >> 4;
    for (int kt = 0; kt < nk; ++kt) {
        const int cur = kt & 1;
        const bool pf = (kt + 1) < nk;
        uint4 ra[2], rb[2];
        if (pf) {
            long long k0 = (long long)(kt + 1) * 16;
#pragma unroll
            for (int j = 0; j < 2; j++) { ra[j] = *(const uint4*)(srcA[j] + k0); rb[j] = *(const uint4*)(srcB[j] + k0); }
        }
        uint32_t bhf[4][2], blf[4][2], af[4][4];
#pragma unroll
        for (int nf = 0; nf < 4; nf++) {
            ldsm2(bhf[nf][0], bhf[nf][1], smaddr(&sB[cur][0][wn + nf * 8 + (lane & 7)][((lane >> 3) & 1) * 8]));
            ldsm2(blf[nf][0], blf[nf][1], smaddr(&sB[cur][1][wn + nf * 8 + (lane & 7)][((lane >> 3) & 1) * 8]));
        }
#pragma unroll
        for (int mf = 0; mf < 4; mf++)
            ldsm4(af[mf][0], af[mf][1], af[mf][2], af[mf][3],
                  smaddr(&sA[cur][0][wm + mf * 16 + (lane & 15)][(lane >> 4) * 8]));
#pragma unroll
        for (int mf = 0; mf < 4; mf++)
#pragma unroll
            for (int nf = 0; nf < 4; nf++) { MMA16816(acc[mf][nf], af[mf], bhf[nf]); MMA16816(acc[mf][nf], af[mf], blf[nf]); }
#pragma unroll
        for (int mf = 0; mf < 4; mf++)
            ldsm4(af[mf][0], af[mf][1], af[mf][2], af[mf][3],
                  smaddr(&sA[cur][1][wm + mf * 16 + (lane & 15)][(lane >> 4) * 8]));
#pragma unroll
        for (int mf = 0; mf < 4; mf++)
#pragma unroll
            for (int nf = 0; nf < 4; nf++) MMA16816(acc[mf][nf], af[mf], bhf[nf]);
        if (pf) {
            const int nb = cur ^ 1;
#pragma unroll
            for (int j = 0; j < 2; j++) {
                *(uint4*)&sA[nb][aP[j]][aR[j]][aH[j] * 8] = ra[j];
                *(uint4*)&sB[nb][bP[j]][bR[j]][bH[j] * 8] = rb[j];
            }
        }
        __syncthreads();
    }

#pragma unroll
    for (int mf = 0; mf < 4; mf++) {
        const int r0 = blockIdx.y * 128 + wm + mf * 16 + (lane >> 2);
#pragma unroll
        for (int nf = 0; nf < 4; nf++) {
            const int c0 = blockIdx.x * 128 + wn + nf * 8 + (lane & 3) * 2;
            float v00 = acc[mf][nf][0], v01 = acc[mf][nf][1];
            float v10 = acc[mf][nf][2], v11 = acc[mf][nf][3];
            if constexpr (FLAGS & F_BIAS) {
                float b0 = bias[c0], b1 = bias[c0 + 1];
                v00 += b0; v01 += b1; v10 += b0; v11 += b1;
            }
            const bool wf32 = !(FLAGS & F_QKVSPL) || (c0 >= 1024);  // v,s regions only
            const bool wpl  = !(FLAGS & F_QKVSPL) || (c0 < 1024);   // q,k regions only
            if constexpr (FLAGS & F_F32) {
                if (wf32) {
                    *(float2*)&C32[(size_t)r0 * ldc + c0]       = make_float2(v00, v01);
                    *(float2*)&C32[(size_t)(r0 + 8) * ldc + c0] = make_float2(v10, v11);
                }
            }
            if constexpr (FLAGS & F_PLANES) {
                if (wpl) {
                    uint32_t hp, lp;
                    split2pack(v00, v01, hp, lp);
                    *(uint32_t*)&Ch[(size_t)r0 * ldcp + c0] = hp;
                    *(uint32_t*)&Cl[(size_t)r0 * ldcp + c0] = lp;
                    split2pack(v10, v11, hp, lp);
                    *(uint32_t*)&Ch[(size_t)(r0 + 8) * ldcp + c0] = hp;
                    *(uint32_t*)&Cl[(size_t)(r0 + 8) * ldcp + c0] = lp;
                }
            }
        }
    }
}

// ---------------------------------------------------------------------------
// Fused flash attention. 2-stage cp.async pipeline + ldmatrix.x4 fragment loads.
// NV=2 (pass3): dual V + residual + transposed plane output. NV=1: single V,
// row-major plane output. Grid (8, 1, 64); 256 threads; dynamic smem.
// ---------------------------------------------------------------------------
template <int NV>
__global__ __launch_bounds__(256) void fattn(
    const __nv_bfloat16* __restrict__ Qh, const __nv_bfloat16* __restrict__ Ql,
    long long ldq, long long qob, long long qoh,
    const __nv_bfloat16* __restrict__ Kh, const __nv_bfloat16* __restrict__ Kl,
    long long ldk, long long kob, long long koh,
    const __nv_bfloat16* __restrict__ V1h, const __nv_bfloat16* __restrict__ V1l,
    const __nv_bfloat16* __restrict__ V2h, const __nv_bfloat16* __restrict__ V2l,
    const float* __restrict__ R1, const float* __restrict__ R2,
    __nv_bfloat16* __restrict__ O1h, __nv_bfloat16* __restrict__ O1l,
    __nv_bfloat16* __restrict__ O2h, __nv_bfloat16* __restrict__ O2l)
{
    constexpr int SKP = 128 * 72;                    // K plane tile elems
    constexpr int SVP = 64 * 136;                    // V plane tile elems
    constexpr int STG = 2 * SKP + NV * 2 * SVP;      // elems per pipeline stage
    extern __shared__ __align__(16) __nv_bfloat16 sm[];
    // per-stage layout: Kh, Kl, V1h, V1l, [V2h, V2l]
    __nv_bfloat16* bKh  = sm;
    __nv_bfloat16* bKl  = sm + SKP;
    __nv_bfloat16* bV1h = sm + 2 * SKP;
    __nv_bfloat16* bV1l = bV1h + SVP;
    __nv_bfloat16* bV2h = bV1l + SVP;
    __nv_bfloat16* bV2l = bV2h + SVP;

    const int tid = threadIdx.x, lane = tid & 31, w = tid >> 5;
    const int wm = w * 16;
    const int z = blockIdx.z, zb = z >> 3, zh = z & 7;
    const int tok0 = blockIdx.x * 128;

    const __nv_bfloat16* Qbh = Qh + zb * qob + zh * qoh + (long long)tok0 * ldq;
    const __nv_bfloat16* Qbl = Ql + zb * qob + zh * qoh + (long long)tok0 * ldq;
    const __nv_bfloat16* Kbh = Kh + zb * kob + zh * koh;
    const __nv_bfloat16* Kbl = Kl + zb * kob + zh * koh;
    const __nv_bfloat16* V1bh = V1h + (size_t)z * 65536;
    const __nv_bfloat16* V1bl = V1l + (size_t)z * 65536;
    const __nv_bfloat16* V2bh = (NV == 2) ? V2h + (size_t)z * 65536 : nullptr;
    const __nv_bfloat16* V2bl = (NV == 2) ? V2l + (size_t)z * 65536 : nullptr;

    // ---- stage Q (scaled by 2^-3, exact on both planes) into stage-0 K buf ----
    {
        __nv_bfloat162 sc = __float2bfloat162_rn(0.125f);
        for (int i = tid; i < 1024; i += 256) {
            int r = i >> 3, c = (i & 7) * 8;
            const __nv_bfloat162* s0 = (const __nv_bfloat162*)(Qbh + (size_t)r * ldq + c);
            __nv_bfloat162* d0 = (__nv_bfloat162*)&bKh[r * 72 + c];
            d0[0] = __hmul2(s0[0], sc); d0[1] = __hmul2(s0[1], sc);
            d0[2] = __hmul2(s0[2], sc); d0[3] = __hmul2(s0[3], sc);
            const __nv_bfloat162* s1 = (const __nv_bfloat162*)(Qbl + (size_t)r * ldq + c);
            __nv_bfloat162* d1 = (__nv_bfloat162*)&bKl[r * 72 + c];
            d1[0] = __hmul2(s1[0], sc); d1[1] = __hmul2(s1[1], sc);
            d1[2] = __hmul2(s1[2], sc); d1[3] = __hmul2(s1[3], sc);
        }
    }
    __syncthreads();
    uint32_t qh[4][4], ql[4][4];
#pragma unroll
    for (int kc = 0; kc < 4; kc++) {
        ldsm4(qh[kc][0], qh[kc][1], qh[kc][2], qh[kc][3],
              smaddr(&bKh[(wm + (lane & 15)) * 72 + kc * 16 + (lane >> 4) * 8]));
        ldsm4(ql[kc][0], ql[kc][1], ql[kc][2], ql[kc][3],
              smaddr(&bKl[(wm + (lane & 15)) * 72 + kc * 16 + (lane >> 4) * 8]));
    }
    __syncthreads();

    // ---- pipeline prologue: stage 0 loads (kt = 0) ----
    {
        for (int i = tid; i < 1024; i += 256) {
            int r = i >> 3, c = (i & 7) * 8;
            CPA16(smaddr(&bKh[r * 72 + c]), Kbh + (size_t)r * ldk + c);
            CPA16(smaddr(&bKl[r * 72 + c]), Kbl + (size_t)r * ldk + c);
        }
        for (int i = tid; i < 1024; i += 256) {
            int d = i >> 4, c = (i & 15) * 8;
            size_t so = (size_t)d * 1024 + c;
            CPA16(smaddr(&bV1h[d * 136 + c]), V1bh + so);
            CPA16(smaddr(&bV1l[d * 136 + c]), V1bl + so);
            if (NV == 2) {
                CPA16(smaddr(&bV2h[d * 136 + c]), V2bh + so);
                CPA16(smaddr(&bV2l[d * 136 + c]), V2bl + so);
            }
        }
        CPCOMMIT();
    }

    float m0 = -1e30f, m1 = -1e30f, l0 = 0.f, l1 = 0.f;
    float O1a[8][4], O2a[8][4];
#pragma unroll
    for (int i = 0; i < 8; i++)
#pragma unroll
        for (int j = 0; j < 4; j++) { O1a[i][j] = 0.f; if (NV == 2) O2a[i][j] = 0.f; }

    for (int kt = 0; kt < 8; kt++) {
        const int cur = (kt & 1) * STG;
        const bool pf = (kt + 1) < 8;
        if (pf) {
            const int nxt = ((kt + 1) & 1) * STG;
            for (int i = tid; i < 1024; i += 256) {
                int r = i >> 3, c = (i & 7) * 8;
                CPA16(smaddr(&bKh[nxt + r * 72 + c]), Kbh + (size_t)((kt + 1) * 128 + r) * ldk + c);
                CPA16(smaddr(&bKl[nxt + r * 72 + c]), Kbl + (size_t)((kt + 1) * 128 + r) * ldk + c);
            }
            for (int i = tid; i < 1024; i += 256) {
                int d = i >> 4, c = (i & 15) * 8;
                size_t so = (size_t)d * 1024 + (kt + 1) * 128 + c;
                CPA16(smaddr(&bV1h[nxt + d * 136 + c]), V1bh + so);
                CPA16(smaddr(&bV1l[nxt + d * 136 + c]), V1bl + so);
                if (NV == 2) {
                    CPA16(smaddr(&bV2h[nxt + d * 136 + c]), V2bh + so);
                    CPA16(smaddr(&bV2l[nxt + d * 136 + c]), V2bl + so);
                }
            }
            CPCOMMIT();
            CPWAIT1();
        } else {
            CPWAIT0();
        }
        __syncthreads();

        // ---- S = Q K^T (3-term split), ldmatrix.x4 over nf pairs ----
        float sacc[16][4];
#pragma unroll
        for (int nf = 0; nf < 16; nf++)
#pragma unroll
            for (int j = 0; j < 4; j++) sacc[nf][j] = 0.f;
#pragma unroll
        for (int kc = 0; kc < 4; kc++) {
#pragma unroll
            for (int nfp = 0; nfp < 8; nfp++) {
                uint32_t bh4[4], bl4[4];
                int off = cur + (nfp * 16 + ((lane >> 4) & 1) * 8 + (lane & 7)) * 72
                        + kc * 16 + ((lane >> 3) & 1) * 8;
                ldsm4(bh4[0], bh4[1], bh4[2], bh4[3], smaddr(&bKh[off]));
                ldsm4(bl4[0], bl4[1], bl4[2], bl4[3], smaddr(&bKl[off]));
                uint32_t b0h[2] = {bh4[0], bh4[1]}, b1h[2] = {bh4[2], bh4[3]};
                uint32_t b0l[2] = {bl4[0], bl4[1]}, b1l[2] = {bl4[2], bl4[3]};
                MMA16816(sacc[2 * nfp],     qh[kc], b0h);
                MMA16816(sacc[2 * nfp],     qh[kc], b0l);
                MMA16816(sacc[2 * nfp],     ql[kc], b0h);
                MMA16816(sacc[2 * nfp + 1], qh[kc], b1h);
                MMA16816(sacc[2 * nfp + 1], qh[kc], b1l);
                MMA16816(sacc[2 * nfp + 1], ql[kc], b1h);
            }
        }

        // ---- online softmax ----
        float tm0 = -1e30f, tm1 = -1e30f;
#pragma unroll
        for (int nf = 0; nf < 16; nf++) {
            tm0 = fmaxf(tm0, fmaxf(sacc[nf][0], sacc[nf][1]));
            tm1 = fmaxf(tm1, fmaxf(sacc[nf][2], sacc[nf][3]));
        }
        tm0 = fmaxf(tm0, __shfl_xor_sync(~0u, tm0, 1));
        tm0 = fmaxf(tm0, __shfl_xor_sync(~0u, tm0, 2));
        tm1 = fmaxf(tm1, __shfl_xor_sync(~0u, tm1, 1));
        tm1 = fmaxf(tm1, __shfl_xor_sync(~0u, tm1, 2));
        float mn0 = fmaxf(m0, tm0), mn1 = fmaxf(m1, tm1);
        float a0 = __expf(m0 - mn0), a1 = __expf(m1 - mn1);
        m0 = mn0; m1 = mn1;
        float rs0 = 0.f, rs1 = 0.f;
#pragma unroll
        for (int nf = 0; nf < 16; nf++) {
            float p0 = __expf(sacc[nf][0] - mn0); sacc[nf][0] = p0; rs0 += p0;
            float p1 = __expf(sacc[nf][1] - mn0); sacc[nf][1] = p1; rs0 += p1;
            float p2 = __expf(sacc[nf][2] - mn1); sacc[nf][2] = p2; rs1 += p2;
            float p3 = __expf(sacc[nf][3] - mn1); sacc[nf][3] = p3; rs1 += p3;
        }
        rs0 += __shfl_xor_sync(~0u, rs0, 1); rs0 += __shfl_xor_sync(~0u, rs0, 2);
        rs1 += __shfl_xor_sync(~0u, rs1, 1); rs1 += __shfl_xor_sync(~0u, rs1, 2);
        l0 = l0 * a0 + rs0; l1 = l1 * a1 + rs1;
#pragma unroll
        for (int vnf = 0; vnf < 8; vnf++) {
            O1a[vnf][0] *= a0; O1a[vnf][1] *= a0; O1a[vnf][2] *= a1; O1a[vnf][3] *= a1;
            if (NV == 2) { O2a[vnf][0] *= a0; O2a[vnf][1] *= a0; O2a[vnf][2] *= a1; O2a[vnf][3] *= a1; }
        }

        // ---- O += P V (3-term split), ldmatrix.x4 over vnf pairs ----
#pragma unroll
        for (int kcp = 0; kcp < 8; kcp++) {
            uint32_t ph[4], pl[4];
            split2pack(sacc[2 * kcp][0],     sacc[2 * kcp][1],     ph[0], pl[0]);
            split2pack(sacc[2 * kcp][2],     sacc[2 * kcp][3],     ph[1], pl[1]);
            split2pack(sacc[2 * kcp + 1][0], sacc[2 * kcp + 1][1], ph[2], pl[2]);
            split2pack(sacc[2 * kcp + 1][2], sacc[2 * kcp + 1][3], ph[3], pl[3]);
#pragma unroll
            for (int vnp = 0; vnp < 4; vnp++) {
                int off = cur + (vnp * 16 + ((lane >> 4) & 1) * 8 + (lane & 7)) * 136
                        + kcp * 16 + ((lane >> 3) & 1) * 8;
                uint32_t vh4[4], vl4[4];
                ldsm4(vh4[0], vh4[1], vh4[2], vh4[3], smaddr(&bV1h[off]));
                ldsm4(vl4[0], vl4[1], vl4[2], vl4[3], smaddr(&bV1l[off]));
                uint32_t v0h[2] = {vh4[0], vh4[1]}, v1h[2] = {vh4[2], vh4[3]};
                uint32_t v0l[2] = {vl4[0], vl4[1]}, v1l[2] = {vl4[2], vl4[3]};
                MMA16816(O1a[2 * vnp],     ph, v0h);
                MMA16816(O1a[2 * vnp],     ph, v0l);
                MMA16816(O1a[2 * vnp],     pl, v0h);
                MMA16816(O1a[2 * vnp + 1], ph, v1h);
                MMA16816(O1a[2 * vnp + 1], ph, v1l);
                MMA16816(O1a[2 * vnp + 1], pl, v1h);
                if (NV == 2) {
                    uint32_t wh4[4], wl4[4];
                    ldsm4(wh4[0], wh4[1], wh4[2], wh4[3], smaddr(&bV2h[off]));
                    ldsm4(wl4[0], wl4[1], wl4[2], wl4[3], smaddr(&bV2l[off]));
                    uint32_t w0h[2] = {wh4[0], wh4[1]}, w1h[2] = {wh4[2], wh4[3]};
                    uint32_t w0l[2] = {wl4[0], wl4[1]}, w1l[2] = {wl4[2], wl4[3]};
                    MMA16816(O2a[2 * vnp],     ph, w0h);
                    MMA16816(O2a[2 * vnp],     ph, w0l);
                    MMA16816(O2a[2 * vnp],     pl, w0h);
                    MMA16816(O2a[2 * vnp + 1], ph, w1h);
                    MMA16816(O2a[2 * vnp + 1], ph, w1l);
                    MMA16816(O2a[2 * vnp + 1], pl, w1h);
                }
            }
        }
        __syncthreads();
    }

    // ---- finalize ----
    const float i0 = 1.f / l0, i1 = 1.f / l1;
#pragma unroll
    for (int vnf = 0; vnf < 8; vnf++) {
        O1a[vnf][0] *= i0; O1a[vnf][1] *= i0; O1a[vnf][2] *= i1; O1a[vnf][3] *= i1;
        if (NV == 2) { O2a[vnf][0] *= i0; O2a[vnf][1] *= i0; O2a[vnf][2] *= i1; O2a[vnf][3] *= i1; }
    }

    const int r = wm + (lane >> 2);
    if (NV == 2) {
        // residual add (u = a3 @ v + v)
        const float* R1p = R1 + (size_t)zb * 2097152 + (size_t)zh * 64;
        const float* R2p = R2 + (size_t)zb * 2097152 + (size_t)zh * 64;
        const size_t row = (size_t)(tok0 + r);
#pragma unroll
        for (int vnf = 0; vnf < 8; vnf++) {
            int c0 = vnf * 8 + (lane & 3) * 2;
            float2 ra = *(const float2*)&R1p[row * 2048 + c0];
            float2 rb = *(const float2*)&R1p[(row + 8) * 2048 + c0];
            O1a[vnf][0] += ra.x; O1a[vnf][1] += ra.y; O1a[vnf][2] += rb.x; O1a[vnf][3] += rb.y;
            float2 rc = *(const float2*)&R2p[row * 2048 + c0];
            float2 rd = *(const float2*)&R2p[(row + 8) * 2048 + c0];
            O2a[vnf][0] += rc.x; O2a[vnf][1] += rc.y; O2a[vnf][2] += rd.x; O2a[vnf][3] += rd.y;
        }
        // transposed plane output via smem bounce (stage-0 K buffers are free)
#pragma unroll
        for (int s = 0; s < 2; s++) {
            float (*Oa)[4] = s ? O2a : O1a;
#pragma unroll
            for (int vnf = 0; vnf < 8; vnf++) {
                int c0 = vnf * 8 + (lane & 3) * 2;
                uint32_t hp, lp;
                split2pack(Oa[vnf][0], Oa[vnf][1], hp, lp);
                *(uint32_t*)&bKh[r * 72 + c0] = hp;
                *(uint32_t*)&bKl[r * 72 + c0] = lp;
                split2pack(Oa[vnf][2], Oa[vnf][3], hp, lp);
                *(uint32_t*)&bKh[(r + 8) * 72 + c0] = hp;
                *(uint32_t*)&bKl[(r + 8) * 72 + c0] = lp;
            }
            __syncthreads();
            __nv_bfloat16* OH = (s ? O2h : O1h) + (size_t)z * 65536 + tok0;
            __nv_bfloat16* OL = (s ? O2l : O1l) + (size_t)z * 65536 + tok0;
            for (int i = tid; i < 2048; i += 256) {
                int plane = i >> 10, rem = i & 1023, d = rem >> 4, ch = (rem & 15) * 8;
                const unsigned short* src = (const unsigned short*)(plane ? bKl : bKh);
                unsigned short v[8];
#pragma unroll
                for (int j = 0; j < 8; j++) v[j] = src[(ch + j) * 72 + d];
                uint4 pk;
                pk.x = (uint32_t)v[0] | ((uint32_t)v[1] << 16);
                pk.y = (uint32_t)v[2] | ((uint32_t)v[3] << 16);
                pk.z = (uint32_t)v[4] | ((uint32_t)v[5] << 16);
                pk.w = (uint32_t)v[6] | ((uint32_t)v[7] << 16);
                *(uint4*)((plane ? OL : OH) + (size_t)d * 1024 + ch) = pk;
            }
            __syncthreads();
        }
    } else {
        // row-major plane output
        __nv_bfloat16* OH = O1h + (size_t)zb * 524288 + zh * 64;
        __nv_bfloat16* OL = O1l + (size_t)zb * 524288 + zh * 64;
        const size_t row = (size_t)(tok0 + r);
#pragma unroll
        for (int vnf = 0; vnf < 8; vnf++) {
            int c0 = vnf * 8 + (lane & 3) * 2;
            uint32_t hp, lp;
            split2pack(O1a[vnf][0], O1a[vnf][1], hp, lp);
            *(uint32_t*)&OH[row * 512 + c0] = hp;
            *(uint32_t*)&OL[row * 512 + c0] = lp;
            split2pack(O1a[vnf][2], O1a[vnf][3], hp, lp);
            *(uint32_t*)&OH[(row + 8) * 512 + c0] = hp;
            *(uint32_t*)&OL[(row + 8) * 512 + c0] = lp;
        }
    }
}

// ---------------------------------------------------------------------------
// Converters / gate / vtrans
// ---------------------------------------------------------------------------
__global__ void convN(const float* __restrict__ X, __nv_bfloat16* __restrict__ H,
                      __nv_bfloat16* __restrict__ L, int n4)
{
    int i = blockIdx.x * blockDim.x + threadIdx.x;
    if (i >= n4) return;
    float4 v = ((const float4*)X)[i];
    uint32_t hp, lp;
    split2pack(v.x, v.y, hp, lp);
    *(uint32_t*)&H[(size_t)i * 4] = hp; *(uint32_t*)&L[(size_t)i * 4] = lp;
    split2pack(v.z, v.w, hp, lp);
    *(uint32_t*)&H[(size_t)i * 4 + 2] = hp; *(uint32_t*)&L[(size_t)i * 4 + 2] = lp;
}

__global__ void convT(const float* __restrict__ W, __nv_bfloat16* __restrict__ H,
                      __nv_bfloat16* __restrict__ L, int K, int N)
{
    int i = blockIdx.x * blockDim.x + threadIdx.x;
    if (i >= K * N) return;
    int n = i / K, k = i % K;
    float v = W[(size_t)k * N + n];
    split1(v, H[i], L[i]);
}

__global__ void vtrans(const float* __restrict__ qkv, __nv_bfloat16* __restrict__ H,
                       __nv_bfloat16* __restrict__ L)
{
    __shared__ float t[64][65];
    const int z = blockIdx.y, tokb = blockIdx.x, b = z >> 3, h = z & 7;
    const int tid = threadIdx.x;
    for (int i = tid; i < 4096; i += 256) {
        int tl = i >> 6, n = i & 63;
        t[tl][n] = qkv[(size_t)(b * 1024 + tokb * 64 + tl) * 2048 + 1024 + h * 64 + n];
    }
    __syncthreads();
    for (int i = tid; i < 4096; i += 256) {
        int n = i >> 6, tl = i & 63;
        float v = t[tl][n];
        size_t o = ((size_t)z * 64 + n) * 1024 + tokb * 64 + tl;
        split1(v, H[o], L[o]);
    }
}

__global__ __launch_bounds__(128) void gate_conv(
    const float* __restrict__ qkv1, const float* __restrict__ qkv2,
    const float* __restrict__ w, const float* __restrict__ cb,
    __nv_bfloat16* __restrict__ H, __nv_bfloat16* __restrict__ L)
{
    __shared__ float ms[516];
    const int bn = blockIdx.x, n = bn & 1023, tid = threadIdx.x;
    const float* r1 = qkv1 + (size_t)bn * 2048 + 1536;
    const float* r2 = qkv2 + (size_t)bn * 2048 + 1536;
    for (int f = tid; f < 512; f += 128) ms[f + 2] = r1[f] + r2[f];
    if (tid < 2) { ms[tid] = 0.f; ms[514 + tid] = 0.f; }
    __syncthreads();
    const float w0 = w[n * 5], w1 = w[n * 5 + 1], w2 = w[n * 5 + 2],
                w3 = w[n * 5 + 3], w4 = w[n * 5 + 4], bb = cb[n];
    for (int f = tid; f < 512; f += 128) {
        float a = w0 * ms[f] + w1 * ms[f + 1] + w2 * ms[f + 2]
                + w3 * ms[f + 3] + w4 * ms[f + 4] + bb;
        float s = 1.f / (1.f + __expf(-a));
        float v = s * ms[f + 2];
        split1(v, H[(size_t)bn * 512 + f], L[(size_t)bn * 512 + f]);
    }
}

// ---------------------------------------------------------------------------
// Launch
// ---------------------------------------------------------------------------
extern "C" void kernel_launch(void* const* d_in, const int* in_sizes, int n_in,
                              void* d_out, int out_size)
{
    const float* x1    = (const float*)d_in[0];
    const float* x2    = (const float*)d_in[1];
    const float* Wqkv1 = (const float*)d_in[2];
    const float* Wqkv2 = (const float*)d_in[3];
    const float* Wout1 = (const float*)d_in[4];
    const float* bout1 = (const float*)d_in[5];
    const float* Wout2 = (const float*)d_in[6];
    const float* bout2 = (const float*)d_in[7];
    const float* convw = (const float*)d_in[8];
    const float* convb = (const float*)d_in[9];
    float* out = (float*)d_out;

    __nv_bfloat16 *xp1, *xp2, *Wq1, *Wq2, *Wo1, *Wo2, *qkvp1, *qkvp2,
                  *vT1, *vT2, *msgp, *uT1, *uT2, *tp1, *tp2;
    float *qkv1, *qkv2;
    cudaGetSymbolAddress((void**)&xp1, g_xp1);   cudaGetSymbolAddress((void**)&xp2, g_xp2);
    cudaGetSymbolAddress((void**)&Wq1, g_Wq1);   cudaGetSymbolAddress((void**)&Wq2, g_Wq2);
    cudaGetSymbolAddress((void**)&Wo1, g_Wo1);   cudaGetSymbolAddress((void**)&Wo2, g_Wo2);
    cudaGetSymbolAddress((void**)&qkv1, g_qkv1); cudaGetSymbolAddress((void**)&qkv2, g_qkv2);
    cudaGetSymbolAddress((void**)&qkvp1, g_qkvp1); cudaGetSymbolAddress((void**)&qkvp2, g_qkvp2);
    cudaGetSymbolAddress((void**)&vT1, g_vT1);   cudaGetSymbolAddress((void**)&vT2, g_vT2);
    cudaGetSymbolAddress((void**)&msgp, g_msgp);
    cudaGetSymbolAddress((void**)&uT1, g_uT1);   cudaGetSymbolAddress((void**)&uT2, g_uT2);
    cudaGetSymbolAddress((void**)&tp1, g_tp1);   cudaGetSymbolAddress((void**)&tp2, g_tp2);

    const long long PX  = 4194304;    // 8192*512
    const long long PQ  = 16777216;   // 8192*2048
    const long long PW  = 1048576;    // 2048*512
    const long long PWo = 262144;     // 512*512
    const long long PV  = 4194304;    // 64*64*1024

    const int SMEM2 = 2 * (2 * 128 * 72 + 4 * 64 * 136) * 2;  // 212992 (2 stages)
    const int SMEM1 = 2 * (2 * 128 * 72 + 2 * 64 * 136) * 2;  // 143360 (2 stages)
    cudaFuncSetAttribute(fattn<2>, cudaFuncAttributeMaxDynamicSharedMemorySize, SMEM2);
    cudaFuncSetAttribute(fattn<1>, cudaFuncAttributeMaxDynamicSharedMemorySize, SMEM1);

    // operand conversion
    convN<<<4096, 256>>>(x1, xp1, xp1 + PX, 1048576);
    convN<<<4096, 256>>>(x2, xp2, xp2 + PX, 1048576);
    convT<<<4096, 256>>>(Wqkv1, Wq1, Wq1 + PW, 512, 2048);
    convT<<<4096, 256>>>(Wqkv2, Wq2, Wq2 + PW, 512, 2048);
    convT<<<1024, 256>>>(Wout1, Wo1, Wo1 + PWo, 512, 512);
    convT<<<1024, 256>>>(Wout2, Wo2, Wo2 + PWo, 512, 512);

    // QKVS projections: fp32 only for v/s cols, planes only for q/k cols
    gemm_bs<F_F32 | F_PLANES | F_QKVSPL><<<dim3(16, 64), 256>>>(
        xp1, xp1 + PX, 512, Wq1, Wq1 + PW, 512,
        qkv1, 2048, qkvp1, qkvp1 + PQ, 2048, nullptr, 512);
    gemm_bs<F_F32 | F_PLANES | F_QKVSPL><<<dim3(16, 64), 256>>>(
        xp2, xp2 + PX, 512, Wq2, Wq2 + PW, 512,
        qkv2, 2048, qkvp2, qkvp2 + PQ, 2048, nullptr, 512);

    gate_conv<<<8192, 128>>>(qkv1, qkv2, convw, convb, msgp, msgp + PX);
    vtrans<<<dim3(16, 64), 256>>>(qkv1, vT1, vT1 + PV);
    vtrans<<<dim3(16, 64), 256>>>(qkv2, vT2, vT2 + PV);

    // Pass 3 fused: a3 = softmax(MSh MSh^T * scale); u_i = a3 @ v_i + v_i
    fattn<2><<<dim3(8, 1, 64), 256, SMEM2>>>(
        msgp, msgp + PX, 512, 524288, 64,
        msgp, msgp + PX, 512, 524288, 64,
        vT1, vT1 + PV, vT2, vT2 + PV,
        qkv1 + 1024, qkv2 + 1024,
        uT1, uT1 + PV, uT2, uT2 + PV);

    // Pass 1 fused: t1 = softmax(q1 k1^T * scale) @ u1
    fattn<1><<<dim3(8, 1, 64), 256, SMEM1>>>(
        qkvp1, qkvp1 + PQ, 2048, 2097152, 64,
        qkvp1 + 512, qkvp1 + PQ + 512, 2048, 2097152, 64,
        uT1, uT1 + PV, nullptr, nullptr,
        nullptr, nullptr,
        tp1, tp1 + PX, nullptr, nullptr);

    // Pass 2 fused: t2 = softmax(q2 k2^T * scale) @ u2
    fattn<1><<<dim3(8, 1, 64), 256, SMEM1>>>(
        qkvp2, qkvp2 + PQ, 2048, 2097152, 64,
        qkvp2 + 512, qkvp2 + PQ + 512, 2048, 2097152, 64,
        uT2, uT2 + PV, nullptr, nullptr,
        nullptr, nullptr,
        tp2, tp2 + PX, nullptr, nullptr);

    // Output projections
    gemm_bs<F_F32 | F_BIAS><<<dim3(4, 64), 256>>>(
        tp1, tp1 + PX, 512, Wo1, Wo1 + PWo, 512,
        out, 512, nullptr, nullptr, 0, bout1, 512);
    gemm_bs<F_F32 | F_BIAS><<<dim3(4, 64), 256>>>(
        tp2, tp2 + PX, 512, Wo2, Wo2 + PWo, 512,
        out + 4194304, 512, nullptr, nullptr, 0, bout2, 512);
}

// round 8
// speedup vs baseline: 2.8211x; 1.0093x over previous
#include <cuda_runtime.h>
#include <cuda_bf16.h>
#include <cstdint>

// ---------------------------------------------------------------------------
// B=8, N=1024, DIM=512, H=8, HD=64, INNER=512, KS=5
// Split-bf16 tensor-core pipeline + fused flash-style attention passes.
// Launch order arranged so the 6th launch (ncu -s 5 -c 1) is fattn<2>.
// ---------------------------------------------------------------------------

#define F_F32    1
#define F_PLANES 2
#define F_BIAS   16
#define F_QKVSPL 32

// plane sizes (elems)
#define PXc  4194304LL
#define PQc  16777216LL
#define PWc  1048576LL
#define PWoc 262144LL
#define PVc  4194304LL

// ---------------- scratch ---------------------------------------------------
__device__ __nv_bfloat16 g_xp1 [2ull*8192*512];
__device__ __nv_bfloat16 g_xp2 [2ull*8192*512];
__device__ __nv_bfloat16 g_Wq1 [2ull*2048*512];
__device__ __nv_bfloat16 g_Wq2 [2ull*2048*512];
__device__ __nv_bfloat16 g_Wo1 [2ull*512*512];
__device__ __nv_bfloat16 g_Wo2 [2ull*512*512];
__device__ float         g_qkv1[8192ull*2048];
__device__ float         g_qkv2[8192ull*2048];
__device__ __nv_bfloat16 g_qkvp1[2ull*8192*2048];
__device__ __nv_bfloat16 g_qkvp2[2ull*8192*2048];
__device__ __nv_bfloat16 g_vT1 [2ull*64*64*1024];
__device__ __nv_bfloat16 g_vT2 [2ull*64*64*1024];
__device__ __nv_bfloat16 g_msgp[2ull*8192*512];
__device__ __nv_bfloat16 g_uT1 [2ull*64*64*1024];
__device__ __nv_bfloat16 g_uT2 [2ull*64*64*1024];
__device__ __nv_bfloat16 g_tp1 [2ull*8192*512];
__device__ __nv_bfloat16 g_tp2 [2ull*8192*512];

// ---------------- helpers ----------------------------------------------------
__device__ __forceinline__ void split1(float v, __nv_bfloat16& h, __nv_bfloat16& l) {
    h = __float2bfloat16(v);
    l = __float2bfloat16(v - __bfloat162float(h));
}
__device__ __forceinline__ void split2pack(float f0, float f1, uint32_t& hp, uint32_t& lp) {
    __nv_bfloat16 h0, l0, h1, l1;
    split1(f0, h0, l0); split1(f1, h1, l1);
    __nv_bfloat162 th; th.x = h0; th.y = h1; hp = *(uint32_t*)&th;
    __nv_bfloat162 tl; tl.x = l0; tl.y = l1; lp = *(uint32_t*)&tl;
}
__device__ __forceinline__ uint32_t smaddr(const void* p) {
    return (uint32_t)__cvta_generic_to_shared(p);
}
__device__ __forceinline__ void ldsm4(uint32_t& r0, uint32_t& r1, uint32_t& r2, uint32_t& r3, uint32_t a) {
    asm volatile("ldmatrix.sync.aligned.m8n8.x4.shared.b16 {%0,%1,%2,%3},[%4];\n"
                 : "=r"(r0), "=r"(r1), "=r"(r2), "=r"(r3) : "r"(a));
}
__device__ __forceinline__ void ldsm2(uint32_t& r0, uint32_t& r1, uint32_t a) {
    asm volatile("ldmatrix.sync.aligned.m8n8.x2.shared.b16 {%0,%1},[%2];\n"
                 : "=r"(r0), "=r"(r1) : "r"(a));
}
#define MMA16816(c, a, b)                                                            \
    asm volatile("mma.sync.aligned.m16n8k16.row.col.f32.bf16.bf16.f32 "              \
                 "{%0,%1,%2,%3},{%4,%5,%6,%7},{%8,%9},{%0,%1,%2,%3};\n"              \
                 : "+f"((c)[0]), "+f"((c)[1]), "+f"((c)[2]), "+f"((c)[3])            \
                 : "r"((a)[0]), "r"((a)[1]), "r"((a)[2]), "r"((a)[3]),               \
                   "r"((b)[0]), "r"((b)[1]))
#define CPA16(dst, src)                                                              \
    asm volatile("cp.async.ca.shared.global [%0], [%1], 16;\n" :: "r"(dst), "l"(src))
#define CPCOMMIT() asm volatile("cp.async.commit_group;\n" ::: "memory")
#define CPWAIT1()  asm volatile("cp.async.wait_group 1;\n" ::: "memory")
#define CPWAIT0()  asm volatile("cp.async.wait_group 0;\n" ::: "memory")

// ---------------------------------------------------------------------------
// Split-bf16 GEMM (projections). Block 128x128xK16, double-buffered.
// ---------------------------------------------------------------------------
template <int FLAGS>
__global__ __launch_bounds__(256) void gemm_bs(
    const __nv_bfloat16* __restrict__ Ah, const __nv_bfloat16* __restrict__ Al, long long lda,
    const __nv_bfloat16* __restrict__ Bh, const __nv_bfloat16* __restrict__ Bl, long long ldb,
    float* __restrict__ C32, long long ldc,
    __nv_bfloat16* __restrict__ Ch, __nv_bfloat16* __restrict__ Cl, long long ldcp,
    const float* __restrict__ bias, int K)
{
    __shared__ __align__(16) __nv_bfloat16 sA[2][2][128][24];
    __shared__ __align__(16) __nv_bfloat16 sB[2][2][128][24];

    const int tid = threadIdx.x;
    const __nv_bfloat16* srcA[2]; int aP[2], aR[2], aH[2];
#pragma unroll
    for (int j = 0; j < 2; j++) {
        int idx = tid + j * 256;
        aP[j] = idx >> 8; int rem = idx & 255; aR[j] = rem >> 1; aH[j] = rem & 1;
        const __nv_bfloat16* base = aP[j] ? Al : Ah;
        srcA[j] = base + (size_t)(blockIdx.y * 128 + aR[j]) * lda + aH[j] * 8;
    }
    const __nv_bfloat16* srcB[2]; int bP[2], bR[2], bH[2];
#pragma unroll
    for (int j = 0; j < 2; j++) {
        int idx = tid + j * 256;
        bP[j] = idx >> 8; int rem = idx & 255; bR[j] = rem >> 1; bH[j] = rem & 1;
        const __nv_bfloat16* base = bP[j] ? Bl : Bh;
        srcB[j] = base + (size_t)(blockIdx.x * 128 + bR[j]) * ldb + bH[j] * 8;
    }
#pragma unroll
    for (int j = 0; j < 2; j++) {
        *(uint4*)&sA[0][aP[j]][aR[j]][aH[j] * 8] = *(const uint4*)srcA[j];
        *(uint4*)&sB[0][bP[j]][bR[j]][bH[j] * 8] = *(const uint4*)srcB[j];
    }
    __syncthreads();

    const int lane = tid & 31, w = tid >> 5;
    const int wm = (w >> 2) * 64, wn = (w & 3) * 32;

    float acc[4][4][4];
#pragma unroll
    for (int i = 0; i < 4; i++)
#pragma unroll
        for (int j = 0; j < 4; j++)
#pragma unroll
            for (int k = 0; k < 4; k++) acc[i][j][k] = 0.f;

    const int nk = K >> 4;
    for (int kt = 0; kt < nk; ++kt) {
        const int cur = kt & 1;
        const bool pf = (kt + 1) < nk;
        uint4 ra[2], rb[2];
        if (pf) {
            long long k0 = (long long)(kt + 1) * 16;
#pragma unroll
            for (int j = 0; j < 2; j++) { ra[j] = *(const uint4*)(srcA[j] + k0); rb[j] = *(const uint4*)(srcB[j] + k0); }
        }
        uint32_t bhf[4][2], blf[4][2], af[4][4];
#pragma unroll
        for (int nf = 0; nf < 4; nf++) {
            ldsm2(bhf[nf][0], bhf[nf][1], smaddr(&sB[cur][0][wn + nf * 8 + (lane & 7)][((lane >> 3) & 1) * 8]));
            ldsm2(blf[nf][0], blf[nf][1], smaddr(&sB[cur][1][wn + nf * 8 + (lane & 7)][((lane >> 3) & 1) * 8]));
        }
#pragma unroll
        for (int mf = 0; mf < 4; mf++)
            ldsm4(af[mf][0], af[mf][1], af[mf][2], af[mf][3],
                  smaddr(&sA[cur][0][wm + mf * 16 + (lane & 15)][(lane >> 4) * 8]));
#pragma unroll
        for (int mf = 0; mf < 4; mf++)
#pragma unroll
            for (int nf = 0; nf < 4; nf++) { MMA16816(acc[mf][nf], af[mf], bhf[nf]); MMA16816(acc[mf][nf], af[mf], blf[nf]); }
#pragma unroll
        for (int mf = 0; mf < 4; mf++)
            ldsm4(af[mf][0], af[mf][1], af[mf][2], af[mf][3],
                  smaddr(&sA[cur][1][wm + mf * 16 + (lane & 15)][(lane >> 4) * 8]));
#pragma unroll
        for (int mf = 0; mf < 4; mf++)
#pragma unroll
            for (int nf = 0; nf < 4; nf++) MMA16816(acc[mf][nf], af[mf], bhf[nf]);
        if (pf) {
            const int nb = cur ^ 1;
#pragma unroll
            for (int j = 0; j < 2; j++) {
                *(uint4*)&sA[nb][aP[j]][aR[j]][aH[j] * 8] = ra[j];
                *(uint4*)&sB[nb][bP[j]][bR[j]][bH[j] * 8] = rb[j];
            }
        }
        __syncthreads();
    }

#pragma unroll
    for (int mf = 0; mf < 4; mf++) {
        const int r0 = blockIdx.y * 128 + wm + mf * 16 + (lane >> 2);
#pragma unroll
        for (int nf = 0; nf < 4; nf++) {
            const int c0 = blockIdx.x * 128 + wn + nf * 8 + (lane & 3) * 2;
            float v00 = acc[mf][nf][0], v01 = acc[mf][nf][1];
            float v10 = acc[mf][nf][2], v11 = acc[mf][nf][3];
            if constexpr (FLAGS & F_BIAS) {
                float b0 = bias[c0], b1 = bias[c0 + 1];
                v00 += b0; v01 += b1; v10 += b0; v11 += b1;
            }
            const bool wf32 = !(FLAGS & F_QKVSPL) || (c0 >= 1024);  // v,s regions only
            const bool wpl  = !(FLAGS & F_QKVSPL) || (c0 < 1024);   // q,k regions only
            if constexpr (FLAGS & F_F32) {
                if (wf32) {
                    *(float2*)&C32[(size_t)r0 * ldc + c0]       = make_float2(v00, v01);
                    *(float2*)&C32[(size_t)(r0 + 8) * ldc + c0] = make_float2(v10, v11);
                }
            }
            if constexpr (FLAGS & F_PLANES) {
                if (wpl) {
                    uint32_t hp, lp;
                    split2pack(v00, v01, hp, lp);
                    *(uint32_t*)&Ch[(size_t)r0 * ldcp + c0] = hp;
                    *(uint32_t*)&Cl[(size_t)r0 * ldcp + c0] = lp;
                    split2pack(v10, v11, hp, lp);
                    *(uint32_t*)&Ch[(size_t)(r0 + 8) * ldcp + c0] = hp;
                    *(uint32_t*)&Cl[(size_t)(r0 + 8) * ldcp + c0] = lp;
                }
            }
        }
    }
}

// ---------------------------------------------------------------------------
// Fused flash attention. 2-stage cp.async pipeline + ldmatrix.x4 fragment loads.
// NV=2 (pass3): dual V + residual + transposed plane output. NV=1: single V,
// row-major plane output. Grid (8, 1, 64); 256 threads; dynamic smem.
// ---------------------------------------------------------------------------
template <int NV>
__global__ __launch_bounds__(256) void fattn(
    const __nv_bfloat16* __restrict__ Qh, const __nv_bfloat16* __restrict__ Ql,
    long long ldq, long long qob, long long qoh,
    const __nv_bfloat16* __restrict__ Kh, const __nv_bfloat16* __restrict__ Kl,
    long long ldk, long long kob, long long koh,
    const __nv_bfloat16* __restrict__ V1h, const __nv_bfloat16* __restrict__ V1l,
    const __nv_bfloat16* __restrict__ V2h, const __nv_bfloat16* __restrict__ V2l,
    const float* __restrict__ R1, const float* __restrict__ R2,
    __nv_bfloat16* __restrict__ O1h, __nv_bfloat16* __restrict__ O1l,
    __nv_bfloat16* __restrict__ O2h, __nv_bfloat16* __restrict__ O2l)
{
    constexpr int SKP = 128 * 72;                    // K plane tile elems
    constexpr int SVP = 64 * 136;                    // V plane tile elems
    constexpr int STG = 2 * SKP + NV * 2 * SVP;      // elems per pipeline stage
    extern __shared__ __align__(16) __nv_bfloat16 sm[];
    // per-stage layout: Kh, Kl, V1h, V1l, [V2h, V2l]
    __nv_bfloat16* bKh  = sm;
    __nv_bfloat16* bKl  = sm + SKP;
    __nv_bfloat16* bV1h = sm + 2 * SKP;
    __nv_bfloat16* bV1l = bV1h + SVP;
    __nv_bfloat16* bV2h = bV1l + SVP;
    __nv_bfloat16* bV2l = bV2h + SVP;

    const int tid = threadIdx.x, lane = tid & 31, w = tid >> 5;
    const int wm = w * 16;
    const int z = blockIdx.z, zb = z >> 3, zh = z & 7;
    const int tok0 = blockIdx.x * 128;

    const __nv_bfloat16* Qbh = Qh + zb * qob + zh * qoh + (long long)tok0 * ldq;
    const __nv_bfloat16* Qbl = Ql + zb * qob + zh * qoh + (long long)tok0 * ldq;
    const __nv_bfloat16* Kbh = Kh + zb * kob + zh * koh;
    const __nv_bfloat16* Kbl = Kl + zb * kob + zh * koh;
    const __nv_bfloat16* V1bh = V1h + (size_t)z * 65536;
    const __nv_bfloat16* V1bl = V1l + (size_t)z * 65536;
    const __nv_bfloat16* V2bh = (NV == 2) ? V2h + (size_t)z * 65536 : nullptr;
    const __nv_bfloat16* V2bl = (NV == 2) ? V2l + (size_t)z * 65536 : nullptr;

    // ---- stage Q (scaled by 2^-3, exact on both planes) into stage-0 K buf ----
    {
        __nv_bfloat162 sc = __float2bfloat162_rn(0.125f);
        for (int i = tid; i < 1024; i += 256) {
            int r = i >> 3, c = (i & 7) * 8;
            const __nv_bfloat162* s0 = (const __nv_bfloat162*)(Qbh + (size_t)r * ldq + c);
            __nv_bfloat162* d0 = (__nv_bfloat162*)&bKh[r * 72 + c];
            d0[0] = __hmul2(s0[0], sc); d0[1] = __hmul2(s0[1], sc);
            d0[2] = __hmul2(s0[2], sc); d0[3] = __hmul2(s0[3], sc);
            const __nv_bfloat162* s1 = (const __nv_bfloat162*)(Qbl + (size_t)r * ldq + c);
            __nv_bfloat162* d1 = (__nv_bfloat162*)&bKl[r * 72 + c];
            d1[0] = __hmul2(s1[0], sc); d1[1] = __hmul2(s1[1], sc);
            d1[2] = __hmul2(s1[2], sc); d1[3] = __hmul2(s1[3], sc);
        }
    }
    __syncthreads();
    uint32_t qh[4][4], ql[4][4];
#pragma unroll
    for (int kc = 0; kc < 4; kc++) {
        ldsm4(qh[kc][0], qh[kc][1], qh[kc][2], qh[kc][3],
              smaddr(&bKh[(wm + (lane & 15)) * 72 + kc * 16 + (lane >> 4) * 8]));
        ldsm4(ql[kc][0], ql[kc][1], ql[kc][2], ql[kc][3],
              smaddr(&bKl[(wm + (lane & 15)) * 72 + kc * 16 + (lane >> 4) * 8]));
    }
    __syncthreads();

    // ---- pipeline prologue: stage 0 loads (kt = 0) ----
    {
        for (int i = tid; i < 1024; i += 256) {
            int r = i >> 3, c = (i & 7) * 8;
            CPA16(smaddr(&bKh[r * 72 + c]), Kbh + (size_t)r * ldk + c);
            CPA16(smaddr(&bKl[r * 72 + c]), Kbl + (size_t)r * ldk + c);
        }
        for (int i = tid; i < 1024; i += 256) {
            int d = i >> 4, c = (i & 15) * 8;
            size_t so = (size_t)d * 1024 + c;
            CPA16(smaddr(&bV1h[d * 136 + c]), V1bh + so);
            CPA16(smaddr(&bV1l[d * 136 + c]), V1bl + so);
            if (NV == 2) {
                CPA16(smaddr(&bV2h[d * 136 + c]), V2bh + so);
                CPA16(smaddr(&bV2l[d * 136 + c]), V2bl + so);
            }
        }
        CPCOMMIT();
    }

    float m0 = -1e30f, m1 = -1e30f, l0 = 0.f, l1 = 0.f;
    float O1a[8][4], O2a[8][4];
#pragma unroll
    for (int i = 0; i < 8; i++)
#pragma unroll
        for (int j = 0; j < 4; j++) { O1a[i][j] = 0.f; if (NV == 2) O2a[i][j] = 0.f; }

    for (int kt = 0; kt < 8; kt++) {
        const int cur = (kt & 1) * STG;
        const bool pf = (kt + 1) < 8;
        if (pf) {
            const int nxt = ((kt + 1) & 1) * STG;
            for (int i = tid; i < 1024; i += 256) {
                int r = i >> 3, c = (i & 7) * 8;
                CPA16(smaddr(&bKh[nxt + r * 72 + c]), Kbh + (size_t)((kt + 1) * 128 + r) * ldk + c);
                CPA16(smaddr(&bKl[nxt + r * 72 + c]), Kbl + (size_t)((kt + 1) * 128 + r) * ldk + c);
            }
            for (int i = tid; i < 1024; i += 256) {
                int d = i >> 4, c = (i & 15) * 8;
                size_t so = (size_t)d * 1024 + (kt + 1) * 128 + c;
                CPA16(smaddr(&bV1h[nxt + d * 136 + c]), V1bh + so);
                CPA16(smaddr(&bV1l[nxt + d * 136 + c]), V1bl + so);
                if (NV == 2) {
                    CPA16(smaddr(&bV2h[nxt + d * 136 + c]), V2bh + so);
                    CPA16(smaddr(&bV2l[nxt + d * 136 + c]), V2bl + so);
                }
            }
            CPCOMMIT();
            CPWAIT1();
        } else {
            CPWAIT0();
        }
        __syncthreads();

        // ---- S = Q K^T (3-term split), ldmatrix.x4 over nf pairs ----
        float sacc[16][4];
#pragma unroll
        for (int nf = 0; nf < 16; nf++)
#pragma unroll
            for (int j = 0; j < 4; j++) sacc[nf][j] = 0.f;
#pragma unroll
        for (int kc = 0; kc < 4; kc++) {
#pragma unroll
            for (int nfp = 0; nfp < 8; nfp++) {
                uint32_t bh4[4], bl4[4];
                int off = cur + (nfp * 16 + ((lane >> 4) & 1) * 8 + (lane & 7)) * 72
                        + kc * 16 + ((lane >> 3) & 1) * 8;
                ldsm4(bh4[0], bh4[1], bh4[2], bh4[3], smaddr(&bKh[off]));
                ldsm4(bl4[0], bl4[1], bl4[2], bl4[3], smaddr(&bKl[off]));
                uint32_t b0h[2] = {bh4[0], bh4[1]}, b1h[2] = {bh4[2], bh4[3]};
                uint32_t b0l[2] = {bl4[0], bl4[1]}, b1l[2] = {bl4[2], bl4[3]};
                MMA16816(sacc[2 * nfp],     qh[kc], b0h);
                MMA16816(sacc[2 * nfp],     qh[kc], b0l);
                MMA16816(sacc[2 * nfp],     ql[kc], b0h);
                MMA16816(sacc[2 * nfp + 1], qh[kc], b1h);
                MMA16816(sacc[2 * nfp + 1], qh[kc], b1l);
                MMA16816(sacc[2 * nfp + 1], ql[kc], b1h);
            }
        }

        // ---- online softmax ----
        float tm0 = -1e30f, tm1 = -1e30f;
#pragma unroll
        for (int nf = 0; nf < 16; nf++) {
            tm0 = fmaxf(tm0, fmaxf(sacc[nf][0], sacc[nf][1]));
            tm1 = fmaxf(tm1, fmaxf(sacc[nf][2], sacc[nf][3]));
        }
        tm0 = fmaxf(tm0, __shfl_xor_sync(~0u, tm0, 1));
        tm0 = fmaxf(tm0, __shfl_xor_sync(~0u, tm0, 2));
        tm1 = fmaxf(tm1, __shfl_xor_sync(~0u, tm1, 1));
        tm1 = fmaxf(tm1, __shfl_xor_sync(~0u, tm1, 2));
        float mn0 = fmaxf(m0, tm0), mn1 = fmaxf(m1, tm1);
        float a0 = __expf(m0 - mn0), a1 = __expf(m1 - mn1);
        m0 = mn0; m1 = mn1;
        float rs0 = 0.f, rs1 = 0.f;
#pragma unroll
        for (int nf = 0; nf < 16; nf++) {
            float p0 = __expf(sacc[nf][0] - mn0); sacc[nf][0] = p0; rs0 += p0;
            float p1 = __expf(sacc[nf][1] - mn0); sacc[nf][1] = p1; rs0 += p1;
            float p2 = __expf(sacc[nf][2] - mn1); sacc[nf][2] = p2; rs1 += p2;
            float p3 = __expf(sacc[nf][3] - mn1); sacc[nf][3] = p3; rs1 += p3;
        }
        rs0 += __shfl_xor_sync(~0u, rs0, 1); rs0 += __shfl_xor_sync(~0u, rs0, 2);
        rs1 += __shfl_xor_sync(~0u, rs1, 1); rs1 += __shfl_xor_sync(~0u, rs1, 2);
        l0 = l0 * a0 + rs0; l1 = l1 * a1 + rs1;
#pragma unroll
        for (int vnf = 0; vnf < 8; vnf++) {
            O1a[vnf][0] *= a0; O1a[vnf][1] *= a0; O1a[vnf][2] *= a1; O1a[vnf][3] *= a1;
            if (NV == 2) { O2a[vnf][0] *= a0; O2a[vnf][1] *= a0; O2a[vnf][2] *= a1; O2a[vnf][3] *= a1; }
        }

        // ---- O += P V (3-term split), ldmatrix.x4 over vnf pairs ----
#pragma unroll
        for (int kcp = 0; kcp < 8; kcp++) {
            uint32_t ph[4], pl[4];
            split2pack(sacc[2 * kcp][0],     sacc[2 * kcp][1],     ph[0], pl[0]);
            split2pack(sacc[2 * kcp][2],     sacc[2 * kcp][3],     ph[1], pl[1]);
            split2pack(sacc[2 * kcp + 1][0], sacc[2 * kcp + 1][1], ph[2], pl[2]);
            split2pack(sacc[2 * kcp + 1][2], sacc[2 * kcp + 1][3], ph[3], pl[3]);
#pragma unroll
            for (int vnp = 0; vnp < 4; vnp++) {
                int off = cur + (vnp * 16 + ((lane >> 4) & 1) * 8 + (lane & 7)) * 136
                        + kcp * 16 + ((lane >> 3) & 1) * 8;
                uint32_t vh4[4], vl4[4];
                ldsm4(vh4[0], vh4[1], vh4[2], vh4[3], smaddr(&bV1h[off]));
                ldsm4(vl4[0], vl4[1], vl4[2], vl4[3], smaddr(&bV1l[off]));
                uint32_t v0h[2] = {vh4[0], vh4[1]}, v1h[2] = {vh4[2], vh4[3]};
                uint32_t v0l[2] = {vl4[0], vl4[1]}, v1l[2] = {vl4[2], vl4[3]};
                MMA16816(O1a[2 * vnp],     ph, v0h);
                MMA16816(O1a[2 * vnp],     ph, v0l);
                MMA16816(O1a[2 * vnp],     pl, v0h);
                MMA16816(O1a[2 * vnp + 1], ph, v1h);
                MMA16816(O1a[2 * vnp + 1], ph, v1l);
                MMA16816(O1a[2 * vnp + 1], pl, v1h);
                if (NV == 2) {
                    uint32_t wh4[4], wl4[4];
                    ldsm4(wh4[0], wh4[1], wh4[2], wh4[3], smaddr(&bV2h[off]));
                    ldsm4(wl4[0], wl4[1], wl4[2], wl4[3], smaddr(&bV2l[off]));
                    uint32_t w0h[2] = {wh4[0], wh4[1]}, w1h[2] = {wh4[2], wh4[3]};
                    uint32_t w0l[2] = {wl4[0], wl4[1]}, w1l[2] = {wl4[2], wl4[3]};
                    MMA16816(O2a[2 * vnp],     ph, w0h);
                    MMA16816(O2a[2 * vnp],     ph, w0l);
                    MMA16816(O2a[2 * vnp],     pl, w0h);
                    MMA16816(O2a[2 * vnp + 1], ph, w1h);
                    MMA16816(O2a[2 * vnp + 1], ph, w1l);
                    MMA16816(O2a[2 * vnp + 1], pl, w1h);
                }
            }
        }
        __syncthreads();
    }

    // ---- finalize ----
    const float i0 = 1.f / l0, i1 = 1.f / l1;
#pragma unroll
    for (int vnf = 0; vnf < 8; vnf++) {
        O1a[vnf][0] *= i0; O1a[vnf][1] *= i0; O1a[vnf][2] *= i1; O1a[vnf][3] *= i1;
        if (NV == 2) { O2a[vnf][0] *= i0; O2a[vnf][1] *= i0; O2a[vnf][2] *= i1; O2a[vnf][3] *= i1; }
    }

    const int r = wm + (lane >> 2);
    if (NV == 2) {
        // residual add (u = a3 @ v + v)
        const float* R1p = R1 + (size_t)zb * 2097152 + (size_t)zh * 64;
        const float* R2p = R2 + (size_t)zb * 2097152 + (size_t)zh * 64;
        const size_t row = (size_t)(tok0 + r);
#pragma unroll
        for (int vnf = 0; vnf < 8; vnf++) {
            int c0 = vnf * 8 + (lane & 3) * 2;
            float2 ra = *(const float2*)&R1p[row * 2048 + c0];
            float2 rb = *(const float2*)&R1p[(row + 8) * 2048 + c0];
            O1a[vnf][0] += ra.x; O1a[vnf][1] += ra.y; O1a[vnf][2] += rb.x; O1a[vnf][3] += rb.y;
            float2 rc = *(const float2*)&R2p[row * 2048 + c0];
            float2 rd = *(const float2*)&R2p[(row + 8) * 2048 + c0];
            O2a[vnf][0] += rc.x; O2a[vnf][1] += rc.y; O2a[vnf][2] += rd.x; O2a[vnf][3] += rd.y;
        }
        // transposed plane output via smem bounce (stage-0 K buffers are free)
#pragma unroll
        for (int s = 0; s < 2; s++) {
            float (*Oa)[4] = s ? O2a : O1a;
#pragma unroll
            for (int vnf = 0; vnf < 8; vnf++) {
                int c0 = vnf * 8 + (lane & 3) * 2;
                uint32_t hp, lp;
                split2pack(Oa[vnf][0], Oa[vnf][1], hp, lp);
                *(uint32_t*)&bKh[r * 72 + c0] = hp;
                *(uint32_t*)&bKl[r * 72 + c0] = lp;
                split2pack(Oa[vnf][2], Oa[vnf][3], hp, lp);
                *(uint32_t*)&bKh[(r + 8) * 72 + c0] = hp;
                *(uint32_t*)&bKl[(r + 8) * 72 + c0] = lp;
            }
            __syncthreads();
            __nv_bfloat16* OH = (s ? O2h : O1h) + (size_t)z * 65536 + tok0;
            __nv_bfloat16* OL = (s ? O2l : O1l) + (size_t)z * 65536 + tok0;
            for (int i = tid; i < 2048; i += 256) {
                int plane = i >> 10, rem = i & 1023, d = rem >> 4, ch = (rem & 15) * 8;
                const unsigned short* src = (const unsigned short*)(plane ? bKl : bKh);
                unsigned short v[8];
#pragma unroll
                for (int j = 0; j < 8; j++) v[j] = src[(ch + j) * 72 + d];
                uint4 pk;
                pk.x = (uint32_t)v[0] | ((uint32_t)v[1] << 16);
                pk.y = (uint32_t)v[2] | ((uint32_t)v[3] << 16);
                pk.z = (uint32_t)v[4] | ((uint32_t)v[5] << 16);
                pk.w = (uint32_t)v[6] | ((uint32_t)v[7] << 16);
                *(uint4*)((plane ? OL : OH) + (size_t)d * 1024 + ch) = pk;
            }
            __syncthreads();
        }
    } else {
        // row-major plane output
        __nv_bfloat16* OH = O1h + (size_t)zb * 524288 + zh * 64;
        __nv_bfloat16* OL = O1l + (size_t)zb * 524288 + zh * 64;
        const size_t row = (size_t)(tok0 + r);
#pragma unroll
        for (int vnf = 0; vnf < 8; vnf++) {
            int c0 = vnf * 8 + (lane & 3) * 2;
            uint32_t hp, lp;
            split2pack(O1a[vnf][0], O1a[vnf][1], hp, lp);
            *(uint32_t*)&OH[row * 512 + c0] = hp;
            *(uint32_t*)&OL[row * 512 + c0] = lp;
            split2pack(O1a[vnf][2], O1a[vnf][3], hp, lp);
            *(uint32_t*)&OH[(row + 8) * 512 + c0] = hp;
            *(uint32_t*)&OL[(row + 8) * 512 + c0] = lp;
        }
    }
}

// ---------------------------------------------------------------------------
// conv_all: all 6 operand conversions in ONE launch (keeps fattn<2> as the
// 6th launch so ncu -s 5 -c 1 profiles it).
// blocks: [0,4096) x1 | [4096,8192) x2 | [8192,12288) Wq1 | [12288,16384) Wq2
//         | [16384,17408) Wo1 | [17408,18432) Wo2
// ---------------------------------------------------------------------------
__global__ void conv_all(
    const float* __restrict__ x1, const float* __restrict__ x2,
    const float* __restrict__ Wq1f, const float* __restrict__ Wq2f,
    const float* __restrict__ Wo1f, const float* __restrict__ Wo2f,
    __nv_bfloat16* __restrict__ xp1, __nv_bfloat16* __restrict__ xp2,
    __nv_bfloat16* __restrict__ Wq1, __nv_bfloat16* __restrict__ Wq2,
    __nv_bfloat16* __restrict__ Wo1, __nv_bfloat16* __restrict__ Wo2)
{
    int b = blockIdx.x;
    if (b < 8192) {
        const float* X; __nv_bfloat16 *H, *L;
        if (b < 4096) { X = x1; H = xp1; L = xp1 + PXc; }
        else          { X = x2; H = xp2; L = xp2 + PXc; b -= 4096; }
        int i = b * 256 + threadIdx.x;
        float4 v = ((const float4*)X)[i];
        uint32_t hp, lp;
        split2pack(v.x, v.y, hp, lp);
        *(uint32_t*)&H[(size_t)i * 4] = hp; *(uint32_t*)&L[(size_t)i * 4] = lp;
        split2pack(v.z, v.w, hp, lp);
        *(uint32_t*)&H[(size_t)i * 4 + 2] = hp; *(uint32_t*)&L[(size_t)i * 4 + 2] = lp;
    } else {
        b -= 8192;
        const float* W; __nv_bfloat16 *H, *L; int N;
        if (b < 4096)      { W = Wq1f; H = Wq1; L = Wq1 + PWc;  N = 2048; }
        else if (b < 8192) { W = Wq2f; H = Wq2; L = Wq2 + PWc;  N = 2048; b -= 4096; }
        else if (b < 9216) { W = Wo1f; H = Wo1; L = Wo1 + PWoc; N = 512;  b -= 8192; }
        else               { W = Wo2f; H = Wo2; L = Wo2 + PWoc; N = 512;  b -= 9216; }
        int i = b * 256 + threadIdx.x;
        int n = i >> 9, k = i & 511;   // K = 512
        float v = W[(size_t)k * N + n];
        split1(v, H[i], L[i]);
    }
}

// ---------------------------------------------------------------------------
// vtrans (both streams in one launch): qkv fp32 v-region -> transposed planes
// vT[(z*64+n)][token]. grid (16, 128).
// ---------------------------------------------------------------------------
__global__ void vtrans2k(const float* __restrict__ qkv1, const float* __restrict__ qkv2,
                         __nv_bfloat16* __restrict__ H1, __nv_bfloat16* __restrict__ L1,
                         __nv_bfloat16* __restrict__ H2, __nv_bfloat16* __restrict__ L2)
{
    __shared__ float t[64][65];
    const int zz = blockIdx.y;
    const float* qkv = (zz < 64) ? qkv1 : qkv2;
    __nv_bfloat16* H  = (zz < 64) ? H1 : H2;
    __nv_bfloat16* L  = (zz < 64) ? L1 : L2;
    const int z = zz & 63, tokb = blockIdx.x, b = z >> 3, h = z & 7;
    const int tid = threadIdx.x;
    for (int i = tid; i < 4096; i += 256) {
        int tl = i >> 6, n = i & 63;
        t[tl][n] = qkv[(size_t)(b * 1024 + tokb * 64 + tl) * 2048 + 1024 + h * 64 + n];
    }
    __syncthreads();
    for (int i = tid; i < 4096; i += 256) {
        int n = i >> 6, tl = i & 63;
        float v = t[tl][n];
        size_t o = ((size_t)z * 64 + n) * 1024 + tokb * 64 + tl;
        split1(v, H[o], L[o]);
    }
}

// ---------------------------------------------------------------------------
// Gate: MS = s1+s2; depthwise conv-5 over features; MSg = sigmoid(.)*MS -> planes
// ---------------------------------------------------------------------------
__global__ __launch_bounds__(128) void gate_conv(
    const float* __restrict__ qkv1, const float* __restrict__ qkv2,
    const float* __restrict__ w, const float* __restrict__ cb,
    __nv_bfloat16* __restrict__ H, __nv_bfloat16* __restrict__ L)
{
    __shared__ float ms[516];
    const int bn = blockIdx.x, n = bn & 1023, tid = threadIdx.x;
    const float* r1 = qkv1 + (size_t)bn * 2048 + 1536;
    const float* r2 = qkv2 + (size_t)bn * 2048 + 1536;
    for (int f = tid; f < 512; f += 128) ms[f + 2] = r1[f] + r2[f];
    if (tid < 2) { ms[tid] = 0.f; ms[514 + tid] = 0.f; }
    __syncthreads();
    const float w0 = w[n * 5], w1 = w[n * 5 + 1], w2 = w[n * 5 + 2],
                w3 = w[n * 5 + 3], w4 = w[n * 5 + 4], bb = cb[n];
    for (int f = tid; f < 512; f += 128) {
        float a = w0 * ms[f] + w1 * ms[f + 1] + w2 * ms[f + 2]
                + w3 * ms[f + 3] + w4 * ms[f + 4] + bb;
        float s = 1.f / (1.f + __expf(-a));
        float v = s * ms[f + 2];
        split1(v, H[(size_t)bn * 512 + f], L[(size_t)bn * 512 + f]);
    }
}

// ---------------------------------------------------------------------------
// Launch — order matters: 6th launch (index 5) = fattn<2> gets profiled.
// ---------------------------------------------------------------------------
extern "C" void kernel_launch(void* const* d_in, const int* in_sizes, int n_in,
                              void* d_out, int out_size)
{
    const float* x1    = (const float*)d_in[0];
    const float* x2    = (const float*)d_in[1];
    const float* Wqkv1 = (const float*)d_in[2];
    const float* Wqkv2 = (const float*)d_in[3];
    const float* Wout1 = (const float*)d_in[4];
    const float* bout1 = (const float*)d_in[5];
    const float* Wout2 = (const float*)d_in[6];
    const float* bout2 = (const float*)d_in[7];
    const float* convw = (const float*)d_in[8];
    const float* convb = (const float*)d_in[9];
    float* out = (float*)d_out;

    __nv_bfloat16 *xp1, *xp2, *Wq1, *Wq2, *Wo1, *Wo2, *qkvp1, *qkvp2,
                  *vT1, *vT2, *msgp, *uT1, *uT2, *tp1, *tp2;
    float *qkv1, *qkv2;
    cudaGetSymbolAddress((void**)&xp1, g_xp1);   cudaGetSymbolAddress((void**)&xp2, g_xp2);
    cudaGetSymbolAddress((void**)&Wq1, g_Wq1);   cudaGetSymbolAddress((void**)&Wq2, g_Wq2);
    cudaGetSymbolAddress((void**)&Wo1, g_Wo1);   cudaGetSymbolAddress((void**)&Wo2, g_Wo2);
    cudaGetSymbolAddress((void**)&qkv1, g_qkv1); cudaGetSymbolAddress((void**)&qkv2, g_qkv2);
    cudaGetSymbolAddress((void**)&qkvp1, g_qkvp1); cudaGetSymbolAddress((void**)&qkvp2, g_qkvp2);
    cudaGetSymbolAddress((void**)&vT1, g_vT1);   cudaGetSymbolAddress((void**)&vT2, g_vT2);
    cudaGetSymbolAddress((void**)&msgp, g_msgp);
    cudaGetSymbolAddress((void**)&uT1, g_uT1);   cudaGetSymbolAddress((void**)&uT2, g_uT2);
    cudaGetSymbolAddress((void**)&tp1, g_tp1);   cudaGetSymbolAddress((void**)&tp2, g_tp2);

    const long long PX  = PXc;
    const long long PQ  = PQc;
    const long long PW  = PWc;
    const long long PWo = PWoc;
    const long long PV  = PVc;

    const int SMEM2 = 2 * (2 * 128 * 72 + 4 * 64 * 136) * 2;  // 212992 (2 stages)
    const int SMEM1 = 2 * (2 * 128 * 72 + 2 * 64 * 136) * 2;  // 143360 (2 stages)
    cudaFuncSetAttribute(fattn<2>, cudaFuncAttributeMaxDynamicSharedMemorySize, SMEM2);
    cudaFuncSetAttribute(fattn<1>, cudaFuncAttributeMaxDynamicSharedMemorySize, SMEM1);

    // 1: all operand conversions
    conv_all<<<18432, 256>>>(x1, x2, Wqkv1, Wqkv2, Wout1, Wout2,
                             xp1, xp2, Wq1, Wq2, Wo1, Wo2);

    // 2-3: QKVS projections (fp32 only for v/s cols, planes only for q/k cols)
    gemm_bs<F_F32 | F_PLANES | F_QKVSPL><<<dim3(16, 64), 256>>>(
        xp1, xp1 + PX, 512, Wq1, Wq1 + PW, 512,
        qkv1, 2048, qkvp1, qkvp1 + PQ, 2048, nullptr, 512);
    gemm_bs<F_F32 | F_PLANES | F_QKVSPL><<<dim3(16, 64), 256>>>(
        xp2, xp2 + PX, 512, Wq2, Wq2 + PW, 512,
        qkv2, 2048, qkvp2, qkvp2 + PQ, 2048, nullptr, 512);

    // 4: gate path
    gate_conv<<<8192, 128>>>(qkv1, qkv2, convw, convb, msgp, msgp + PX);

    // 5: both v transposes
    vtrans2k<<<dim3(16, 128), 256>>>(qkv1, qkv2, vT1, vT1 + PV, vT2, vT2 + PV);

    // 6: Pass 3 fused (PROFILED): a3 = softmax(MSh MSh^T * scale); u_i = a3 @ v_i + v_i
    fattn<2><<<dim3(8, 1, 64), 256, SMEM2>>>(
        msgp, msgp + PX, 512, 524288, 64,
        msgp, msgp + PX, 512, 524288, 64,
        vT1, vT1 + PV, vT2, vT2 + PV,
        qkv1 + 1024, qkv2 + 1024,
        uT1, uT1 + PV, uT2, uT2 + PV);

    // 7: Pass 1 fused: t1 = softmax(q1 k1^T * scale) @ u1
    fattn<1><<<dim3(8, 1, 64), 256, SMEM1>>>(
        qkvp1, qkvp1 + PQ, 2048, 2097152, 64,
        qkvp1 + 512, qkvp1 + PQ + 512, 2048, 2097152, 64,
        uT1, uT1 + PV, nullptr, nullptr,
        nullptr, nullptr,
        tp1, tp1 + PX, nullptr, nullptr);

    // 8: Pass 2 fused: t2 = softmax(q2 k2^T * scale) @ u2
    fattn<1><<<dim3(8, 1, 64), 256, SMEM1>>>(
        qkvp2, qkvp2 + PQ, 2048, 2097152, 64,
        qkvp2 + 512, qkvp2 + PQ + 512, 2048, 2097152, 64,
        uT2, uT2 + PV, nullptr, nullptr,
        nullptr, nullptr,
        tp2, tp2 + PX, nullptr, nullptr);

    // 9-10: Output projections
    gemm_bs<F_F32 | F_BIAS><<<dim3(4, 64), 256>>>(
        tp1, tp1 + PX, 512, Wo1, Wo1 + PWo, 512,
        out, 512, nullptr, nullptr, 0, bout1, 512);
    gemm_bs<F_F32 | F_BIAS><<<dim3(4, 64), 256>>>(
        tp2, tp2 + PX, 512, Wo2, Wo2 + PWo, 512,
        out + 4194304, 512, nullptr, nullptr, 0, bout2, 512);
}

// round 9
// speedup vs baseline: 2.9076x; 1.0307x over previous
#include <cuda_runtime.h>
#include <cuda_bf16.h>
#include <cstdint>

// ---------------------------------------------------------------------------
// B=8, N=1024, DIM=512, H=8, HD=64, INNER=512, KS=5
// Split-bf16 tensor-core pipeline + fused flash-style attention passes.
// Launch order: conv_all(0), qkvs_dual(1), gate_vtrans(2), fattn<2>(3)=PROFILED,
// fattn<1>dual(4), outproj_dual(5).
// ---------------------------------------------------------------------------

#define F_F32    1
#define F_PLANES 2
#define F_BIAS   16
#define F_QKVSPL 32
#define F_DUAL   64

// plane sizes (elems)
#define PXc  4194304LL
#define PQc  16777216LL
#define PWc  1048576LL
#define PWoc 262144LL
#define PVc  4194304LL

// ---------------- scratch ---------------------------------------------------
__device__ __nv_bfloat16 g_xp1 [2ull*8192*512];
__device__ __nv_bfloat16 g_xp2 [2ull*8192*512];
__device__ __nv_bfloat16 g_Wq1 [2ull*2048*512];
__device__ __nv_bfloat16 g_Wq2 [2ull*2048*512];
__device__ __nv_bfloat16 g_Wo1 [2ull*512*512];
__device__ __nv_bfloat16 g_Wo2 [2ull*512*512];
__device__ float         g_qkv1[8192ull*2048];
__device__ float         g_qkv2[8192ull*2048];
__device__ __nv_bfloat16 g_qkvp1[2ull*8192*2048];
__device__ __nv_bfloat16 g_qkvp2[2ull*8192*2048];
__device__ __nv_bfloat16 g_vT1 [2ull*64*64*1024];
__device__ __nv_bfloat16 g_vT2 [2ull*64*64*1024];
__device__ __nv_bfloat16 g_msgp[2ull*8192*512];
__device__ __nv_bfloat16 g_uT1 [2ull*64*64*1024];
__device__ __nv_bfloat16 g_uT2 [2ull*64*64*1024];
__device__ __nv_bfloat16 g_tp1 [2ull*8192*512];
__device__ __nv_bfloat16 g_tp2 [2ull*8192*512];

// ---------------- helpers ----------------------------------------------------
__device__ __forceinline__ void split1(float v, __nv_bfloat16& h, __nv_bfloat16& l) {
    h = __float2bfloat16(v);
    l = __float2bfloat16(v - __bfloat162float(h));
}
__device__ __forceinline__ void split2pack(float f0, float f1, uint32_t& hp, uint32_t& lp) {
    __nv_bfloat16 h0, l0, h1, l1;
    split1(f0, h0, l0); split1(f1, h1, l1);
    __nv_bfloat162 th; th.x = h0; th.y = h1; hp = *(uint32_t*)&th;
    __nv_bfloat162 tl; tl.x = l0; tl.y = l1; lp = *(uint32_t*)&tl;
}
__device__ __forceinline__ uint32_t smaddr(const void* p) {
    return (uint32_t)__cvta_generic_to_shared(p);
}
__device__ __forceinline__ void ldsm4(uint32_t& r0, uint32_t& r1, uint32_t& r2, uint32_t& r3, uint32_t a) {
    asm volatile("ldmatrix.sync.aligned.m8n8.x4.shared.b16 {%0,%1,%2,%3},[%4];\n"
                 : "=r"(r0), "=r"(r1), "=r"(r2), "=r"(r3) : "r"(a));
}
__device__ __forceinline__ void ldsm2(uint32_t& r0, uint32_t& r1, uint32_t a) {
    asm volatile("ldmatrix.sync.aligned.m8n8.x2.shared.b16 {%0,%1},[%2];\n"
                 : "=r"(r0), "=r"(r1) : "r"(a));
}
#define MMA16816(c, a, b)                                                            \
    asm volatile("mma.sync.aligned.m16n8k16.row.col.f32.bf16.bf16.f32 "              \
                 "{%0,%1,%2,%3},{%4,%5,%6,%7},{%8,%9},{%0,%1,%2,%3};\n"              \
                 : "+f"((c)[0]), "+f"((c)[1]), "+f"((c)[2]), "+f"((c)[3])            \
                 : "r"((a)[0]), "r"((a)[1]), "r"((a)[2]), "r"((a)[3]),               \
                   "r"((b)[0]), "r"((b)[1]))
#define CPA16(dst, src)                                                              \
    asm volatile("cp.async.ca.shared.global [%0], [%1], 16;\n" :: "r"(dst), "l"(src))
#define CPCOMMIT() asm volatile("cp.async.commit_group;\n" ::: "memory")
#define CPWAIT1()  asm volatile("cp.async.wait_group 1;\n" ::: "memory")
#define CPWAIT0()  asm volatile("cp.async.wait_group 0;\n" ::: "memory")

// ---------------------------------------------------------------------------
// Split-bf16 GEMM (projections). Block 128x128xK16, double-buffered.
// F_DUAL: blockIdx.z==1 switches to the second pointer set (stream 2).
// ---------------------------------------------------------------------------
template <int FLAGS>
__global__ __launch_bounds__(256) void gemm_bs(
    const __nv_bfloat16* __restrict__ Ah, const __nv_bfloat16* __restrict__ Al, long long lda,
    const __nv_bfloat16* __restrict__ Bh, const __nv_bfloat16* __restrict__ Bl, long long ldb,
    float* __restrict__ C32, long long ldc,
    __nv_bfloat16* __restrict__ Ch, __nv_bfloat16* __restrict__ Cl, long long ldcp,
    const float* __restrict__ bias, int K,
    const __nv_bfloat16* Ah2, const __nv_bfloat16* Al2,
    const __nv_bfloat16* Bh2, const __nv_bfloat16* Bl2,
    float* C32b, __nv_bfloat16* Ch2, __nv_bfloat16* Cl2,
    const float* bias2)
{
    if ((FLAGS & F_DUAL) && blockIdx.z == 1) {
        Ah = Ah2; Al = Al2; Bh = Bh2; Bl = Bl2;
        C32 = C32b; Ch = Ch2; Cl = Cl2; bias = bias2;
    }

    __shared__ __align__(16) __nv_bfloat16 sA[2][2][128][24];
    __shared__ __align__(16) __nv_bfloat16 sB[2][2][128][24];

    const int tid = threadIdx.x;
    const __nv_bfloat16* srcA[2]; int aP[2], aR[2], aH[2];
#pragma unroll
    for (int j = 0; j < 2; j++) {
        int idx = tid + j * 256;
        aP[j] = idx >> 8; int rem = idx & 255; aR[j] = rem >> 1; aH[j] = rem & 1;
        const __nv_bfloat16* base = aP[j] ? Al : Ah;
        srcA[j] = base + (size_t)(blockIdx.y * 128 + aR[j]) * lda + aH[j] * 8;
    }
    const __nv_bfloat16* srcB[2]; int bP[2], bR[2], bH[2];
#pragma unroll
    for (int j = 0; j < 2; j++) {
        int idx = tid + j * 256;
        bP[j] = idx >> 8; int rem = idx & 255; bR[j] = rem >> 1; bH[j] = rem & 1;
        const __nv_bfloat16* base = bP[j] ? Bl : Bh;
        srcB[j] = base + (size_t)(blockIdx.x * 128 + bR[j]) * ldb + bH[j] * 8;
    }
#pragma unroll
    for (int j = 0; j < 2; j++) {
        *(uint4*)&sA[0][aP[j]][aR[j]][aH[j] * 8] = *(const uint4*)srcA[j];
        *(uint4*)&sB[0][bP[j]][bR[j]][bH[j] * 8] = *(const uint4*)srcB[j];
    }
    __syncthreads();

    const int lane = tid & 31, w = tid >> 5;
    const int wm = (w >> 2) * 64, wn = (w & 3) * 32;

    float acc[4][4][4];
#pragma unroll
    for (int i = 0; i < 4; i++)
#pragma unroll
        for (int j = 0; j < 4; j++)
#pragma unroll
            for (int k = 0; k < 4; k++) acc[i][j][k] = 0.f;

    const int nk = K >> 4;
    for (int kt = 0; kt < nk; ++kt) {
        const int cur = kt & 1;
        const bool pf = (kt + 1) < nk;
        uint4 ra[2], rb[2];
        if (pf) {
            long long k0 = (long long)(kt + 1) * 16;
#pragma unroll
            for (int j = 0; j < 2; j++) { ra[j] = *(const uint4*)(srcA[j] + k0); rb[j] = *(const uint4*)(srcB[j] + k0); }
        }
        uint32_t bhf[4][2], blf[4][2], af[4][4];
#pragma unroll
        for (int nf = 0; nf < 4; nf++) {
            ldsm2(bhf[nf][0], bhf[nf][1], smaddr(&sB[cur][0][wn + nf * 8 + (lane & 7)][((lane >> 3) & 1) * 8]));
            ldsm2(blf[nf][0], blf[nf][1], smaddr(&sB[cur][1][wn + nf * 8 + (lane & 7)][((lane >> 3) & 1) * 8]));
        }
#pragma unroll
        for (int mf = 0; mf < 4; mf++)
            ldsm4(af[mf][0], af[mf][1], af[mf][2], af[mf][3],
                  smaddr(&sA[cur][0][wm + mf * 16 + (lane & 15)][(lane >> 4) * 8]));
#pragma unroll
        for (int mf = 0; mf < 4; mf++)
#pragma unroll
            for (int nf = 0; nf < 4; nf++) { MMA16816(acc[mf][nf], af[mf], bhf[nf]); MMA16816(acc[mf][nf], af[mf], blf[nf]); }
#pragma unroll
        for (int mf = 0; mf < 4; mf++)
            ldsm4(af[mf][0], af[mf][1], af[mf][2], af[mf][3],
                  smaddr(&sA[cur][1][wm + mf * 16 + (lane & 15)][(lane >> 4) * 8]));
#pragma unroll
        for (int mf = 0; mf < 4; mf++)
#pragma unroll
            for (int nf = 0; nf < 4; nf++) MMA16816(acc[mf][nf], af[mf], bhf[nf]);
        if (pf) {
            const int nb = cur ^ 1;
#pragma unroll
            for (int j = 0; j < 2; j++) {
                *(uint4*)&sA[nb][aP[j]][aR[j]][aH[j] * 8] = ra[j];
                *(uint4*)&sB[nb][bP[j]][bR[j]][bH[j] * 8] = rb[j];
            }
        }
        __syncthreads();
    }

#pragma unroll
    for (int mf = 0; mf < 4; mf++) {
        const int r0 = blockIdx.y * 128 + wm + mf * 16 + (lane >> 2);
#pragma unroll
        for (int nf = 0; nf < 4; nf++) {
            const int c0 = blockIdx.x * 128 + wn + nf * 8 + (lane & 3) * 2;
            float v00 = acc[mf][nf][0], v01 = acc[mf][nf][1];
            float v10 = acc[mf][nf][2], v11 = acc[mf][nf][3];
            if constexpr (FLAGS & F_BIAS) {
                float b0 = bias[c0], b1 = bias[c0 + 1];
                v00 += b0; v01 += b1; v10 += b0; v11 += b1;
            }
            const bool wf32 = !(FLAGS & F_QKVSPL) || (c0 >= 1024);  // v,s regions only
            const bool wpl  = !(FLAGS & F_QKVSPL) || (c0 < 1024);   // q,k regions only
            if constexpr (FLAGS & F_F32) {
                if (wf32) {
                    *(float2*)&C32[(size_t)r0 * ldc + c0]       = make_float2(v00, v01);
                    *(float2*)&C32[(size_t)(r0 + 8) * ldc + c0] = make_float2(v10, v11);
                }
            }
            if constexpr (FLAGS & F_PLANES) {
                if (wpl) {
                    uint32_t hp, lp;
                    split2pack(v00, v01, hp, lp);
                    *(uint32_t*)&Ch[(size_t)r0 * ldcp + c0] = hp;
                    *(uint32_t*)&Cl[(size_t)r0 * ldcp + c0] = lp;
                    split2pack(v10, v11, hp, lp);
                    *(uint32_t*)&Ch[(size_t)(r0 + 8) * ldcp + c0] = hp;
                    *(uint32_t*)&Cl[(size_t)(r0 + 8) * ldcp + c0] = lp;
                }
            }
        }
    }
}

// ---------------------------------------------------------------------------
// Fused flash attention. 2-stage cp.async pipeline + ldmatrix.x4 fragment loads.
// NV=2 (pass3): dual V + residual + transposed plane output, grid (8,1,64).
// NV=1: single V, row-major plane output; blockIdx.y selects stream, grid (8,2,64).
// ---------------------------------------------------------------------------
template <int NV>
__global__ __launch_bounds__(256) void fattn(
    const __nv_bfloat16* Qh, const __nv_bfloat16* Ql,
    long long ldq, long long qob, long long qoh,
    const __nv_bfloat16* Kh, const __nv_bfloat16* Kl,
    long long ldk, long long kob, long long koh,
    const __nv_bfloat16* V1h, const __nv_bfloat16* V1l,
    const __nv_bfloat16* V2h, const __nv_bfloat16* V2l,
    const float* __restrict__ R1, const float* __restrict__ R2,
    __nv_bfloat16* O1h, __nv_bfloat16* O1l,
    __nv_bfloat16* __restrict__ O2h, __nv_bfloat16* __restrict__ O2l,
    const __nv_bfloat16* Q2h, const __nv_bfloat16* Q2l,
    const __nv_bfloat16* K2h, const __nv_bfloat16* K2l,
    const __nv_bfloat16* W1h, const __nv_bfloat16* W1l,
    __nv_bfloat16* P1h, __nv_bfloat16* P1l)
{
    if (NV == 1 && blockIdx.y == 1) {
        Qh = Q2h; Ql = Q2l; Kh = K2h; Kl = K2l;
        V1h = W1h; V1l = W1l; O1h = P1h; O1l = P1l;
    }

    constexpr int SKP = 128 * 72;                    // K plane tile elems
    constexpr int SVP = 64 * 136;                    // V plane tile elems
    constexpr int STG = 2 * SKP + NV * 2 * SVP;      // elems per pipeline stage
    extern __shared__ __align__(16) __nv_bfloat16 sm[];
    // per-stage layout: Kh, Kl, V1h, V1l, [V2h, V2l]
    __nv_bfloat16* bKh  = sm;
    __nv_bfloat16* bKl  = sm + SKP;
    __nv_bfloat16* bV1h = sm + 2 * SKP;
    __nv_bfloat16* bV1l = bV1h + SVP;
    __nv_bfloat16* bV2h = bV1l + SVP;
    __nv_bfloat16* bV2l = bV2h + SVP;

    const int tid = threadIdx.x, lane = tid & 31, w = tid >> 5;
    const int wm = w * 16;
    const int z = blockIdx.z, zb = z >> 3, zh = z & 7;
    const int tok0 = blockIdx.x * 128;

    const __nv_bfloat16* Qbh = Qh + zb * qob + zh * qoh + (long long)tok0 * ldq;
    const __nv_bfloat16* Qbl = Ql + zb * qob + zh * qoh + (long long)tok0 * ldq;
    const __nv_bfloat16* Kbh = Kh + zb * kob + zh * koh;
    const __nv_bfloat16* Kbl = Kl + zb * kob + zh * koh;
    const __nv_bfloat16* V1bh = V1h + (size_t)z * 65536;
    const __nv_bfloat16* V1bl = V1l + (size_t)z * 65536;
    const __nv_bfloat16* V2bh = (NV == 2) ? V2h + (size_t)z * 65536 : nullptr;
    const __nv_bfloat16* V2bl = (NV == 2) ? V2l + (size_t)z * 65536 : nullptr;

    // ---- stage Q (scaled by 2^-3, exact on both planes) into stage-0 K buf ----
    {
        __nv_bfloat162 sc = __float2bfloat162_rn(0.125f);
        for (int i = tid; i < 1024; i += 256) {
            int r = i >> 3, c = (i & 7) * 8;
            const __nv_bfloat162* s0 = (const __nv_bfloat162*)(Qbh + (size_t)r * ldq + c);
            __nv_bfloat162* d0 = (__nv_bfloat162*)&bKh[r * 72 + c];
            d0[0] = __hmul2(s0[0], sc); d0[1] = __hmul2(s0[1], sc);
            d0[2] = __hmul2(s0[2], sc); d0[3] = __hmul2(s0[3], sc);
            const __nv_bfloat162* s1 = (const __nv_bfloat162*)(Qbl + (size_t)r * ldq + c);
            __nv_bfloat162* d1 = (__nv_bfloat162*)&bKl[r * 72 + c];
            d1[0] = __hmul2(s1[0], sc); d1[1] = __hmul2(s1[1], sc);
            d1[2] = __hmul2(s1[2], sc); d1[3] = __hmul2(s1[3], sc);
        }
    }
    __syncthreads();
    uint32_t qh[4][4], ql[4][4];
#pragma unroll
    for (int kc = 0; kc < 4; kc++) {
        ldsm4(qh[kc][0], qh[kc][1], qh[kc][2], qh[kc][3],
              smaddr(&bKh[(wm + (lane & 15)) * 72 + kc * 16 + (lane >> 4) * 8]));
        ldsm4(ql[kc][0], ql[kc][1], ql[kc][2], ql[kc][3],
              smaddr(&bKl[(wm + (lane & 15)) * 72 + kc * 16 + (lane >> 4) * 8]));
    }
    __syncthreads();

    // ---- pipeline prologue: stage 0 loads (kt = 0) ----
    {
        for (int i = tid; i < 1024; i += 256) {
            int r = i >> 3, c = (i & 7) * 8;
            CPA16(smaddr(&bKh[r * 72 + c]), Kbh + (size_t)r * ldk + c);
            CPA16(smaddr(&bKl[r * 72 + c]), Kbl + (size_t)r * ldk + c);
        }
        for (int i = tid; i < 1024; i += 256) {
            int d = i >> 4, c = (i & 15) * 8;
            size_t so = (size_t)d * 1024 + c;
            CPA16(smaddr(&bV1h[d * 136 + c]), V1bh + so);
            CPA16(smaddr(&bV1l[d * 136 + c]), V1bl + so);
            if (NV == 2) {
                CPA16(smaddr(&bV2h[d * 136 + c]), V2bh + so);
                CPA16(smaddr(&bV2l[d * 136 + c]), V2bl + so);
            }
        }
        CPCOMMIT();
    }

    float m0 = -1e30f, m1 = -1e30f, l0 = 0.f, l1 = 0.f;
    float O1a[8][4], O2a[8][4];
#pragma unroll
    for (int i = 0; i < 8; i++)
#pragma unroll
        for (int j = 0; j < 4; j++) { O1a[i][j] = 0.f; if (NV == 2) O2a[i][j] = 0.f; }

    for (int kt = 0; kt < 8; kt++) {
        const int cur = (kt & 1) * STG;
        const bool pf = (kt + 1) < 8;
        if (pf) {
            const int nxt = ((kt + 1) & 1) * STG;
            for (int i = tid; i < 1024; i += 256) {
                int r = i >> 3, c = (i & 7) * 8;
                CPA16(smaddr(&bKh[nxt + r * 72 + c]), Kbh + (size_t)((kt + 1) * 128 + r) * ldk + c);
                CPA16(smaddr(&bKl[nxt + r * 72 + c]), Kbl + (size_t)((kt + 1) * 128 + r) * ldk + c);
            }
            for (int i = tid; i < 1024; i += 256) {
                int d = i >> 4, c = (i & 15) * 8;
                size_t so = (size_t)d * 1024 + (kt + 1) * 128 + c;
                CPA16(smaddr(&bV1h[nxt + d * 136 + c]), V1bh + so);
                CPA16(smaddr(&bV1l[nxt + d * 136 + c]), V1bl + so);
                if (NV == 2) {
                    CPA16(smaddr(&bV2h[nxt + d * 136 + c]), V2bh + so);
                    CPA16(smaddr(&bV2l[nxt + d * 136 + c]), V2bl + so);
                }
            }
            CPCOMMIT();
            CPWAIT1();
        } else {
            CPWAIT0();
        }
        __syncthreads();

        // ---- S = Q K^T (3-term split), ldmatrix.x4 over nf pairs ----
        float sacc[16][4];
#pragma unroll
        for (int nf = 0; nf < 16; nf++)
#pragma unroll
            for (int j = 0; j < 4; j++) sacc[nf][j] = 0.f;
#pragma unroll
        for (int kc = 0; kc < 4; kc++) {
#pragma unroll
            for (int nfp = 0; nfp < 8; nfp++) {
                uint32_t bh4[4], bl4[4];
                int off = cur + (nfp * 16 + ((lane >> 4) & 1) * 8 + (lane & 7)) * 72
                        + kc * 16 + ((lane >> 3) & 1) * 8;
                ldsm4(bh4[0], bh4[1], bh4[2], bh4[3], smaddr(&bKh[off]));
                ldsm4(bl4[0], bl4[1], bl4[2], bl4[3], smaddr(&bKl[off]));
                uint32_t b0h[2] = {bh4[0], bh4[1]}, b1h[2] = {bh4[2], bh4[3]};
                uint32_t b0l[2] = {bl4[0], bl4[1]}, b1l[2] = {bl4[2], bl4[3]};
                MMA16816(sacc[2 * nfp],     qh[kc], b0h);
                MMA16816(sacc[2 * nfp],     qh[kc], b0l);
                MMA16816(sacc[2 * nfp],     ql[kc], b0h);
                MMA16816(sacc[2 * nfp + 1], qh[kc], b1h);
                MMA16816(sacc[2 * nfp + 1], qh[kc], b1l);
                MMA16816(sacc[2 * nfp + 1], ql[kc], b1h);
            }
        }

        // ---- online softmax ----
        float tm0 = -1e30f, tm1 = -1e30f;
#pragma unroll
        for (int nf = 0; nf < 16; nf++) {
            tm0 = fmaxf(tm0, fmaxf(sacc[nf][0], sacc[nf][1]));
            tm1 = fmaxf(tm1, fmaxf(sacc[nf][2], sacc[nf][3]));
        }
        tm0 = fmaxf(tm0, __shfl_xor_sync(~0u, tm0, 1));
        tm0 = fmaxf(tm0, __shfl_xor_sync(~0u, tm0, 2));
        tm1 = fmaxf(tm1, __shfl_xor_sync(~0u, tm1, 1));
        tm1 = fmaxf(tm1, __shfl_xor_sync(~0u, tm1, 2));
        float mn0 = fmaxf(m0, tm0), mn1 = fmaxf(m1, tm1);
        float a0 = __expf(m0 - mn0), a1 = __expf(m1 - mn1);
        m0 = mn0; m1 = mn1;
        float rs0 = 0.f, rs1 = 0.f;
#pragma unroll
        for (int nf = 0; nf < 16; nf++) {
            float p0 = __expf(sacc[nf][0] - mn0); sacc[nf][0] = p0; rs0 += p0;
            float p1 = __expf(sacc[nf][1] - mn0); sacc[nf][1] = p1; rs0 += p1;
            float p2 = __expf(sacc[nf][2] - mn1); sacc[nf][2] = p2; rs1 += p2;
            float p3 = __expf(sacc[nf][3] - mn1); sacc[nf][3] = p3; rs1 += p3;
        }
        rs0 += __shfl_xor_sync(~0u, rs0, 1); rs0 += __shfl_xor_sync(~0u, rs0, 2);
        rs1 += __shfl_xor_sync(~0u, rs1, 1); rs1 += __shfl_xor_sync(~0u, rs1, 2);
        l0 = l0 * a0 + rs0; l1 = l1 * a1 + rs1;
#pragma unroll
        for (int vnf = 0; vnf < 8; vnf++) {
            O1a[vnf][0] *= a0; O1a[vnf][1] *= a0; O1a[vnf][2] *= a1; O1a[vnf][3] *= a1;
            if (NV == 2) { O2a[vnf][0] *= a0; O2a[vnf][1] *= a0; O2a[vnf][2] *= a1; O2a[vnf][3] *= a1; }
        }

        // ---- O += P V (3-term split), ldmatrix.x4 over vnf pairs ----
#pragma unroll
        for (int kcp = 0; kcp < 8; kcp++) {
            uint32_t ph[4], pl[4];
            split2pack(sacc[2 * kcp][0],     sacc[2 * kcp][1],     ph[0], pl[0]);
            split2pack(sacc[2 * kcp][2],     sacc[2 * kcp][3],     ph[1], pl[1]);
            split2pack(sacc[2 * kcp + 1][0], sacc[2 * kcp + 1][1], ph[2], pl[2]);
            split2pack(sacc[2 * kcp + 1][2], sacc[2 * kcp + 1][3], ph[3], pl[3]);
#pragma unroll
            for (int vnp = 0; vnp < 4; vnp++) {
                int off = cur + (vnp * 16 + ((lane >> 4) & 1) * 8 + (lane & 7)) * 136
                        + kcp * 16 + ((lane >> 3) & 1) * 8;
                uint32_t vh4[4], vl4[4];
                ldsm4(vh4[0], vh4[1], vh4[2], vh4[3], smaddr(&bV1h[off]));
                ldsm4(vl4[0], vl4[1], vl4[2], vl4[3], smaddr(&bV1l[off]));
                uint32_t v0h[2] = {vh4[0], vh4[1]}, v1h[2] = {vh4[2], vh4[3]};
                uint32_t v0l[2] = {vl4[0], vl4[1]}, v1l[2] = {vl4[2], vl4[3]};
                MMA16816(O1a[2 * vnp],     ph, v0h);
                MMA16816(O1a[2 * vnp],     ph, v0l);
                MMA16816(O1a[2 * vnp],     pl, v0h);
                MMA16816(O1a[2 * vnp + 1], ph, v1h);
                MMA16816(O1a[2 * vnp + 1], ph, v1l);
                MMA16816(O1a[2 * vnp + 1], pl, v1h);
                if (NV == 2) {
                    uint32_t wh4[4], wl4[4];
                    ldsm4(wh4[0], wh4[1], wh4[2], wh4[3], smaddr(&bV2h[off]));
                    ldsm4(wl4[0], wl4[1], wl4[2], wl4[3], smaddr(&bV2l[off]));
                    uint32_t w0h[2] = {wh4[0], wh4[1]}, w1h[2] = {wh4[2], wh4[3]};
                    uint32_t w0l[2] = {wl4[0], wl4[1]}, w1l[2] = {wl4[2], wl4[3]};
                    MMA16816(O2a[2 * vnp],     ph, w0h);
                    MMA16816(O2a[2 * vnp],     ph, w0l);
                    MMA16816(O2a[2 * vnp],     pl, w0h);
                    MMA16816(O2a[2 * vnp + 1], ph, w1h);
                    MMA16816(O2a[2 * vnp + 1], ph, w1l);
                    MMA16816(O2a[2 * vnp + 1], pl, w1h);
                }
            }
        }
        __syncthreads();
    }

    // ---- finalize ----
    const float i0 = 1.f / l0, i1 = 1.f / l1;
#pragma unroll
    for (int vnf = 0; vnf < 8; vnf++) {
        O1a[vnf][0] *= i0; O1a[vnf][1] *= i0; O1a[vnf][2] *= i1; O1a[vnf][3] *= i1;
        if (NV == 2) { O2a[vnf][0] *= i0; O2a[vnf][1] *= i0; O2a[vnf][2] *= i1; O2a[vnf][3] *= i1; }
    }

    const int r = wm + (lane >> 2);
    if (NV == 2) {
        // residual add (u = a3 @ v + v)
        const float* R1p = R1 + (size_t)zb * 2097152 + (size_t)zh * 64;
        const float* R2p = R2 + (size_t)zb * 2097152 + (size_t)zh * 64;
        const size_t row = (size_t)(tok0 + r);
#pragma unroll
        for (int vnf = 0; vnf < 8; vnf++) {
            int c0 = vnf * 8 + (lane & 3) * 2;
            float2 ra = *(const float2*)&R1p[row * 2048 + c0];
            float2 rb = *(const float2*)&R1p[(row + 8) * 2048 + c0];
            O1a[vnf][0] += ra.x; O1a[vnf][1] += ra.y; O1a[vnf][2] += rb.x; O1a[vnf][3] += rb.y;
            float2 rc = *(const float2*)&R2p[row * 2048 + c0];
            float2 rd = *(const float2*)&R2p[(row + 8) * 2048 + c0];
            O2a[vnf][0] += rc.x; O2a[vnf][1] += rc.y; O2a[vnf][2] += rd.x; O2a[vnf][3] += rd.y;
        }
        // transposed plane output via smem bounce (stage-0 K buffers are free)
#pragma unroll
        for (int s = 0; s < 2; s++) {
            float (*Oa)[4] = s ? O2a : O1a;
#pragma unroll
            for (int vnf = 0; vnf < 8; vnf++) {
                int c0 = vnf * 8 + (lane & 3) * 2;
                uint32_t hp, lp;
                split2pack(Oa[vnf][0], Oa[vnf][1], hp, lp);
                *(uint32_t*)&bKh[r * 72 + c0] = hp;
                *(uint32_t*)&bKl[r * 72 + c0] = lp;
                split2pack(Oa[vnf][2], Oa[vnf][3], hp, lp);
                *(uint32_t*)&bKh[(r + 8) * 72 + c0] = hp;
                *(uint32_t*)&bKl[(r + 8) * 72 + c0] = lp;
            }
            __syncthreads();
            __nv_bfloat16* OH = (s ? O2h : O1h) + (size_t)z * 65536 + tok0;
            __nv_bfloat16* OL = (s ? O2l : O1l) + (size_t)z * 65536 + tok0;
            for (int i = tid; i < 2048; i += 256) {
                int plane = i >> 10, rem = i & 1023, d = rem >> 4, ch = (rem & 15) * 8;
                const unsigned short* src = (const unsigned short*)(plane ? bKl : bKh);
                unsigned short v[8];
#pragma unroll
                for (int j = 0; j < 8; j++) v[j] = src[(ch + j) * 72 + d];
                uint4 pk;
                pk.x = (uint32_t)v[0] | ((uint32_t)v[1] << 16);
                pk.y = (uint32_t)v[2] | ((uint32_t)v[3] << 16);
                pk.z = (uint32_t)v[4] | ((uint32_t)v[5] << 16);
                pk.w = (uint32_t)v[6] | ((uint32_t)v[7] << 16);
                *(uint4*)((plane ? OL : OH) + (size_t)d * 1024 + ch) = pk;
            }
            __syncthreads();
        }
    } else {
        // row-major plane output
        __nv_bfloat16* OH = O1h + (size_t)zb * 524288 + zh * 64;
        __nv_bfloat16* OL = O1l + (size_t)zb * 524288 + zh * 64;
        const size_t row = (size_t)(tok0 + r);
#pragma unroll
        for (int vnf = 0; vnf < 8; vnf++) {
            int c0 = vnf * 8 + (lane & 3) * 2;
            uint32_t hp, lp;
            split2pack(O1a[vnf][0], O1a[vnf][1], hp, lp);
            *(uint32_t*)&OH[row * 512 + c0] = hp;
            *(uint32_t*)&OL[row * 512 + c0] = lp;
            split2pack(O1a[vnf][2], O1a[vnf][3], hp, lp);
            *(uint32_t*)&OH[(row + 8) * 512 + c0] = hp;
            *(uint32_t*)&OL[(row + 8) * 512 + c0] = lp;
        }
    }
}

// ---------------------------------------------------------------------------
// conv_all: all 6 operand conversions in ONE launch.
// ---------------------------------------------------------------------------
__global__ void conv_all(
    const float* __restrict__ x1, const float* __restrict__ x2,
    const float* __restrict__ Wq1f, const float* __restrict__ Wq2f,
    const float* __restrict__ Wo1f, const float* __restrict__ Wo2f,
    __nv_bfloat16* __restrict__ xp1, __nv_bfloat16* __restrict__ xp2,
    __nv_bfloat16* __restrict__ Wq1, __nv_bfloat16* __restrict__ Wq2,
    __nv_bfloat16* __restrict__ Wo1, __nv_bfloat16* __restrict__ Wo2)
{
    int b = blockIdx.x;
    if (b < 8192) {
        const float* X; __nv_bfloat16 *H, *L;
        if (b < 4096) { X = x1; H = xp1; L = xp1 + PXc; }
        else          { X = x2; H = xp2; L = xp2 + PXc; b -= 4096; }
        int i = b * 256 + threadIdx.x;
        float4 v = ((const float4*)X)[i];
        uint32_t hp, lp;
        split2pack(v.x, v.y, hp, lp);
        *(uint32_t*)&H[(size_t)i * 4] = hp; *(uint32_t*)&L[(size_t)i * 4] = lp;
        split2pack(v.z, v.w, hp, lp);
        *(uint32_t*)&H[(size_t)i * 4 + 2] = hp; *(uint32_t*)&L[(size_t)i * 4 + 2] = lp;
    } else {
        b -= 8192;
        const float* W; __nv_bfloat16 *H, *L; int N;
        if (b < 4096)      { W = Wq1f; H = Wq1; L = Wq1 + PWc;  N = 2048; }
        else if (b < 8192) { W = Wq2f; H = Wq2; L = Wq2 + PWc;  N = 2048; b -= 4096; }
        else if (b < 9216) { W = Wo1f; H = Wo1; L = Wo1 + PWoc; N = 512;  b -= 8192; }
        else               { W = Wo2f; H = Wo2; L = Wo2 + PWoc; N = 512;  b -= 9216; }
        int i = b * 256 + threadIdx.x;
        int n = i >> 9, k = i & 511;   // K = 512
        float v = W[(size_t)k * N + n];
        split1(v, H[i], L[i]);
    }
}

// ---------------------------------------------------------------------------
// gate_vtrans: gate path (blocks [0,8192)) + both v-transposes ([8192,10240)).
// ---------------------------------------------------------------------------
__global__ __launch_bounds__(256) void gate_vtrans(
    const float* __restrict__ qkv1, const float* __restrict__ qkv2,
    const float* __restrict__ w, const float* __restrict__ cb,
    __nv_bfloat16* __restrict__ H, __nv_bfloat16* __restrict__ L,
    __nv_bfloat16* __restrict__ H1, __nv_bfloat16* __restrict__ L1,
    __nv_bfloat16* __restrict__ H2, __nv_bfloat16* __restrict__ L2)
{
    __shared__ float t[64][65];
    int b = blockIdx.x;
    const int tid = threadIdx.x;
    if (b < 8192) {
        // gate: MS = s1+s2; depthwise conv-5 over features; sigmoid gate -> planes
        float* ms = (float*)t;   // needs 516 floats
        const int bn = b, n = bn & 1023;
        const float* r1 = qkv1 + (size_t)bn * 2048 + 1536;
        const float* r2 = qkv2 + (size_t)bn * 2048 + 1536;
        for (int f = tid; f < 512; f += 256) ms[f + 2] = r1[f] + r2[f];
        if (tid < 2) { ms[tid] = 0.f; ms[514 + tid] = 0.f; }
        __syncthreads();
        const float w0 = w[n * 5], w1 = w[n * 5 + 1], w2 = w[n * 5 + 2],
                    w3 = w[n * 5 + 3], w4 = w[n * 5 + 4], bb = cb[n];
        for (int f = tid; f < 512; f += 256) {
            float a = w0 * ms[f] + w1 * ms[f + 1] + w2 * ms[f + 2]
                    + w3 * ms[f + 3] + w4 * ms[f + 4] + bb;
            float s = 1.f / (1.f + __expf(-a));
            float v = s * ms[f + 2];
            split1(v, H[(size_t)bn * 512 + f], L[(size_t)bn * 512 + f]);
        }
    } else {
        b -= 8192;
        const int zz = b >> 4, tokb = b & 15;
        const float* qkv = (zz < 64) ? qkv1 : qkv2;
        __nv_bfloat16* Ho = (zz < 64) ? H1 : H2;
        __nv_bfloat16* Lo = (zz < 64) ? L1 : L2;
        const int z = zz & 63, bb_ = z >> 3, h = z & 7;
        for (int i = tid; i < 4096; i += 256) {
            int tl = i >> 6, n = i & 63;
            t[tl][n] = qkv[(size_t)(bb_ * 1024 + tokb * 64 + tl) * 2048 + 1024 + h * 64 + n];
        }
        __syncthreads();
        for (int i = tid; i < 4096; i += 256) {
            int n = i >> 6, tl = i & 63;
            float v = t[tl][n];
            size_t o = ((size_t)z * 64 + n) * 1024 + tokb * 64 + tl;
            split1(v, Ho[o], Lo[o]);
        }
    }
}

// ---------------------------------------------------------------------------
// Launch — fattn<2> is the 4th launch (index 3), which the ncu capture hits.
// ---------------------------------------------------------------------------
extern "C" void kernel_launch(void* const* d_in, const int* in_sizes, int n_in,
                              void* d_out, int out_size)
{
    const float* x1    = (const float*)d_in[0];
    const float* x2    = (const float*)d_in[1];
    const float* Wqkv1 = (const float*)d_in[2];
    const float* Wqkv2 = (const float*)d_in[3];
    const float* Wout1 = (const float*)d_in[4];
    const float* bout1 = (const float*)d_in[5];
    const float* Wout2 = (const float*)d_in[6];
    const float* bout2 = (const float*)d_in[7];
    const float* convw = (const float*)d_in[8];
    const float* convb = (const float*)d_in[9];
    float* out = (float*)d_out;

    __nv_bfloat16 *xp1, *xp2, *Wq1, *Wq2, *Wo1, *Wo2, *qkvp1, *qkvp2,
                  *vT1, *vT2, *msgp, *uT1, *uT2, *tp1, *tp2;
    float *qkv1, *qkv2;
    cudaGetSymbolAddress((void**)&xp1, g_xp1);   cudaGetSymbolAddress((void**)&xp2, g_xp2);
    cudaGetSymbolAddress((void**)&Wq1, g_Wq1);   cudaGetSymbolAddress((void**)&Wq2, g_Wq2);
    cudaGetSymbolAddress((void**)&Wo1, g_Wo1);   cudaGetSymbolAddress((void**)&Wo2, g_Wo2);
    cudaGetSymbolAddress((void**)&qkv1, g_qkv1); cudaGetSymbolAddress((void**)&qkv2, g_qkv2);
    cudaGetSymbolAddress((void**)&qkvp1, g_qkvp1); cudaGetSymbolAddress((void**)&qkvp2, g_qkvp2);
    cudaGetSymbolAddress((void**)&vT1, g_vT1);   cudaGetSymbolAddress((void**)&vT2, g_vT2);
    cudaGetSymbolAddress((void**)&msgp, g_msgp);
    cudaGetSymbolAddress((void**)&uT1, g_uT1);   cudaGetSymbolAddress((void**)&uT2, g_uT2);
    cudaGetSymbolAddress((void**)&tp1, g_tp1);   cudaGetSymbolAddress((void**)&tp2, g_tp2);

    const long long PX  = PXc;
    const long long PQ  = PQc;
    const long long PW  = PWc;
    const long long PWo = PWoc;
    const long long PV  = PVc;

    const int SMEM2 = 2 * (2 * 128 * 72 + 4 * 64 * 136) * 2;  // 212992 (2 stages)
    const int SMEM1 = 2 * (2 * 128 * 72 + 2 * 64 * 136) * 2;  // 143360 (2 stages)
    cudaFuncSetAttribute(fattn<2>, cudaFuncAttributeMaxDynamicSharedMemorySize, SMEM2);
    cudaFuncSetAttribute(fattn<1>, cudaFuncAttributeMaxDynamicSharedMemorySize, SMEM1);

    // 0: all operand conversions
    conv_all<<<18432, 256>>>(x1, x2, Wqkv1, Wqkv2, Wout1, Wout2,
                             xp1, xp2, Wq1, Wq2, Wo1, Wo2);

    // 1: dual QKVS projection (z=0 stream1, z=1 stream2)
    gemm_bs<F_F32 | F_PLANES | F_QKVSPL | F_DUAL><<<dim3(16, 64, 2), 256>>>(
        xp1, xp1 + PX, 512, Wq1, Wq1 + PW, 512,
        qkv1, 2048, qkvp1, qkvp1 + PQ, 2048, nullptr, 512,
        xp2, xp2 + PX, Wq2, Wq2 + PW, qkv2, qkvp2, qkvp2 + PQ, nullptr);

    // 2: gate path + both v transposes
    gate_vtrans<<<10240, 256>>>(qkv1, qkv2, convw, convb,
                                msgp, msgp + PX, vT1, vT1 + PV, vT2, vT2 + PV);

    // 3 (PROFILED): Pass 3 fused: a3 = softmax(MSh MSh^T * scale); u_i = a3 @ v_i + v_i
    fattn<2><<<dim3(8, 1, 64), 256, SMEM2>>>(
        msgp, msgp + PX, 512, 524288, 64,
        msgp, msgp + PX, 512, 524288, 64,
        vT1, vT1 + PV, vT2, vT2 + PV,
        qkv1 + 1024, qkv2 + 1024,
        uT1, uT1 + PV, uT2, uT2 + PV,
        nullptr, nullptr, nullptr, nullptr, nullptr, nullptr, nullptr, nullptr);

    // 4: dual Pass 1/2 fused: t_i = softmax(q_i k_i^T * scale) @ u_i
    fattn<1><<<dim3(8, 2, 64), 256, SMEM1>>>(
        qkvp1, qkvp1 + PQ, 2048, 2097152, 64,
        qkvp1 + 512, qkvp1 + PQ + 512, 2048, 2097152, 64,
        uT1, uT1 + PV, nullptr, nullptr,
        nullptr, nullptr,
        tp1, tp1 + PX, nullptr, nullptr,
        qkvp2, qkvp2 + PQ, qkvp2 + 512, qkvp2 + PQ + 512,
        uT2, uT2 + PV, tp2, tp2 + PX);

    // 5: dual output projection
    gemm_bs<F_F32 | F_BIAS | F_DUAL><<<dim3(4, 64, 2), 256>>>(
        tp1, tp1 + PX, 512, Wo1, Wo1 + PWo, 512,
        out, 512, nullptr, nullptr, 0, bout1, 512,
        tp2, tp2 + PX, Wo2, Wo2 + PWo, out + 4194304, nullptr, nullptr, bout2);
}